// round 10
// baseline (speedup 1.0000x reference)
#include <cuda_runtime.h>
#include <cuda_bf16.h>
#include <math.h>
#include <stdint.h>

// Problem dims
#define S_  1024
#define B_  4
#define D_  768
#define NH_ 12
#define DH_ 64
#define L_  4
#define DI_ 3072
#define SB_ (S_*B_)

// weight-scale table offsets (per layer, 6912 rows total)
#define OQ_  0
#define OKV_ 768
#define OO_  2304
#define OW1_ 3072
#define OW2_ 6144
#define WS_  6912

// ---------------- scratch (device globals; no allocation allowed) ------------
__device__ float g_h[SB_*D_];
__device__ float g_q[SB_*D_];
__device__ float g_kv[SB_*2*D_];
__device__ float g_attn[SB_*D_];
__device__ float g_content[SB_*D_];
__device__ float g_cK[SB_*D_];
__device__ float g_diff[SB_*D_];
__device__ float g_ff[SB_*DI_];
__device__ float g_out1[SB_*D_];
__device__ float g_wo[SB_*D_];
__device__ float g_sa[SB_],  g_isa[SB_];
__device__ float g_ws[L_*WS_], g_iws[L_*WS_];

// pack two floats into bf16x2 (lo half = first arg)
__device__ __forceinline__ uint32_t pack_bf2(float a, float b) {
    __nv_bfloat162 h = __floats2bfloat162_rn(a, b);
    return *(uint32_t*)&h;
}

__device__ __forceinline__ void mma16816(float* d, const uint32_t* a,
                                         uint32_t b0, uint32_t b1) {
    asm volatile(
        "mma.sync.aligned.m16n8k16.row.col.f32.bf16.bf16.f32 "
        "{%0,%1,%2,%3}, {%4,%5,%6,%7}, {%8,%9}, {%0,%1,%2,%3};"
        : "+f"(d[0]), "+f"(d[1]), "+f"(d[2]), "+f"(d[3])
        : "r"(a[0]), "r"(a[1]), "r"(a[2]), "r"(a[3]), "r"(b0), "r"(b1));
}

__device__ __forceinline__ void mma_s8(int* d, const uint32_t* a,
                                       uint32_t b0, uint32_t b1) {
    asm volatile(
        "mma.sync.aligned.m16n8k32.row.col.s32.s8.s8.s32 "
        "{%0,%1,%2,%3}, {%4,%5,%6,%7}, {%8,%9}, {%0,%1,%2,%3};"
        : "+r"(d[0]), "+r"(d[1]), "+r"(d[2]), "+r"(d[3])
        : "r"(a[0]), "r"(a[1]), "r"(a[2]), "r"(a[3]), "r"(b0), "r"(b1));
}

// 2-term int8 quantization of a float4: v = s*(q1 + q2/128)
__device__ __forceinline__ void quant_f4(float4 a, float inv,
                                         uint32_t& w1, uint32_t& w2) {
    float sx = a.x*inv, sy = a.y*inv, sz = a.z*inv, sw = a.w*inv;
    int x1 = __float2int_rn(sx), y1 = __float2int_rn(sy);
    int z1 = __float2int_rn(sz), v1 = __float2int_rn(sw);
    int x2 = __float2int_rn((sx - (float)x1)*128.f);
    int y2 = __float2int_rn((sy - (float)y1)*128.f);
    int z2 = __float2int_rn((sz - (float)z1)*128.f);
    int v2 = __float2int_rn((sw - (float)v1)*128.f);
    w1 = (x1 & 0xFF) | ((y1 & 0xFF) << 8) | ((z1 & 0xFF) << 16)
       | ((uint32_t)(v1 & 0xFF) << 24);
    w2 = (x2 & 0xFF) | ((y2 & 0xFF) << 8) | ((z2 & 0xFF) << 16)
       | ((uint32_t)(v2 & 0xFF) << 24);
}

// ---------------- embedding + sinusoidal positional encoding -----------------
__global__ void embed_kernel(const int* __restrict__ inp,
                             const float* __restrict__ we,
                             float* __restrict__ h)
{
    int row = blockIdx.x;
    int s = row / B_;
    int b = row % B_;
    int t = threadIdx.x;
    int tok = inp[s*B_ + b];
    float pos = (float)(S_ - 1 - s);
    const float lg = logf(10000.0f);
    for (int d = t; d < D_; d += 256) {
        int i = (d < 384) ? d : d - 384;
        float freq = expf(-((float)(2*i) / (float)D_) * lg);
        float ang = pos * freq;
        float pe = (d < 384) ? sinf(ang) : cosf(ang);
        h[(size_t)row*D_ + d] = we[(size_t)tok*D_ + d] * 27.712812921102035f + pe;
    }
}

// -------- row |max| scan (optionally of the gated combination) ---------------
__global__ __launch_bounds__(256) void rowmax_k(
    const float* __restrict__ A, const float* __restrict__ A2, float gate,
    int K, float* __restrict__ sa, float* __restrict__ isa)
{
    int row = blockIdx.x, t = threadIdx.x, lane = t & 31, warp = t >> 5;
    __shared__ float wmx[8];
    const float* p  = A + (size_t)row*K;
    const float* p2 = A2 ? (A2 + (size_t)row*K) : nullptr;
    float mx = 0.f;
    for (int k = t; k < K; k += 256) {
        float v = p[k];
        if (A2) v = gate*v + (1.f - gate)*p2[k];
        mx = fmaxf(mx, fabsf(v));
    }
    #pragma unroll
    for (int off = 16; off > 0; off >>= 1)
        mx = fmaxf(mx, __shfl_xor_sync(0xffffffff, mx, off));
    if (lane == 0) wmx[warp] = mx;
    __syncthreads();
    if (t == 0) {
        float m = wmx[0];
        #pragma unroll
        for (int w = 1; w < 8; w++) m = fmaxf(m, wmx[w]);
        m = fmaxf(m, 1e-20f);
        sa[row]  = m * (1.f/126.f);
        isa[row] = 126.f / m;
    }
}

// ---------------- int8 NT GEMM (2-term row-scaled split) ---------------------
// C[M,N] = A[M,K] @ B[N,K]^T via 3 s8 mmas per 32-k chunk:
//   a1b1 -> acc1 (exact), a1b2 + a2b1 -> accX (shared 2^-7 scale)
// C = sa[m]*sb[n]*(acc1 + accX/128).  FUSE: A := gate*A + (1-gate)*A2.
#define KP 20
template <bool FUSE>
__device__ __forceinline__ void gemm_i8_body(
    const float* __restrict__ A, const float* __restrict__ A2, float gate,
    const float* __restrict__ Bm, const float* __restrict__ bias,
    const float* __restrict__ saA, const float* __restrict__ isaA,
    const float* __restrict__ sbB, const float* __restrict__ isbB,
    float* __restrict__ C, int N, int K, int epi, int m0, int n0)
{
    __shared__ __align__(16) uint32_t As[2][128][KP];
    __shared__ __align__(16) uint32_t Bs[2][128][KP];
    int tid = threadIdx.x;
    int warp = tid >> 5, lane = tid & 31;
    int wm = warp >> 2, wn = warp & 3;          // 2 x 4 warp grid
    int r0 = lane >> 2, cq = lane & 3;
    int lrow = tid >> 3;                        // 0..31
    int lf4  = (tid & 7) * 4;                   // float offset within 32-chunk
    int wcol = lf4 >> 2;                        // word col 0..7

    int acc1[16][4], accX[16][4];
    #pragma unroll
    for (int i = 0; i < 16; i++)
        #pragma unroll
        for (int j = 0; j < 4; j++) { acc1[i][j] = 0; accX[i][j] = 0; }

    float4 av[4], bv4[4];
    float invA[4], invB[4];

    auto issue_loads = [&](int kc) {
        #pragma unroll
        for (int it = 0; it < 4; it++) {
            int row = lrow + it*32;
            invA[it] = isaA[m0 + row];
            av[it] = *(const float4*)(A + (size_t)(m0+row)*K + kc + lf4);
            if (FUSE) {
                float4 b2v = *(const float4*)(A2 + (size_t)(m0+row)*K + kc + lf4);
                av[it].x = gate*av[it].x + (1.f-gate)*b2v.x;
                av[it].y = gate*av[it].y + (1.f-gate)*b2v.y;
                av[it].z = gate*av[it].z + (1.f-gate)*b2v.z;
                av[it].w = gate*av[it].w + (1.f-gate)*b2v.w;
            }
            invB[it] = isbB[n0 + row];
            bv4[it] = *(const float4*)(Bm + (size_t)(n0+row)*K + kc + lf4);
        }
    };
    auto store_smem = [&](int bi) {
        #pragma unroll
        for (int it = 0; it < 4; it++) {
            int row = lrow + it*32;
            uint32_t w1, w2;
            quant_f4(av[it], invA[it], w1, w2);
            As[bi][row][wcol] = w1; As[bi][row][8 + wcol] = w2;
            quant_f4(bv4[it], invB[it], w1, w2);
            Bs[bi][row][wcol] = w1; Bs[bi][row][8 + wcol] = w2;
        }
    };

    issue_loads(0);
    store_smem(0);
    __syncthreads();

    int NC = K >> 5;
    for (int c = 0; c < NC; c++) {
        int buf = c & 1;
        if (c + 1 < NC) issue_loads((c + 1) << 5);

        uint32_t af[4][4], bf[4][2];
        // a1 fragments
        #pragma unroll
        for (int mi = 0; mi < 4; mi++) {
            int mr = wm*64 + mi*16 + r0;
            af[mi][0] = As[buf][mr    ][cq];
            af[mi][1] = As[buf][mr + 8][cq];
            af[mi][2] = As[buf][mr    ][cq + 4];
            af[mi][3] = As[buf][mr + 8][cq + 4];
        }
        // b1 fragments; term 1: a1*b1 -> acc1
        #pragma unroll
        for (int ni = 0; ni < 4; ni++) {
            int nr = wn*32 + ni*8 + r0;
            bf[ni][0] = Bs[buf][nr][cq];
            bf[ni][1] = Bs[buf][nr][cq + 4];
        }
        #pragma unroll
        for (int mi = 0; mi < 4; mi++)
            #pragma unroll
            for (int ni = 0; ni < 4; ni++)
                mma_s8(acc1[mi*4 + ni], af[mi], bf[ni][0], bf[ni][1]);
        // b2; term 2: a1*b2 -> accX
        #pragma unroll
        for (int ni = 0; ni < 4; ni++) {
            int nr = wn*32 + ni*8 + r0;
            bf[ni][0] = Bs[buf][nr][8 + cq];
            bf[ni][1] = Bs[buf][nr][12 + cq];
        }
        #pragma unroll
        for (int mi = 0; mi < 4; mi++)
            #pragma unroll
            for (int ni = 0; ni < 4; ni++)
                mma_s8(accX[mi*4 + ni], af[mi], bf[ni][0], bf[ni][1]);
        // a2, b1 back; term 3: a2*b1 -> accX
        #pragma unroll
        for (int mi = 0; mi < 4; mi++) {
            int mr = wm*64 + mi*16 + r0;
            af[mi][0] = As[buf][mr    ][8 + cq];
            af[mi][1] = As[buf][mr + 8][8 + cq];
            af[mi][2] = As[buf][mr    ][12 + cq];
            af[mi][3] = As[buf][mr + 8][12 + cq];
        }
        #pragma unroll
        for (int ni = 0; ni < 4; ni++) {
            int nr = wn*32 + ni*8 + r0;
            bf[ni][0] = Bs[buf][nr][cq];
            bf[ni][1] = Bs[buf][nr][cq + 4];
        }
        #pragma unroll
        for (int mi = 0; mi < 4; mi++)
            #pragma unroll
            for (int ni = 0; ni < 4; ni++)
                mma_s8(accX[mi*4 + ni], af[mi], bf[ni][0], bf[ni][1]);

        if (c + 1 < NC) store_smem(buf ^ 1);
        __syncthreads();
    }

    // epilogue
    #pragma unroll
    for (int mi = 0; mi < 4; mi++) {
        int m = m0 + wm*64 + mi*16 + r0;
        float sa0 = saA[m], sa8 = saA[m + 8];
        #pragma unroll
        for (int ni = 0; ni < 4; ni++) {
            int n = n0 + wn*32 + ni*8 + 2*cq;
            float sb0 = sbB[n], sb1v = sbB[n + 1];
            int* d1 = acc1[mi*4 + ni];
            int* dx = accX[mi*4 + ni];
            float2 v0, v1;
            v0.x = ((float)d1[0] + (float)dx[0]*0.0078125f) * sa0 * sb0;
            v0.y = ((float)d1[1] + (float)dx[1]*0.0078125f) * sa0 * sb1v;
            v1.x = ((float)d1[2] + (float)dx[2]*0.0078125f) * sa8 * sb0;
            v1.y = ((float)d1[3] + (float)dx[3]*0.0078125f) * sa8 * sb1v;
            if (epi == 1) {
                float b0v = bias[n], b1v = bias[n+1];
                v0.x = fmaxf(v0.x + b0v, 0.f); v0.y = fmaxf(v0.y + b1v, 0.f);
                v1.x = fmaxf(v1.x + b0v, 0.f); v1.y = fmaxf(v1.y + b1v, 0.f);
            } else if (epi == 2) {
                float b0v = bias[n], b1v = bias[n+1];
                v0.x += b0v; v0.y += b1v;
                v1.x += b0v; v1.y += b1v;
            }
            *(float2*)(C + (size_t)m*N + n)     = v0;
            *(float2*)(C + (size_t)(m+8)*N + n) = v1;
        }
    }
}

__global__ __launch_bounds__(256) void gemm_i8(
    const float* __restrict__ A, const float* __restrict__ Bm,
    const float* __restrict__ bias,
    const float* __restrict__ sa, const float* __restrict__ isa,
    const float* __restrict__ sb, const float* __restrict__ isb,
    float* __restrict__ C, int N, int K, int epi)
{
    gemm_i8_body<false>(A, nullptr, 0.f, Bm, bias, sa, isa, sb, isb,
                        C, N, K, epi, blockIdx.y*128, blockIdx.x*128);
}

__global__ __launch_bounds__(256) void gemm_i8_wo(
    const float* __restrict__ A, const float* __restrict__ A2, float gate,
    const float* __restrict__ Bm,
    const float* __restrict__ sa, const float* __restrict__ isa,
    const float* __restrict__ sb, const float* __restrict__ isb,
    float* __restrict__ C, int N, int K)
{
    gemm_i8_body<true>(A, A2, gate, Bm, nullptr, sa, isa, sb, isb,
                       C, N, K, 0, blockIdx.y*128, blockIdx.x*128);
}

__global__ __launch_bounds__(256) void gemm_i8_qkv(
    const float* __restrict__ A,
    const float* __restrict__ Wq, const float* __restrict__ Wkv,
    const float* __restrict__ sa, const float* __restrict__ isa,
    const float* __restrict__ sbq, const float* __restrict__ isbq,
    const float* __restrict__ sbkv, const float* __restrict__ isbkv,
    float* __restrict__ q, float* __restrict__ kv, int K)
{
    int bx = blockIdx.x, m0 = blockIdx.y*128;
    if (bx < 6)
        gemm_i8_body<false>(A, nullptr, 0.f, Wq, nullptr, sa, isa, sbq, isbq,
                            q, D_, K, 0, m0, bx*128);
    else
        gemm_i8_body<false>(A, nullptr, 0.f, Wkv, nullptr, sa, isa, sbkv, isbkv,
                            kv, 2*D_, K, 0, m0, (bx - 6)*128);
}

// ------------- tensor-core flash attention (bf16 hi/lo, fp32 acc) -------------
__global__ __launch_bounds__(256) void attn_mma(
    const float* __restrict__ q, const float* __restrict__ k,
    const float* __restrict__ v, float* __restrict__ o,
    int qS, int kvS, int oS)
{
    int qt = 7 - (int)blockIdx.x;
    int bn = blockIdx.y;
    int b = bn / NH_, n = bn % NH_;
    int col0 = n * DH_;
    int t = threadIdx.x, lane = t & 31, warp = t >> 5;
    int r0 = lane >> 2, cq = lane & 3;

    __shared__ __align__(16) uint32_t Ks[64][68];
    __shared__ __align__(16) uint32_t Vt[64][68];

    int qrow = qt*128 + warp*16;

    uint32_t qh[4][4], ql[4][4];
    #pragma unroll
    for (int ks = 0; ks < 4; ks++) {
        int cb = ks*16 + 2*cq;
        #pragma unroll
        for (int u = 0; u < 4; u++) {
            int rr = qrow + r0 + ((u & 1) ? 8 : 0);
            int cc = cb + ((u & 2) ? 8 : 0);
            float2 qv = *(const float2*)(q + ((size_t)rr*B_ + b)*qS + col0 + cc);
            float hx = __bfloat162float(__float2bfloat16_rn(qv.x));
            float hy = __bfloat162float(__float2bfloat16_rn(qv.y));
            qh[ks][u] = pack_bf2(hx, hy);
            ql[ks][u] = pack_bf2(qv.x - hx, qv.y - hy);
        }
    }

    float Oc[8][4];
    #pragma unroll
    for (int i = 0; i < 8; i++)
        #pragma unroll
        for (int j = 0; j < 4; j++) Oc[i][j] = 0.f;
    float m0 = -3.4e38f, m8 = -3.4e38f, l0 = 0.f, l8 = 0.f;

    int nkt = 2*qt + 2;
    for (int kt = 0; kt < nkt; kt++) {
        for (int idx = t; idx < 64*16; idx += 256) {
            int key = idx >> 4, c = idx & 15;
            float4 kv4 = *(const float4*)(k + ((size_t)(kt*64+key)*B_ + b)*kvS
                                            + col0 + 4*c);
            float hx = __bfloat162float(__float2bfloat16_rn(kv4.x));
            float hy = __bfloat162float(__float2bfloat16_rn(kv4.y));
            float hz = __bfloat162float(__float2bfloat16_rn(kv4.z));
            float hw = __bfloat162float(__float2bfloat16_rn(kv4.w));
            Ks[key][2*c  ] = pack_bf2(hx, hy);
            Ks[key][2*c+1] = pack_bf2(hz, hw);
            Ks[key][32 + 2*c  ] = pack_bf2(kv4.x - hx, kv4.y - hy);
            Ks[key][32 + 2*c+1] = pack_bf2(kv4.z - hz, kv4.w - hw);
        }
        #pragma unroll
        for (int it = 0; it < 4; it++) {
            int idx = t + 256*it;
            int j = idx >> 5;
            int d = idx & 31;
            const float* vp0 = v + ((size_t)(kt*64 + 2*j)*B_ + b)*kvS + col0 + 2*d;
            float2 va = *(const float2*)vp0;
            float2 vb = *(const float2*)(vp0 + (size_t)B_*kvS);
            float hax = __bfloat162float(__float2bfloat16_rn(va.x));
            float hay = __bfloat162float(__float2bfloat16_rn(va.y));
            float hbx = __bfloat162float(__float2bfloat16_rn(vb.x));
            float hby = __bfloat162float(__float2bfloat16_rn(vb.y));
            Vt[2*d  ][j] = pack_bf2(hax, hbx);
            Vt[2*d+1][j] = pack_bf2(hay, hby);
            Vt[2*d  ][32 + j] = pack_bf2(va.x - hax, vb.x - hbx);
            Vt[2*d+1][32 + j] = pack_bf2(va.y - hay, vb.y - hby);
        }
        __syncthreads();

        float sc[8][4];
        #pragma unroll
        for (int i = 0; i < 8; i++)
            #pragma unroll
            for (int j = 0; j < 4; j++) sc[i][j] = 0.f;
        #pragma unroll
        for (int ks = 0; ks < 4; ks++)
            #pragma unroll
            for (int ni = 0; ni < 8; ni++) {
                int nr = ni*8 + r0;
                mma16816(sc[ni], qh[ks], Ks[nr][cq + 8*ks], Ks[nr][cq + 8*ks + 4]);
            }
        #pragma unroll
        for (int ks = 0; ks < 4; ks++)
            #pragma unroll
            for (int ni = 0; ni < 8; ni++) {
                int nr = ni*8 + r0;
                mma16816(sc[ni], qh[ks], Ks[nr][32 + cq + 8*ks],
                         Ks[nr][32 + cq + 8*ks + 4]);
            }
        #pragma unroll
        for (int ks = 0; ks < 4; ks++)
            #pragma unroll
            for (int ni = 0; ni < 8; ni++) {
                int nr = ni*8 + r0;
                mma16816(sc[ni], ql[ks], Ks[nr][cq + 8*ks], Ks[nr][cq + 8*ks + 4]);
            }

        const float scale = 0.125f;
        bool diag = (kt >= 2*qt);
        int rg0 = qrow + r0, rg8 = rg0 + 8;
        float tm0 = -3.4e38f, tm8 = -3.4e38f;
        #pragma unroll
        for (int ni = 0; ni < 8; ni++) {
            float s0 = sc[ni][0]*scale, s1 = sc[ni][1]*scale;
            float s2 = sc[ni][2]*scale, s3 = sc[ni][3]*scale;
            if (diag) {
                int colg = kt*64 + ni*8 + 2*cq;
                if (colg     > rg0) s0 = -3.4e38f;
                if (colg + 1 > rg0) s1 = -3.4e38f;
                if (colg     > rg8) s2 = -3.4e38f;
                if (colg + 1 > rg8) s3 = -3.4e38f;
            }
            sc[ni][0] = s0; sc[ni][1] = s1; sc[ni][2] = s2; sc[ni][3] = s3;
            tm0 = fmaxf(tm0, fmaxf(s0, s1));
            tm8 = fmaxf(tm8, fmaxf(s2, s3));
        }
        tm0 = fmaxf(tm0, __shfl_xor_sync(0xffffffff, tm0, 1));
        tm0 = fmaxf(tm0, __shfl_xor_sync(0xffffffff, tm0, 2));
        tm8 = fmaxf(tm8, __shfl_xor_sync(0xffffffff, tm8, 1));
        tm8 = fmaxf(tm8, __shfl_xor_sync(0xffffffff, tm8, 2));
        float mn0 = fmaxf(m0, tm0), mn8 = fmaxf(m8, tm8);
        float al0 = __expf(m0 - mn0), al8 = __expf(m8 - mn8);
        m0 = mn0; m8 = mn8;
        float rs0 = 0.f, rs8 = 0.f;
        #pragma unroll
        for (int ni = 0; ni < 8; ni++) {
            float p0 = __expf(sc[ni][0] - mn0);
            float p1 = __expf(sc[ni][1] - mn0);
            float p2 = __expf(sc[ni][2] - mn8);
            float p3 = __expf(sc[ni][3] - mn8);
            sc[ni][0] = p0; sc[ni][1] = p1; sc[ni][2] = p2; sc[ni][3] = p3;
            rs0 += p0 + p1; rs8 += p2 + p3;
        }
        rs0 += __shfl_xor_sync(0xffffffff, rs0, 1);
        rs0 += __shfl_xor_sync(0xffffffff, rs0, 2);
        rs8 += __shfl_xor_sync(0xffffffff, rs8, 1);
        rs8 += __shfl_xor_sync(0xffffffff, rs8, 2);
        l0 = l0*al0 + rs0;
        l8 = l8*al8 + rs8;
        #pragma unroll
        for (int ni = 0; ni < 8; ni++) {
            Oc[ni][0] *= al0; Oc[ni][1] *= al0;
            Oc[ni][2] *= al8; Oc[ni][3] *= al8;
        }

        uint32_t ph[4][4], pl[4][4];
        #pragma unroll
        for (int ks2 = 0; ks2 < 4; ks2++) {
            float x0 = sc[2*ks2][0],   x1 = sc[2*ks2][1];
            float x2 = sc[2*ks2][2],   x3 = sc[2*ks2][3];
            float y0 = sc[2*ks2+1][0], y1 = sc[2*ks2+1][1];
            float y2 = sc[2*ks2+1][2], y3 = sc[2*ks2+1][3];
            float hx0 = __bfloat162float(__float2bfloat16_rn(x0));
            float hx1 = __bfloat162float(__float2bfloat16_rn(x1));
            float hx2 = __bfloat162float(__float2bfloat16_rn(x2));
            float hx3 = __bfloat162float(__float2bfloat16_rn(x3));
            float hy0 = __bfloat162float(__float2bfloat16_rn(y0));
            float hy1 = __bfloat162float(__float2bfloat16_rn(y1));
            float hy2 = __bfloat162float(__float2bfloat16_rn(y2));
            float hy3 = __bfloat162float(__float2bfloat16_rn(y3));
            ph[ks2][0] = pack_bf2(hx0, hx1);
            ph[ks2][1] = pack_bf2(hx2, hx3);
            ph[ks2][2] = pack_bf2(hy0, hy1);
            ph[ks2][3] = pack_bf2(hy2, hy3);
            pl[ks2][0] = pack_bf2(x0 - hx0, x1 - hx1);
            pl[ks2][1] = pack_bf2(x2 - hx2, x3 - hx3);
            pl[ks2][2] = pack_bf2(y0 - hy0, y1 - hy1);
            pl[ks2][3] = pack_bf2(y2 - hy2, y3 - hy3);
        }

        #pragma unroll
        for (int ks2 = 0; ks2 < 4; ks2++)
            #pragma unroll
            for (int ni = 0; ni < 8; ni++) {
                int nr = ni*8 + r0;
                mma16816(Oc[ni], ph[ks2], Vt[nr][cq + 8*ks2], Vt[nr][cq + 8*ks2 + 4]);
            }
        #pragma unroll
        for (int ks2 = 0; ks2 < 4; ks2++)
            #pragma unroll
            for (int ni = 0; ni < 8; ni++) {
                int nr = ni*8 + r0;
                mma16816(Oc[ni], ph[ks2], Vt[nr][32 + cq + 8*ks2],
                         Vt[nr][32 + cq + 8*ks2 + 4]);
            }
        #pragma unroll
        for (int ks2 = 0; ks2 < 4; ks2++)
            #pragma unroll
            for (int ni = 0; ni < 8; ni++) {
                int nr = ni*8 + r0;
                mma16816(Oc[ni], pl[ks2], Vt[nr][cq + 8*ks2], Vt[nr][cq + 8*ks2 + 4]);
            }
        __syncthreads();
    }

    float i0 = 1.f / l0, i8 = 1.f / l8;
    #pragma unroll
    for (int ni = 0; ni < 8; ni++) {
        int cc = col0 + ni*8 + 2*cq;
        float2 w0 = {Oc[ni][0]*i0, Oc[ni][1]*i0};
        float2 w8 = {Oc[ni][2]*i8, Oc[ni][3]*i8};
        *(float2*)(o + ((size_t)(qrow + r0    )*B_ + b)*oS + cc) = w0;
        *(float2*)(o + ((size_t)(qrow + r0 + 8)*B_ + b)*oS + cc) = w8;
    }
}

// -------- memory retrieval + delta (no attn dependency) -----------------------
__global__ __launch_bounds__(256) void mem_retrieve(
    const float* __restrict__ q, const float* __restrict__ kp,
    const float* __restrict__ vp, const float* __restrict__ memory,
    const float* __restrict__ mem_norm, int l,
    float* __restrict__ content, float* __restrict__ diff, float* __restrict__ cKout,
    int qS, int kvS)
{
    int bn = blockIdx.x;
    int b = bn / NH_, n = bn % NH_;
    int chunk = blockIdx.y;
    int t = threadIdx.x;

    __shared__ float Msh[DH_][DH_+1];
    __shared__ float normsh[DH_];
    __shared__ float cqsh[4][DH_];
    __shared__ float cksh[4][DH_];

    const float* Mg = memory + ((size_t)(l*B_ + b)*NH_ + n)*DH_*DH_;
    for (int idx = t; idx < DH_*DH_; idx += 256) Msh[idx >> 6][idx & 63] = Mg[idx];
    if (t < DH_) normsh[t] = mem_norm[((size_t)(l*B_ + b)*NH_ + n)*DH_ + t];
    __syncthreads();

    int g = t >> 6, d = t & 63;
    int col = n * DH_;
    for (int it = 0; it < 32; ++it) {
        int s = chunk*128 + it*4 + g;
        size_t row = (size_t)(s*B_ + b);
        float qvl = q [row*qS  + col + d];
        float vvl = vp[row*kvS + col + d];
        float cq = qvl > 0.f ? qvl + 1.f : __expf(qvl);
        float ck = vvl > 0.f ? vvl + 1.f : __expf(vvl);
        cqsh[g][d] = cq; cksh[g][d] = ck;
        __syncthreads();
        float accA = 0.f, accB = 0.f, denQ = 0.f, denK = 0.f;
        #pragma unroll 8
        for (int kk = 0; kk < DH_; kk++) {
            float mq = Msh[kk][d];
            accA += cqsh[g][kk] * mq;
            accB += cksh[g][kk] * mq;
            denQ += cqsh[g][kk] * normsh[kk];
            denK += cksh[g][kk] * normsh[kk];
        }
        size_t oidx = row*D_ + col + d;
        content[oidx] = accA / denQ;
        diff[oidx]    = kp[row*kvS + col + d] - accB / denK;
        cKout[oidx]   = ck;
        __syncthreads();
    }
}

// -------- memory update --------------------------------------------------------
__global__ __launch_bounds__(256) void mem_update(
    const float* __restrict__ cK, const float* __restrict__ diff,
    const float* __restrict__ memory, int l, float* __restrict__ outM)
{
    int bn = blockIdx.x;
    int b = bn / NH_, n = bn % NH_;
    __shared__ float aS[16][DH_];
    __shared__ float bS[16][DH_];
    int t = threadIdx.x;
    int tx = t & 15, ty = t >> 4;
    float acc[4][4] = {};
    int col = n * DH_;
    int r  = t >> 4;
    int c4 = (t & 15) * 4;
    for (int s0 = 0; s0 < S_; s0 += 16) {
        size_t row = (size_t)((s0 + r)*B_ + b);
        *(float4*)&aS[r][c4] = *(const float4*)(cK   + row*D_ + col + c4);
        *(float4*)&bS[r][c4] = *(const float4*)(diff + row*D_ + col + c4);
        __syncthreads();
        #pragma unroll
        for (int ss = 0; ss < 16; ss++) {
            float a[4], bb[4];
            #pragma unroll
            for (int u = 0; u < 4; u++) { a[u] = aS[ss][ty*4+u]; bb[u] = bS[ss][tx*4+u]; }
            #pragma unroll
            for (int i = 0; i < 4; i++)
                #pragma unroll
                for (int j = 0; j < 4; j++)
                    acc[i][j] = fmaf(a[i], bb[j], acc[i][j]);
        }
        __syncthreads();
    }
    const float* Mg = memory + ((size_t)(l*B_ + b)*NH_ + n)*DH_*DH_;
    float*       Og = outM   + ((size_t)(l*B_ + b)*NH_ + n)*DH_*DH_;
    #pragma unroll
    for (int i = 0; i < 4; i++)
        #pragma unroll
        for (int j = 0; j < 4; j++) {
            int kk = ty*4 + i, vv = tx*4 + j;
            Og[kk*DH_ + vv] = Mg[kk*DH_ + vv] + acc[i][j];
        }
}

// -------- norm update ----------------------------------------------------------
__global__ __launch_bounds__(512) void norm_update(
    const float* __restrict__ cK, const float* __restrict__ mem_norm, int l,
    float* __restrict__ outN)
{
    int bn = blockIdx.x;
    int b = bn / NH_, n = bn % NH_;
    int t = threadIdx.x;
    int d = t & 63, sg = t >> 6;
    int col = n * DH_;
    float acc = 0.f;
    for (int s = sg; s < S_; s += 8)
        acc += cK[(size_t)(s*B_ + b)*D_ + col + d];
    __shared__ float red[512];
    red[t] = acc; __syncthreads();
    if (t < 256) red[t] += red[t + 256]; __syncthreads();
    if (t < 128) red[t] += red[t + 128]; __syncthreads();
    if (t < 64) {
        size_t o = ((size_t)(l*B_ + b)*NH_ + n)*DH_ + t;
        outN[o] = mem_norm[o] + red[t] + red[t + 64];
    }
}

// -------- layernorm with residual (single-pass, shuffle) -----------------------
__global__ __launch_bounds__(256) void ln_kernel(
    const float* __restrict__ res, const float* __restrict__ y,
    const float* __restrict__ g, const float* __restrict__ bb,
    float* __restrict__ out)
{
    int row = blockIdx.x;
    int t = threadIdx.x, lane = t & 31, warp = t >> 5;
    __shared__ float ws[8], wss[8];
    size_t base = (size_t)row * D_;
    float x0 = res[base + t      ] + y[base + t      ];
    float x1 = res[base + t + 256] + y[base + t + 256];
    float x2 = res[base + t + 512] + y[base + t + 512];
    float s  = x0 + x1 + x2;
    float ss = x0*x0 + x1*x1 + x2*x2;
    #pragma unroll
    for (int off = 16; off > 0; off >>= 1) {
        s  += __shfl_xor_sync(0xffffffff, s,  off);
        ss += __shfl_xor_sync(0xffffffff, ss, off);
    }
    if (lane == 0) { ws[warp] = s; wss[warp] = ss; }
    __syncthreads();
    float S = 0.f, SS = 0.f;
    #pragma unroll
    for (int w = 0; w < 8; w++) { S += ws[w]; SS += wss[w]; }
    float mu  = S * (1.f / 768.f);
    float var = SS * (1.f / 768.f) - mu*mu;
    float inv = rsqrtf(var + 1e-5f);
    out[base + t      ] = (x0 - mu) * inv * g[t      ] + bb[t      ];
    out[base + t + 256] = (x1 - mu) * inv * g[t + 256] + bb[t + 256];
    out[base + t + 512] = (x2 - mu) * inv * g[t + 512] + bb[t + 512];
}

// ------------------------------- launcher -------------------------------------
extern "C" void kernel_launch(void* const* d_in, const int* in_sizes, int n_in,
                              void* d_out, int out_size)
{
    const int*   inp      = (const int*)  d_in[0];
    const float* word_emb = (const float*)d_in[1];
    const float* Wq       = (const float*)d_in[2];
    const float* Wkv      = (const float*)d_in[3];
    const float* Wo       = (const float*)d_in[4];
    const float* ln1g     = (const float*)d_in[5];
    const float* ln1b     = (const float*)d_in[6];
    const float* ffW1     = (const float*)d_in[7];
    const float* ffb1     = (const float*)d_in[8];
    const float* ffW2     = (const float*)d_in[9];
    const float* ffb2     = (const float*)d_in[10];
    const float* ln2g     = (const float*)d_in[11];
    const float* ln2b     = (const float*)d_in[12];
    const float* memory   = (const float*)d_in[13];
    const float* mem_norm = (const float*)d_in[14];

    float* out  = (float*)d_out;
    float* outH = out;
    float* outM = out + (size_t)SB_*D_;
    float* outN = outM + (size_t)L_*B_*NH_*DH_*DH_;

    float *h, *q, *kv, *attn, *content, *cK, *diff, *ff, *out1, *wo;
    float *sa, *isa, *ws, *iws;
    cudaGetSymbolAddress((void**)&h,       g_h);
    cudaGetSymbolAddress((void**)&q,       g_q);
    cudaGetSymbolAddress((void**)&kv,      g_kv);
    cudaGetSymbolAddress((void**)&attn,    g_attn);
    cudaGetSymbolAddress((void**)&content, g_content);
    cudaGetSymbolAddress((void**)&cK,      g_cK);
    cudaGetSymbolAddress((void**)&diff,    g_diff);
    cudaGetSymbolAddress((void**)&ff,      g_ff);
    cudaGetSymbolAddress((void**)&out1,    g_out1);
    cudaGetSymbolAddress((void**)&wo,      g_wo);
    cudaGetSymbolAddress((void**)&sa,      g_sa);
    cudaGetSymbolAddress((void**)&isa,     g_isa);
    cudaGetSymbolAddress((void**)&ws,      g_ws);
    cudaGetSymbolAddress((void**)&iws,     g_iws);

    static cudaStream_t s1 = nullptr;
    static cudaEvent_t evA = nullptr, evB = nullptr, evC = nullptr, evD = nullptr;
    if (!s1) {
        cudaStreamCreateWithFlags(&s1, cudaStreamNonBlocking);
        cudaEventCreateWithFlags(&evA, cudaEventDisableTiming);
        cudaEventCreateWithFlags(&evB, cudaEventDisableTiming);
        cudaEventCreateWithFlags(&evC, cudaEventDisableTiming);
        cudaEventCreateWithFlags(&evD, cudaEventDisableTiming);
    }

    const float gate = 1.0f / (1.0f + expf(-0.01f));

    embed_kernel<<<SB_, 256>>>(inp, word_emb, h);

    // weight row scales (all layers, up-front; overlaps nothing but cheap)
    for (int l = 0; l < L_; l++) {
        float* wl  = ws  + l*WS_;
        float* iwl = iws + l*WS_;
        rowmax_k<<<D_,   256>>>(Wq   + (size_t)l*D_*D_,   nullptr, 0.f, D_,
                                wl + OQ_,  iwl + OQ_);
        rowmax_k<<<2*D_, 256>>>(Wkv  + (size_t)l*2*D_*D_, nullptr, 0.f, D_,
                                wl + OKV_, iwl + OKV_);
        rowmax_k<<<D_,   256>>>(Wo   + (size_t)l*D_*D_,   nullptr, 0.f, D_,
                                wl + OO_,  iwl + OO_);
        rowmax_k<<<DI_,  256>>>(ffW1 + (size_t)l*DI_*D_,  nullptr, 0.f, D_,
                                wl + OW1_, iwl + OW1_);
        rowmax_k<<<D_,   256>>>(ffW2 + (size_t)l*D_*DI_,  nullptr, 0.f, DI_,
                                wl + OW2_, iwl + OW2_);
    }

    for (int l = 0; l < L_; l++) {
        float* wl  = ws  + l*WS_;
        float* iwl = iws + l*WS_;

        // activation scales of h, then merged q|kv projection
        rowmax_k<<<SB_, 256>>>(h, nullptr, 0.f, D_, sa, isa);
        gemm_i8_qkv<<<dim3(18, SB_/128), 256>>>(
            h, Wq + (size_t)l*D_*D_, Wkv + (size_t)l*2*D_*D_,
            sa, isa, wl + OQ_, iwl + OQ_, wl + OKV_, iwl + OKV_, q, kv, D_);

        cudaEventRecord(evA, 0);
        cudaStreamWaitEvent(s1, evA, 0);
        if (l > 0) cudaStreamWaitEvent(s1, evC, 0);

        // main: attention
        attn_mma<<<dim3(8, B_*NH_), 256>>>(q, kv, kv + D_, attn, D_, 2*D_, D_);

        // side: memory path
        mem_retrieve<<<dim3(B_*NH_, 8), 256, 0, s1>>>(q, kv, kv + D_,
                                                      memory, mem_norm, l,
                                                      content, diff, cK, D_, 2*D_);
        cudaEventRecord(evB, s1);
        mem_update<<<B_*NH_, 256, 0, s1>>>(cK, diff, memory, l, outM);
        norm_update<<<B_*NH_, 512, 0, s1>>>(cK, mem_norm, l, outN);
        cudaEventRecord(evD, s1);

        // main: fused rowmax of gated mix, then Wo projection
        cudaStreamWaitEvent(0, evB, 0);
        rowmax_k<<<SB_, 256>>>(content, attn, gate, D_, sa, isa);
        gemm_i8_wo<<<dim3(D_/128, SB_/128), 256>>>(
            content, attn, gate, Wo + (size_t)l*D_*D_,
            sa, isa, wl + OO_, iwl + OO_, wo, D_, D_);
        cudaEventRecord(evC, 0);

        ln_kernel<<<SB_, 256>>>(h, wo, ln1g + l*D_, ln1b + l*D_, out1);

        rowmax_k<<<SB_, 256>>>(out1, nullptr, 0.f, D_, sa, isa);
        gemm_i8<<<dim3(DI_/128, SB_/128), 256>>>(
            out1, ffW1 + (size_t)l*DI_*D_, ffb1 + l*DI_,
            sa, isa, wl + OW1_, iwl + OW1_, ff, DI_, D_, 1);

        rowmax_k<<<SB_, 256>>>(ff, nullptr, 0.f, DI_, sa, isa);
        gemm_i8<<<dim3(D_/128, SB_/128), 256>>>(
            ff, ffW2 + (size_t)l*D_*DI_, ffb2 + l*D_,
            sa, isa, wl + OW2_, iwl + OW2_, q, D_, DI_, 2);

        ln_kernel<<<SB_, 256>>>(out1, q, ln2g + l*D_, ln2b + l*D_, h);
    }

    cudaStreamWaitEvent(0, evD, 0);
    cudaMemcpyAsync(outH, h, (size_t)SB_*D_*sizeof(float),
                    cudaMemcpyDeviceToDevice);
}

// round 12
// speedup vs baseline: 1.1185x; 1.1185x over previous
#include <cuda_runtime.h>
#include <cuda_bf16.h>
#include <math.h>
#include <stdint.h>

// Problem dims
#define S_  1024
#define B_  4
#define D_  768
#define NH_ 12
#define DH_ 64
#define L_  4
#define DI_ 3072
#define SB_ (S_*B_)

// weight scale-table row offsets (per layer)
#define OQ_  0
#define OKV_ 768
#define OO_  2304
#define OW1_ 3072
#define OW2_ 6144
#define WS_  6912
// weight int8-plane byte offsets (per layer)
#define OQB_  0
#define OKVB_ 589824
#define OOB_  1769472
#define OW1B_ 2359296
#define OW2B_ 4718592
#define PLB_  7077888

// ---------------- scratch (device globals; no allocation allowed) ------------
__device__ float g_h[SB_*D_];
__device__ float g_q[SB_*D_];
__device__ float g_kv[SB_*2*D_];
__device__ float g_attn[SB_*D_];
__device__ float g_content[SB_*D_];
__device__ float g_cK[SB_*D_];
__device__ float g_diff[SB_*D_];
__device__ float g_ff[SB_*DI_];
__device__ float g_out1[SB_*D_];
__device__ float g_wo[SB_*D_];
__device__ float g_sa[SB_];
__device__ float g_ws[L_*WS_];
__device__ int8_t g_a1[SB_*DI_], g_a2[SB_*DI_];
__device__ int8_t g_w1[L_*PLB_], g_w2[L_*PLB_];

__device__ __forceinline__ uint32_t pack_bf2(float a, float b) {
    __nv_bfloat162 h = __floats2bfloat162_rn(a, b);
    return *(uint32_t*)&h;
}

__device__ __forceinline__ void mma16816(float* d, const uint32_t* a,
                                         uint32_t b0, uint32_t b1) {
    asm volatile(
        "mma.sync.aligned.m16n8k16.row.col.f32.bf16.bf16.f32 "
        "{%0,%1,%2,%3}, {%4,%5,%6,%7}, {%8,%9}, {%0,%1,%2,%3};"
        : "+f"(d[0]), "+f"(d[1]), "+f"(d[2]), "+f"(d[3])
        : "r"(a[0]), "r"(a[1]), "r"(a[2]), "r"(a[3]), "r"(b0), "r"(b1));
}

__device__ __forceinline__ void mma_s8(int* d, const uint32_t* a,
                                       uint32_t b0, uint32_t b1) {
    asm volatile(
        "mma.sync.aligned.m16n8k32.row.col.s32.s8.s8.s32 "
        "{%0,%1,%2,%3}, {%4,%5,%6,%7}, {%8,%9}, {%0,%1,%2,%3};"
        : "+r"(d[0]), "+r"(d[1]), "+r"(d[2]), "+r"(d[3])
        : "r"(a[0]), "r"(a[1]), "r"(a[2]), "r"(a[3]), "r"(b0), "r"(b1));
}

// ---------------- embedding + sinusoidal positional encoding -----------------
__global__ void embed_kernel(const int* __restrict__ inp,
                             const float* __restrict__ we,
                             float* __restrict__ h)
{
    int row = blockIdx.x;
    int s = row / B_;
    int b = row % B_;
    int t = threadIdx.x;
    int tok = inp[s*B_ + b];
    float pos = (float)(S_ - 1 - s);
    const float lg = logf(10000.0f);
    for (int d = t; d < D_; d += 256) {
        int i = (d < 384) ? d : d - 384;
        float freq = expf(-((float)(2*i) / (float)D_) * lg);
        float ang = pos * freq;
        float pe = (d < 384) ? sinf(ang) : cosf(ang);
        h[(size_t)row*D_ + d] = we[(size_t)tok*D_ + d] * 27.712812921102035f + pe;
    }
}

// -------- fused rowmax + 2-term int8 quantize (optionally gated mix) ----------
__global__ __launch_bounds__(256) void quant_rows(
    const float* __restrict__ X, const float* __restrict__ X2, float gate,
    int K, int8_t* __restrict__ q1, int8_t* __restrict__ q2,
    float* __restrict__ sa)
{
    int row = blockIdx.x, t = threadIdx.x, lane = t & 31, warp = t >> 5;
    __shared__ float wmx[8];
    __shared__ float sm;
    const float* p  = X + (size_t)row*K;
    const float* p2 = X2 ? (X2 + (size_t)row*K) : nullptr;
    float mx = 0.f;
    for (int k = t; k < K; k += 256) {
        float v = p[k];
        if (X2) v = gate*v + (1.f - gate)*p2[k];
        mx = fmaxf(mx, fabsf(v));
    }
    #pragma unroll
    for (int off = 16; off > 0; off >>= 1)
        mx = fmaxf(mx, __shfl_xor_sync(0xffffffff, mx, off));
    if (lane == 0) wmx[warp] = mx;
    __syncthreads();
    if (t == 0) {
        float m = wmx[0];
        #pragma unroll
        for (int w = 1; w < 8; w++) m = fmaxf(m, wmx[w]);
        m = fmaxf(m, 1e-20f);
        sm = m;
        sa[row] = m * (1.f/126.f);
    }
    __syncthreads();
    float inv = 126.f / sm;
    int K4 = K >> 2;
    char4* o1 = (char4*)q1 + (size_t)row*K4;
    char4* o2 = (char4*)q2 + (size_t)row*K4;
    for (int k4 = t; k4 < K4; k4 += 256) {
        int k = k4*4;
        float v0 = p[k], v1 = p[k+1], v2 = p[k+2], v3 = p[k+3];
        if (X2) {
            v0 = gate*v0 + (1.f-gate)*p2[k];
            v1 = gate*v1 + (1.f-gate)*p2[k+1];
            v2 = gate*v2 + (1.f-gate)*p2[k+2];
            v3 = gate*v3 + (1.f-gate)*p2[k+3];
        }
        float y0 = v0*inv, y1 = v1*inv, y2 = v2*inv, y3 = v3*inv;
        int i0 = __float2int_rn(y0), i1 = __float2int_rn(y1);
        int i2 = __float2int_rn(y2), i3 = __float2int_rn(y3);
        char4 c1 = {(char)i0, (char)i1, (char)i2, (char)i3};
        char4 c2 = {(char)__float2int_rn((y0 - (float)i0)*128.f),
                    (char)__float2int_rn((y1 - (float)i1)*128.f),
                    (char)__float2int_rn((y2 - (float)i2)*128.f),
                    (char)__float2int_rn((y3 - (float)i3)*128.f)};
        o1[k4] = c1;
        o2[k4] = c2;
    }
}

// ---------------- int8 NT GEMM (pre-quantized 2-term planes) ------------------
// C = sa[m]*sb[n]*(a1b1 + (a1b2 + a2b1)/128).  3 s8 mmas per 32-k chunk.
#define KP 20
__device__ __forceinline__ void gemm_i8_body(
    const int8_t* __restrict__ A1, const int8_t* __restrict__ A2,
    const int8_t* __restrict__ B1, const int8_t* __restrict__ B2,
    const float* __restrict__ saA, const float* __restrict__ sbB,
    const float* __restrict__ bias, float* __restrict__ C,
    int N, int K, int epi, int m0, int n0)
{
    __shared__ __align__(16) uint32_t As[2][128][KP];
    __shared__ __align__(16) uint32_t Bs[2][128][KP];
    int tid = threadIdx.x;
    int warp = tid >> 5, lane = tid & 31;
    int wm = warp >> 2, wn = warp & 3;
    int r0 = lane >> 2, cq = lane & 3;
    int lrow = tid >> 1;                 // 0..127
    int lw   = (tid & 1) * 4;            // word offset 0 or 4 (= byte 0/16)

    int acc1[16][4], accX[16][4];
    #pragma unroll
    for (int i = 0; i < 16; i++)
        #pragma unroll
        for (int j = 0; j < 4; j++) { acc1[i][j] = 0; accX[i][j] = 0; }

    const int8_t* Ar1 = A1 + (size_t)(m0 + lrow)*K + lw*4;
    const int8_t* Ar2 = A2 + (size_t)(m0 + lrow)*K + lw*4;
    const int8_t* Br1 = B1 + (size_t)(n0 + lrow)*K + lw*4;
    const int8_t* Br2 = B2 + (size_t)(n0 + lrow)*K + lw*4;

    // prologue
    {
        *(uint4*)&As[0][lrow][lw]     = *(const uint4*)Ar1;
        *(uint4*)&As[0][lrow][8+lw]   = *(const uint4*)Ar2;
        *(uint4*)&Bs[0][lrow][lw]     = *(const uint4*)Br1;
        *(uint4*)&Bs[0][lrow][8+lw]   = *(const uint4*)Br2;
    }
    __syncthreads();

    int NC = K >> 5;
    for (int c = 0; c < NC; c++) {
        int buf = c & 1;
        uint4 na1, na2, nb1, nb2;
        bool more = (c + 1 < NC);
        if (more) {
            int kc = (c + 1) << 5;
            na1 = *(const uint4*)(Ar1 + kc);
            na2 = *(const uint4*)(Ar2 + kc);
            nb1 = *(const uint4*)(Br1 + kc);
            nb2 = *(const uint4*)(Br2 + kc);
        }

        uint32_t af[4][4], bf[4][2];
        #pragma unroll
        for (int mi = 0; mi < 4; mi++) {
            int mr = wm*64 + mi*16 + r0;
            af[mi][0] = As[buf][mr    ][cq];
            af[mi][1] = As[buf][mr + 8][cq];
            af[mi][2] = As[buf][mr    ][cq + 4];
            af[mi][3] = As[buf][mr + 8][cq + 4];
        }
        #pragma unroll
        for (int ni = 0; ni < 4; ni++) {
            int nr = wn*32 + ni*8 + r0;
            bf[ni][0] = Bs[buf][nr][cq];
            bf[ni][1] = Bs[buf][nr][cq + 4];
        }
        #pragma unroll
        for (int mi = 0; mi < 4; mi++)
            #pragma unroll
            for (int ni = 0; ni < 4; ni++)
                mma_s8(acc1[mi*4 + ni], af[mi], bf[ni][0], bf[ni][1]);
        // term a1*b2
        #pragma unroll
        for (int ni = 0; ni < 4; ni++) {
            int nr = wn*32 + ni*8 + r0;
            bf[ni][0] = Bs[buf][nr][8 + cq];
            bf[ni][1] = Bs[buf][nr][12 + cq];
        }
        #pragma unroll
        for (int mi = 0; mi < 4; mi++)
            #pragma unroll
            for (int ni = 0; ni < 4; ni++)
                mma_s8(accX[mi*4 + ni], af[mi], bf[ni][0], bf[ni][1]);
        // term a2*b1
        #pragma unroll
        for (int mi = 0; mi < 4; mi++) {
            int mr = wm*64 + mi*16 + r0;
            af[mi][0] = As[buf][mr    ][8 + cq];
            af[mi][1] = As[buf][mr + 8][8 + cq];
            af[mi][2] = As[buf][mr    ][12 + cq];
            af[mi][3] = As[buf][mr + 8][12 + cq];
        }
        #pragma unroll
        for (int ni = 0; ni < 4; ni++) {
            int nr = wn*32 + ni*8 + r0;
            bf[ni][0] = Bs[buf][nr][cq];
            bf[ni][1] = Bs[buf][nr][cq + 4];
        }
        #pragma unroll
        for (int mi = 0; mi < 4; mi++)
            #pragma unroll
            for (int ni = 0; ni < 4; ni++)
                mma_s8(accX[mi*4 + ni], af[mi], bf[ni][0], bf[ni][1]);

        if (more) {
            int nb = buf ^ 1;
            *(uint4*)&As[nb][lrow][lw]   = na1;
            *(uint4*)&As[nb][lrow][8+lw] = na2;
            *(uint4*)&Bs[nb][lrow][lw]   = nb1;
            *(uint4*)&Bs[nb][lrow][8+lw] = nb2;
            __syncthreads();
        }
    }

    #pragma unroll
    for (int mi = 0; mi < 4; mi++) {
        int m = m0 + wm*64 + mi*16 + r0;
        float sa0 = saA[m], sa8 = saA[m + 8];
        #pragma unroll
        for (int ni = 0; ni < 4; ni++) {
            int n = n0 + wn*32 + ni*8 + 2*cq;
            float sb0 = sbB[n], sb1v = sbB[n + 1];
            int* d1 = acc1[mi*4 + ni];
            int* dx = accX[mi*4 + ni];
            float2 v0, v1;
            v0.x = ((float)d1[0] + (float)dx[0]*0.0078125f) * sa0 * sb0;
            v0.y = ((float)d1[1] + (float)dx[1]*0.0078125f) * sa0 * sb1v;
            v1.x = ((float)d1[2] + (float)dx[2]*0.0078125f) * sa8 * sb0;
            v1.y = ((float)d1[3] + (float)dx[3]*0.0078125f) * sa8 * sb1v;
            if (epi == 1) {
                float b0v = bias[n], b1v = bias[n+1];
                v0.x = fmaxf(v0.x + b0v, 0.f); v0.y = fmaxf(v0.y + b1v, 0.f);
                v1.x = fmaxf(v1.x + b0v, 0.f); v1.y = fmaxf(v1.y + b1v, 0.f);
            } else if (epi == 2) {
                float b0v = bias[n], b1v = bias[n+1];
                v0.x += b0v; v0.y += b1v;
                v1.x += b0v; v1.y += b1v;
            }
            *(float2*)(C + (size_t)m*N + n)     = v0;
            *(float2*)(C + (size_t)(m+8)*N + n) = v1;
        }
    }
}

__global__ __launch_bounds__(256) void gemm_i8(
    const int8_t* __restrict__ A1, const int8_t* __restrict__ A2,
    const int8_t* __restrict__ B1, const int8_t* __restrict__ B2,
    const float* __restrict__ sa, const float* __restrict__ sb,
    const float* __restrict__ bias, float* __restrict__ C,
    int N, int K, int epi)
{
    gemm_i8_body(A1, A2, B1, B2, sa, sb, bias, C, N, K, epi,
                 blockIdx.y*128, blockIdx.x*128);
}

// merged Q + KV projection
__global__ __launch_bounds__(256) void gemm_i8_qkv(
    const int8_t* __restrict__ A1, const int8_t* __restrict__ A2,
    const int8_t* __restrict__ Wq1, const int8_t* __restrict__ Wq2,
    const int8_t* __restrict__ Wkv1, const int8_t* __restrict__ Wkv2,
    const float* __restrict__ sa,
    const float* __restrict__ sbq, const float* __restrict__ sbkv,
    float* __restrict__ q, float* __restrict__ kv, int K)
{
    int bx = blockIdx.x, m0 = blockIdx.y*128;
    if (bx < 6)
        gemm_i8_body(A1, A2, Wq1, Wq2, sa, sbq, nullptr, q, D_, K, 0,
                     m0, bx*128);
    else
        gemm_i8_body(A1, A2, Wkv1, Wkv2, sa, sbkv, nullptr, kv, 2*D_, K, 0,
                     m0, (bx - 6)*128);
}

// ------------- tensor-core flash attention (bf16 hi/lo, fp32 acc) -------------
__global__ __launch_bounds__(256) void attn_mma(
    const float* __restrict__ q, const float* __restrict__ k,
    const float* __restrict__ v, float* __restrict__ o,
    int qS, int kvS, int oS)
{
    int qt = 7 - (int)blockIdx.x;
    int bn = blockIdx.y;
    int b = bn / NH_, n = bn % NH_;
    int col0 = n * DH_;
    int t = threadIdx.x, lane = t & 31, warp = t >> 5;
    int r0 = lane >> 2, cq = lane & 3;

    __shared__ __align__(16) uint32_t Ks[64][68];
    __shared__ __align__(16) uint32_t Vt[64][68];

    int qrow = qt*128 + warp*16;

    uint32_t qh[4][4], ql[4][4];
    #pragma unroll
    for (int ks = 0; ks < 4; ks++) {
        int cb = ks*16 + 2*cq;
        #pragma unroll
        for (int u = 0; u < 4; u++) {
            int rr = qrow + r0 + ((u & 1) ? 8 : 0);
            int cc = cb + ((u & 2) ? 8 : 0);
            float2 qv = *(const float2*)(q + ((size_t)rr*B_ + b)*qS + col0 + cc);
            float hx = __bfloat162float(__float2bfloat16_rn(qv.x));
            float hy = __bfloat162float(__float2bfloat16_rn(qv.y));
            qh[ks][u] = pack_bf2(hx, hy);
            ql[ks][u] = pack_bf2(qv.x - hx, qv.y - hy);
        }
    }

    float Oc[8][4];
    #pragma unroll
    for (int i = 0; i < 8; i++)
        #pragma unroll
        for (int j = 0; j < 4; j++) Oc[i][j] = 0.f;
    float m0 = -3.4e38f, m8 = -3.4e38f, l0 = 0.f, l8 = 0.f;

    int nkt = 2*qt + 2;
    for (int kt = 0; kt < nkt; kt++) {
        for (int idx = t; idx < 64*16; idx += 256) {
            int key = idx >> 4, c = idx & 15;
            float4 kv4 = *(const float4*)(k + ((size_t)(kt*64+key)*B_ + b)*kvS
                                            + col0 + 4*c);
            float hx = __bfloat162float(__float2bfloat16_rn(kv4.x));
            float hy = __bfloat162float(__float2bfloat16_rn(kv4.y));
            float hz = __bfloat162float(__float2bfloat16_rn(kv4.z));
            float hw = __bfloat162float(__float2bfloat16_rn(kv4.w));
            Ks[key][2*c  ] = pack_bf2(hx, hy);
            Ks[key][2*c+1] = pack_bf2(hz, hw);
            Ks[key][32 + 2*c  ] = pack_bf2(kv4.x - hx, kv4.y - hy);
            Ks[key][32 + 2*c+1] = pack_bf2(kv4.z - hz, kv4.w - hw);
        }
        #pragma unroll
        for (int it = 0; it < 4; it++) {
            int idx = t + 256*it;
            int j = idx >> 5;
            int d = idx & 31;
            const float* vp0 = v + ((size_t)(kt*64 + 2*j)*B_ + b)*kvS + col0 + 2*d;
            float2 va = *(const float2*)vp0;
            float2 vb = *(const float2*)(vp0 + (size_t)B_*kvS);
            float hax = __bfloat162float(__float2bfloat16_rn(va.x));
            float hay = __bfloat162float(__float2bfloat16_rn(va.y));
            float hbx = __bfloat162float(__float2bfloat16_rn(vb.x));
            float hby = __bfloat162float(__float2bfloat16_rn(vb.y));
            Vt[2*d  ][j] = pack_bf2(hax, hbx);
            Vt[2*d+1][j] = pack_bf2(hay, hby);
            Vt[2*d  ][32 + j] = pack_bf2(va.x - hax, vb.x - hbx);
            Vt[2*d+1][32 + j] = pack_bf2(va.y - hay, vb.y - hby);
        }
        __syncthreads();

        float sc[8][4];
        #pragma unroll
        for (int i = 0; i < 8; i++)
            #pragma unroll
            for (int j = 0; j < 4; j++) sc[i][j] = 0.f;
        #pragma unroll
        for (int ks = 0; ks < 4; ks++)
            #pragma unroll
            for (int ni = 0; ni < 8; ni++) {
                int nr = ni*8 + r0;
                mma16816(sc[ni], qh[ks], Ks[nr][cq + 8*ks], Ks[nr][cq + 8*ks + 4]);
            }
        #pragma unroll
        for (int ks = 0; ks < 4; ks++)
            #pragma unroll
            for (int ni = 0; ni < 8; ni++) {
                int nr = ni*8 + r0;
                mma16816(sc[ni], qh[ks], Ks[nr][32 + cq + 8*ks],
                         Ks[nr][32 + cq + 8*ks + 4]);
            }
        #pragma unroll
        for (int ks = 0; ks < 4; ks++)
            #pragma unroll
            for (int ni = 0; ni < 8; ni++) {
                int nr = ni*8 + r0;
                mma16816(sc[ni], ql[ks], Ks[nr][cq + 8*ks], Ks[nr][cq + 8*ks + 4]);
            }

        const float scale = 0.125f;
        bool diag = (kt >= 2*qt);
        int rg0 = qrow + r0, rg8 = rg0 + 8;
        float tm0 = -3.4e38f, tm8 = -3.4e38f;
        #pragma unroll
        for (int ni = 0; ni < 8; ni++) {
            float s0 = sc[ni][0]*scale, s1 = sc[ni][1]*scale;
            float s2 = sc[ni][2]*scale, s3 = sc[ni][3]*scale;
            if (diag) {
                int colg = kt*64 + ni*8 + 2*cq;
                if (colg     > rg0) s0 = -3.4e38f;
                if (colg + 1 > rg0) s1 = -3.4e38f;
                if (colg     > rg8) s2 = -3.4e38f;
                if (colg + 1 > rg8) s3 = -3.4e38f;
            }
            sc[ni][0] = s0; sc[ni][1] = s1; sc[ni][2] = s2; sc[ni][3] = s3;
            tm0 = fmaxf(tm0, fmaxf(s0, s1));
            tm8 = fmaxf(tm8, fmaxf(s2, s3));
        }
        tm0 = fmaxf(tm0, __shfl_xor_sync(0xffffffff, tm0, 1));
        tm0 = fmaxf(tm0, __shfl_xor_sync(0xffffffff, tm0, 2));
        tm8 = fmaxf(tm8, __shfl_xor_sync(0xffffffff, tm8, 1));
        tm8 = fmaxf(tm8, __shfl_xor_sync(0xffffffff, tm8, 2));
        float mn0 = fmaxf(m0, tm0), mn8 = fmaxf(m8, tm8);
        float al0 = __expf(m0 - mn0), al8 = __expf(m8 - mn8);
        m0 = mn0; m8 = mn8;
        float rs0 = 0.f, rs8 = 0.f;
        #pragma unroll
        for (int ni = 0; ni < 8; ni++) {
            float p0 = __expf(sc[ni][0] - mn0);
            float p1 = __expf(sc[ni][1] - mn0);
            float p2 = __expf(sc[ni][2] - mn8);
            float p3 = __expf(sc[ni][3] - mn8);
            sc[ni][0] = p0; sc[ni][1] = p1; sc[ni][2] = p2; sc[ni][3] = p3;
            rs0 += p0 + p1; rs8 += p2 + p3;
        }
        rs0 += __shfl_xor_sync(0xffffffff, rs0, 1);
        rs0 += __shfl_xor_sync(0xffffffff, rs0, 2);
        rs8 += __shfl_xor_sync(0xffffffff, rs8, 1);
        rs8 += __shfl_xor_sync(0xffffffff, rs8, 2);
        l0 = l0*al0 + rs0;
        l8 = l8*al8 + rs8;
        #pragma unroll
        for (int ni = 0; ni < 8; ni++) {
            Oc[ni][0] *= al0; Oc[ni][1] *= al0;
            Oc[ni][2] *= al8; Oc[ni][3] *= al8;
        }

        uint32_t ph[4][4], pl[4][4];
        #pragma unroll
        for (int ks2 = 0; ks2 < 4; ks2++) {
            float x0 = sc[2*ks2][0],   x1 = sc[2*ks2][1];
            float x2 = sc[2*ks2][2],   x3 = sc[2*ks2][3];
            float y0 = sc[2*ks2+1][0], y1 = sc[2*ks2+1][1];
            float y2 = sc[2*ks2+1][2], y3 = sc[2*ks2+1][3];
            float hx0 = __bfloat162float(__float2bfloat16_rn(x0));
            float hx1 = __bfloat162float(__float2bfloat16_rn(x1));
            float hx2 = __bfloat162float(__float2bfloat16_rn(x2));
            float hx3 = __bfloat162float(__float2bfloat16_rn(x3));
            float hy0 = __bfloat162float(__float2bfloat16_rn(y0));
            float hy1 = __bfloat162float(__float2bfloat16_rn(y1));
            float hy2 = __bfloat162float(__float2bfloat16_rn(y2));
            float hy3 = __bfloat162float(__float2bfloat16_rn(y3));
            ph[ks2][0] = pack_bf2(hx0, hx1);
            ph[ks2][1] = pack_bf2(hx2, hx3);
            ph[ks2][2] = pack_bf2(hy0, hy1);
            ph[ks2][3] = pack_bf2(hy2, hy3);
            pl[ks2][0] = pack_bf2(x0 - hx0, x1 - hx1);
            pl[ks2][1] = pack_bf2(x2 - hx2, x3 - hx3);
            pl[ks2][2] = pack_bf2(y0 - hy0, y1 - hy1);
            pl[ks2][3] = pack_bf2(y2 - hy2, y3 - hy3);
        }

        #pragma unroll
        for (int ks2 = 0; ks2 < 4; ks2++)
            #pragma unroll
            for (int ni = 0; ni < 8; ni++) {
                int nr = ni*8 + r0;
                mma16816(Oc[ni], ph[ks2], Vt[nr][cq + 8*ks2], Vt[nr][cq + 8*ks2 + 4]);
            }
        #pragma unroll
        for (int ks2 = 0; ks2 < 4; ks2++)
            #pragma unroll
            for (int ni = 0; ni < 8; ni++) {
                int nr = ni*8 + r0;
                mma16816(Oc[ni], ph[ks2], Vt[nr][32 + cq + 8*ks2],
                         Vt[nr][32 + cq + 8*ks2 + 4]);
            }
        #pragma unroll
        for (int ks2 = 0; ks2 < 4; ks2++)
            #pragma unroll
            for (int ni = 0; ni < 8; ni++) {
                int nr = ni*8 + r0;
                mma16816(Oc[ni], pl[ks2], Vt[nr][cq + 8*ks2], Vt[nr][cq + 8*ks2 + 4]);
            }
        __syncthreads();
    }

    float i0 = 1.f / l0, i8 = 1.f / l8;
    #pragma unroll
    for (int ni = 0; ni < 8; ni++) {
        int cc = col0 + ni*8 + 2*cq;
        float2 w0 = {Oc[ni][0]*i0, Oc[ni][1]*i0};
        float2 w8 = {Oc[ni][2]*i8, Oc[ni][3]*i8};
        *(float2*)(o + ((size_t)(qrow + r0    )*B_ + b)*oS + cc) = w0;
        *(float2*)(o + ((size_t)(qrow + r0 + 8)*B_ + b)*oS + cc) = w8;
    }
}

// -------- memory retrieval + delta ---------------------------------------------
__global__ __launch_bounds__(256) void mem_retrieve(
    const float* __restrict__ q, const float* __restrict__ kp,
    const float* __restrict__ vp, const float* __restrict__ memory,
    const float* __restrict__ mem_norm, int l,
    float* __restrict__ content, float* __restrict__ diff, float* __restrict__ cKout,
    int qS, int kvS)
{
    int bn = blockIdx.x;
    int b = bn / NH_, n = bn % NH_;
    int chunk = blockIdx.y;
    int t = threadIdx.x;

    __shared__ float Msh[DH_][DH_+1];
    __shared__ float normsh[DH_];
    __shared__ float cqsh[4][DH_];
    __shared__ float cksh[4][DH_];

    const float* Mg = memory + ((size_t)(l*B_ + b)*NH_ + n)*DH_*DH_;
    for (int idx = t; idx < DH_*DH_; idx += 256) Msh[idx >> 6][idx & 63] = Mg[idx];
    if (t < DH_) normsh[t] = mem_norm[((size_t)(l*B_ + b)*NH_ + n)*DH_ + t];
    __syncthreads();

    int g = t >> 6, d = t & 63;
    int col = n * DH_;
    for (int it = 0; it < 32; ++it) {
        int s = chunk*128 + it*4 + g;
        size_t row = (size_t)(s*B_ + b);
        float qvl = q [row*qS  + col + d];
        float vvl = vp[row*kvS + col + d];
        float cq = qvl > 0.f ? qvl + 1.f : __expf(qvl);
        float ck = vvl > 0.f ? vvl + 1.f : __expf(vvl);
        cqsh[g][d] = cq; cksh[g][d] = ck;
        __syncthreads();
        float accA = 0.f, accB = 0.f, denQ = 0.f, denK = 0.f;
        #pragma unroll 8
        for (int kk = 0; kk < DH_; kk++) {
            float mq = Msh[kk][d];
            accA += cqsh[g][kk] * mq;
            accB += cksh[g][kk] * mq;
            denQ += cqsh[g][kk] * normsh[kk];
            denK += cksh[g][kk] * normsh[kk];
        }
        size_t oidx = row*D_ + col + d;
        content[oidx] = accA / denQ;
        diff[oidx]    = kp[row*kvS + col + d] - accB / denK;
        cKout[oidx]   = ck;
        __syncthreads();
    }
}

// -------- memory update --------------------------------------------------------
__global__ __launch_bounds__(256) void mem_update(
    const float* __restrict__ cK, const float* __restrict__ diff,
    const float* __restrict__ memory, int l, float* __restrict__ outM)
{
    int bn = blockIdx.x;
    int b = bn / NH_, n = bn % NH_;
    __shared__ float aS[16][DH_];
    __shared__ float bS[16][DH_];
    int t = threadIdx.x;
    int tx = t & 15, ty = t >> 4;
    float acc[4][4] = {};
    int col = n * DH_;
    int r  = t >> 4;
    int c4 = (t & 15) * 4;
    for (int s0 = 0; s0 < S_; s0 += 16) {
        size_t row = (size_t)((s0 + r)*B_ + b);
        *(float4*)&aS[r][c4] = *(const float4*)(cK   + row*D_ + col + c4);
        *(float4*)&bS[r][c4] = *(const float4*)(diff + row*D_ + col + c4);
        __syncthreads();
        #pragma unroll
        for (int ss = 0; ss < 16; ss++) {
            float a[4], bb[4];
            #pragma unroll
            for (int u = 0; u < 4; u++) { a[u] = aS[ss][ty*4+u]; bb[u] = bS[ss][tx*4+u]; }
            #pragma unroll
            for (int i = 0; i < 4; i++)
                #pragma unroll
                for (int j = 0; j < 4; j++)
                    acc[i][j] = fmaf(a[i], bb[j], acc[i][j]);
        }
        __syncthreads();
    }
    const float* Mg = memory + ((size_t)(l*B_ + b)*NH_ + n)*DH_*DH_;
    float*       Og = outM   + ((size_t)(l*B_ + b)*NH_ + n)*DH_*DH_;
    #pragma unroll
    for (int i = 0; i < 4; i++)
        #pragma unroll
        for (int j = 0; j < 4; j++) {
            int kk = ty*4 + i, vv = tx*4 + j;
            Og[kk*DH_ + vv] = Mg[kk*DH_ + vv] + acc[i][j];
        }
}

// -------- norm update ----------------------------------------------------------
__global__ __launch_bounds__(512) void norm_update(
    const float* __restrict__ cK, const float* __restrict__ mem_norm, int l,
    float* __restrict__ outN)
{
    int bn = blockIdx.x;
    int b = bn / NH_, n = bn % NH_;
    int t = threadIdx.x;
    int d = t & 63, sg = t >> 6;
    int col = n * DH_;
    float acc = 0.f;
    for (int s = sg; s < S_; s += 8)
        acc += cK[(size_t)(s*B_ + b)*D_ + col + d];
    __shared__ float red[512];
    red[t] = acc; __syncthreads();
    if (t < 256) red[t] += red[t + 256]; __syncthreads();
    if (t < 128) red[t] += red[t + 128]; __syncthreads();
    if (t < 64) {
        size_t o = ((size_t)(l*B_ + b)*NH_ + n)*DH_ + t;
        outN[o] = mem_norm[o] + red[t] + red[t + 64];
    }
}

// -------- layernorm with residual (single-pass, shuffle) -----------------------
__global__ __launch_bounds__(256) void ln_kernel(
    const float* __restrict__ res, const float* __restrict__ y,
    const float* __restrict__ g, const float* __restrict__ bb,
    float* __restrict__ out)
{
    int row = blockIdx.x;
    int t = threadIdx.x, lane = t & 31, warp = t >> 5;
    __shared__ float ws[8], wss[8];
    size_t base = (size_t)row * D_;
    float x0 = res[base + t      ] + y[base + t      ];
    float x1 = res[base + t + 256] + y[base + t + 256];
    float x2 = res[base + t + 512] + y[base + t + 512];
    float s  = x0 + x1 + x2;
    float ss = x0*x0 + x1*x1 + x2*x2;
    #pragma unroll
    for (int off = 16; off > 0; off >>= 1) {
        s  += __shfl_xor_sync(0xffffffff, s,  off);
        ss += __shfl_xor_sync(0xffffffff, ss, off);
    }
    if (lane == 0) { ws[warp] = s; wss[warp] = ss; }
    __syncthreads();
    float S = 0.f, SS = 0.f;
    #pragma unroll
    for (int w = 0; w < 8; w++) { S += ws[w]; SS += wss[w]; }
    float mu  = S * (1.f / 768.f);
    float var = SS * (1.f / 768.f) - mu*mu;
    float inv = rsqrtf(var + 1e-5f);
    out[base + t      ] = (x0 - mu) * inv * g[t      ] + bb[t      ];
    out[base + t + 256] = (x1 - mu) * inv * g[t + 256] + bb[t + 256];
    out[base + t + 512] = (x2 - mu) * inv * g[t + 512] + bb[t + 512];
}

// ------------------------------- launcher -------------------------------------
extern "C" void kernel_launch(void* const* d_in, const int* in_sizes, int n_in,
                              void* d_out, int out_size)
{
    const int*   inp      = (const int*)  d_in[0];
    const float* word_emb = (const float*)d_in[1];
    const float* Wq       = (const float*)d_in[2];
    const float* Wkv      = (const float*)d_in[3];
    const float* Wo       = (const float*)d_in[4];
    const float* ln1g     = (const float*)d_in[5];
    const float* ln1b     = (const float*)d_in[6];
    const float* ffW1     = (const float*)d_in[7];
    const float* ffb1     = (const float*)d_in[8];
    const float* ffW2     = (const float*)d_in[9];
    const float* ffb2     = (const float*)d_in[10];
    const float* ln2g     = (const float*)d_in[11];
    const float* ln2b     = (const float*)d_in[12];
    const float* memory   = (const float*)d_in[13];
    const float* mem_norm = (const float*)d_in[14];

    float* out  = (float*)d_out;
    float* outH = out;
    float* outM = out + (size_t)SB_*D_;
    float* outN = outM + (size_t)L_*B_*NH_*DH_*DH_;

    float *h, *q, *kv, *attn, *content, *cK, *diff, *ff, *out1, *wo;
    float *sa, *ws;
    int8_t *a1, *a2, *w1, *w2;
    cudaGetSymbolAddress((void**)&h,       g_h);
    cudaGetSymbolAddress((void**)&q,       g_q);
    cudaGetSymbolAddress((void**)&kv,      g_kv);
    cudaGetSymbolAddress((void**)&attn,    g_attn);
    cudaGetSymbolAddress((void**)&content, g_content);
    cudaGetSymbolAddress((void**)&cK,      g_cK);
    cudaGetSymbolAddress((void**)&diff,    g_diff);
    cudaGetSymbolAddress((void**)&ff,      g_ff);
    cudaGetSymbolAddress((void**)&out1,    g_out1);
    cudaGetSymbolAddress((void**)&wo,      g_wo);
    cudaGetSymbolAddress((void**)&sa,      g_sa);
    cudaGetSymbolAddress((void**)&ws,      g_ws);
    cudaGetSymbolAddress((void**)&a1,      g_a1);
    cudaGetSymbolAddress((void**)&a2,      g_a2);
    cudaGetSymbolAddress((void**)&w1,      g_w1);
    cudaGetSymbolAddress((void**)&w2,      g_w2);

    static cudaStream_t s1 = nullptr;
    static cudaEvent_t evA = nullptr, evB = nullptr, evC = nullptr, evD = nullptr;
    static cudaEvent_t evF = nullptr;
    if (!s1) {
        cudaStreamCreateWithFlags(&s1, cudaStreamNonBlocking);
        cudaEventCreateWithFlags(&evA, cudaEventDisableTiming);
        cudaEventCreateWithFlags(&evB, cudaEventDisableTiming);
        cudaEventCreateWithFlags(&evC, cudaEventDisableTiming);
        cudaEventCreateWithFlags(&evD, cudaEventDisableTiming);
        cudaEventCreateWithFlags(&evF, cudaEventDisableTiming);
    }

    const float gate = 1.0f / (1.0f + expf(-0.01f));

    embed_kernel<<<SB_, 256>>>(inp, word_emb, h);

    // FORK s1 from the capture-origin stream BEFORE any s1 work (capture rule)
    cudaEventRecord(evF, 0);
    cudaStreamWaitEvent(s1, evF, 0);

    // weight quantization (side stream; overlaps embed)
    for (int l = 0; l < L_; l++) {
        int8_t* p1 = w1 + (size_t)l*PLB_;
        int8_t* p2 = w2 + (size_t)l*PLB_;
        float*  wl = ws + l*WS_;
        quant_rows<<<D_,   256, 0, s1>>>(Wq   + (size_t)l*D_*D_,   nullptr, 0.f, D_,
                                         p1 + OQB_,  p2 + OQB_,  wl + OQ_);
        quant_rows<<<2*D_, 256, 0, s1>>>(Wkv  + (size_t)l*2*D_*D_, nullptr, 0.f, D_,
                                         p1 + OKVB_, p2 + OKVB_, wl + OKV_);
        quant_rows<<<D_,   256, 0, s1>>>(Wo   + (size_t)l*D_*D_,   nullptr, 0.f, D_,
                                         p1 + OOB_,  p2 + OOB_,  wl + OO_);
        quant_rows<<<DI_,  256, 0, s1>>>(ffW1 + (size_t)l*DI_*D_,  nullptr, 0.f, D_,
                                         p1 + OW1B_, p2 + OW1B_, wl + OW1_);
        quant_rows<<<D_,   256, 0, s1>>>(ffW2 + (size_t)l*D_*DI_,  nullptr, 0.f, DI_,
                                         p1 + OW2B_, p2 + OW2B_, wl + OW2_);
    }
    cudaEventRecord(evD, s1);
    cudaStreamWaitEvent(0, evD, 0);   // weights quantized before first GEMM

    for (int l = 0; l < L_; l++) {
        int8_t* p1 = w1 + (size_t)l*PLB_;
        int8_t* p2 = w2 + (size_t)l*PLB_;
        float*  wl = ws + l*WS_;

        // quantize h, merged q|kv projection
        quant_rows<<<SB_, 256>>>(h, nullptr, 0.f, D_, a1, a2, sa);
        gemm_i8_qkv<<<dim3(18, SB_/128), 256>>>(
            a1, a2, p1 + OQB_, p2 + OQB_, p1 + OKVB_, p2 + OKVB_,
            sa, wl + OQ_, wl + OKV_, q, kv, D_);

        cudaEventRecord(evA, 0);
        cudaStreamWaitEvent(s1, evA, 0);
        if (l > 0) cudaStreamWaitEvent(s1, evC, 0);

        // main: attention
        attn_mma<<<dim3(8, B_*NH_), 256>>>(q, kv, kv + D_, attn, D_, 2*D_, D_);

        // side: memory path
        mem_retrieve<<<dim3(B_*NH_, 8), 256, 0, s1>>>(q, kv, kv + D_,
                                                      memory, mem_norm, l,
                                                      content, diff, cK, D_, 2*D_);
        cudaEventRecord(evB, s1);
        mem_update<<<B_*NH_, 256, 0, s1>>>(cK, diff, memory, l, outM);
        norm_update<<<B_*NH_, 512, 0, s1>>>(cK, mem_norm, l, outN);
        cudaEventRecord(evD, s1);

        // main: quantize gated mix, Wo projection
        cudaStreamWaitEvent(0, evB, 0);
        quant_rows<<<SB_, 256>>>(content, attn, gate, D_, a1, a2, sa);
        cudaEventRecord(evC, 0);          // content free after this
        gemm_i8<<<dim3(D_/128, SB_/128), 256>>>(
            a1, a2, p1 + OOB_, p2 + OOB_, sa, wl + OO_, nullptr, wo, D_, D_, 0);

        ln_kernel<<<SB_, 256>>>(h, wo, ln1g + l*D_, ln1b + l*D_, out1);

        quant_rows<<<SB_, 256>>>(out1, nullptr, 0.f, D_, a1, a2, sa);
        gemm_i8<<<dim3(DI_/128, SB_/128), 256>>>(
            a1, a2, p1 + OW1B_, p2 + OW1B_, sa, wl + OW1_,
            ffb1 + l*DI_, ff, DI_, D_, 1);

        quant_rows<<<SB_, 256>>>(ff, nullptr, 0.f, DI_, a1, a2, sa);
        gemm_i8<<<dim3(D_/128, SB_/128), 256>>>(
            a1, a2, p1 + OW2B_, p2 + OW2B_, sa, wl + OW2_,
            ffb2 + l*D_, q, D_, DI_, 2);

        ln_kernel<<<SB_, 256>>>(out1, q, ln2g + l*D_, ln2b + l*D_, h);
    }

    cudaStreamWaitEvent(0, evD, 0);
    cudaMemcpyAsync(outH, h, (size_t)SB_*D_*sizeof(float),
                    cudaMemcpyDeviceToDevice);
}

// round 13
// speedup vs baseline: 2.2492x; 2.0109x over previous
#include <cuda_runtime.h>
#include <cuda_bf16.h>
#include <math.h>
#include <stdint.h>

// Problem dims
#define S_  1024
#define B_  4
#define D_  768
#define NH_ 12
#define DH_ 64
#define L_  4
#define DI_ 3072
#define SB_ (S_*B_)

// ---------------- scratch (device globals; no allocation allowed) ------------
__device__ float g_h[SB_*D_];
__device__ float g_q[SB_*D_];
__device__ float g_kv[SB_*2*D_];
__device__ float g_attn[SB_*D_];
__device__ float g_content[SB_*D_];
__device__ float g_cK[SB_*D_];
__device__ float g_diff[SB_*D_];
__device__ float g_ff[SB_*DI_];
__device__ float g_out1[SB_*D_];
__device__ float g_wo[SB_*D_];

// pack two floats into bf16x2 (lo half = first arg)
__device__ __forceinline__ uint32_t pack_bf2(float a, float b) {
    __nv_bfloat162 h = __floats2bfloat162_rn(a, b);
    return *(uint32_t*)&h;
}

__device__ __forceinline__ void mma16816(float* d, const uint32_t* a,
                                         uint32_t b0, uint32_t b1) {
    asm volatile(
        "mma.sync.aligned.m16n8k16.row.col.f32.bf16.bf16.f32 "
        "{%0,%1,%2,%3}, {%4,%5,%6,%7}, {%8,%9}, {%0,%1,%2,%3};"
        : "+f"(d[0]), "+f"(d[1]), "+f"(d[2]), "+f"(d[3])
        : "r"(a[0]), "r"(a[1]), "r"(a[2]), "r"(a[3]), "r"(b0), "r"(b1));
}

// ---------------- embedding + sinusoidal positional encoding -----------------
__global__ void embed_kernel(const int* __restrict__ inp,
                             const float* __restrict__ we,
                             float* __restrict__ h)
{
    int row = blockIdx.x;          // row = s*B + b
    int s = row / B_;
    int b = row % B_;
    int t = threadIdx.x;           // 256
    int tok = inp[s*B_ + b];
    float pos = (float)(S_ - 1 - s);
    const float lg = logf(10000.0f);
    for (int d = t; d < D_; d += 256) {
        int i = (d < 384) ? d : d - 384;
        float freq = expf(-((float)(2*i) / (float)D_) * lg);
        float ang = pos * freq;
        float pe = (d < 384) ? sinf(ang) : cosf(ang);
        h[(size_t)row*D_ + d] = we[(size_t)tok*D_ + d] * 27.712812921102035f + pe;
    }
}

// ---------------- NT GEMM body (bf16 tensor cores, hi/lo split = ~fp32) ------
// C[M,N] = A[M,K] @ B[N,K]^T. 128x128 tile, KT=16, 8 warps, term-major mma.
// FUSE: A := gate*A + (1-gate)*A2 elementwise at load.
// epi: 0 = none, 1 = bias+relu, 2 = bias
#define KT 16
#define KP 20
template <bool FUSE>
__device__ __forceinline__ void gemm_body(
    const float* __restrict__ A, const float* __restrict__ A2, float gate,
    const float* __restrict__ Bm, const float* __restrict__ bias,
    float* __restrict__ C, int N, int K, int epi, int m0, int n0)
{
    __shared__ __align__(16) uint32_t As[2][128][KP];
    __shared__ __align__(16) uint32_t Bs[2][128][KP];
    int tid  = threadIdx.x;
    int warp = tid >> 5, lane = tid & 31;
    int wm = warp >> 2, wn = warp & 3;        // 2 x 4 warp grid
    int r0 = lane >> 2, cq = lane & 3;

    int lr = tid >> 2;          // 0..63
    int lc = (tid & 3) * 4;     // 0,4,8,12 (k offset in floats)
    int wc = lc >> 1;           // word col: 0,2,4,6
    const float* Ap  = A  + (size_t)(m0 + lr)*K + lc;
    const float* A2p = FUSE ? (A2 + (size_t)(m0 + lr)*K + lc) : nullptr;
    const float* Bp  = Bm + (size_t)(n0 + lr)*K + lc;

    float acc[16][4];
    #pragma unroll
    for (int i = 0; i < 16; i++)
        #pragma unroll
        for (int j = 0; j < 4; j++) acc[i][j] = 0.f;

    #define LOAD_A(off)                                                        \
        ({ float4 _a = *(const float4*)(Ap + (off));                           \
           if (FUSE) { float4 _b = *(const float4*)(A2p + (off));              \
               _a.x = gate*_a.x + (1.f-gate)*_b.x;                              \
               _a.y = gate*_a.y + (1.f-gate)*_b.y;                              \
               _a.z = gate*_a.z + (1.f-gate)*_b.z;                              \
               _a.w = gate*_a.w + (1.f-gate)*_b.w; }                            \
           _a; })

    #define STORE_SPLIT(dst, row, vec)                                          \
    {                                                                           \
        float4 _v = (vec);                                                      \
        float hx = __bfloat162float(__float2bfloat16_rn(_v.x));                 \
        float hy = __bfloat162float(__float2bfloat16_rn(_v.y));                 \
        float hz = __bfloat162float(__float2bfloat16_rn(_v.z));                 \
        float hw = __bfloat162float(__float2bfloat16_rn(_v.w));                 \
        dst[row][wc+0] = pack_bf2(hx, hy);                                      \
        dst[row][wc+1] = pack_bf2(hz, hw);                                      \
        dst[row][8+wc+0] = pack_bf2(_v.x - hx, _v.y - hy);                      \
        dst[row][8+wc+1] = pack_bf2(_v.z - hz, _v.w - hw);                      \
    }

    {
        float4 a0v = LOAD_A(0);
        float4 a1v = LOAD_A((size_t)64*K);
        float4 b0v = *(const float4*)Bp;
        float4 b1v = *(const float4*)(Bp + (size_t)64*K);
        STORE_SPLIT(As[0], lr,      a0v);
        STORE_SPLIT(As[0], lr + 64, a1v);
        STORE_SPLIT(Bs[0], lr,      b0v);
        STORE_SPLIT(Bs[0], lr + 64, b1v);
    }
    __syncthreads();

    int buf = 0;
    for (int k0 = KT; k0 < K + KT; k0 += KT) {
        bool more = (k0 < K);
        float4 a0v, a1v, b0v, b1v;
        if (more) {
            a0v = LOAD_A(k0);
            a1v = LOAD_A((size_t)64*K + k0);
            b0v = *(const float4*)(Bp + k0);
            b1v = *(const float4*)(Bp + (size_t)64*K + k0);
        }
        uint32_t ah[4][4], al[4][4], bh[4][2], bl[4][2];
        #pragma unroll
        for (int mi = 0; mi < 4; mi++) {
            int mr = wm*64 + mi*16 + r0;
            ah[mi][0] = As[buf][mr    ][cq];
            ah[mi][1] = As[buf][mr + 8][cq];
            ah[mi][2] = As[buf][mr    ][cq + 4];
            ah[mi][3] = As[buf][mr + 8][cq + 4];
            al[mi][0] = As[buf][mr    ][8 + cq];
            al[mi][1] = As[buf][mr + 8][8 + cq];
            al[mi][2] = As[buf][mr    ][8 + cq + 4];
            al[mi][3] = As[buf][mr + 8][8 + cq + 4];
        }
        #pragma unroll
        for (int ni = 0; ni < 4; ni++) {
            int nr = wn*32 + ni*8 + r0;
            bh[ni][0] = Bs[buf][nr][cq];
            bh[ni][1] = Bs[buf][nr][cq + 4];
            bl[ni][0] = Bs[buf][nr][8 + cq];
            bl[ni][1] = Bs[buf][nr][8 + cq + 4];
        }
        #pragma unroll
        for (int mi = 0; mi < 4; mi++)
            #pragma unroll
            for (int ni = 0; ni < 4; ni++)
                mma16816(acc[mi*4 + ni], ah[mi], bh[ni][0], bh[ni][1]);
        #pragma unroll
        for (int mi = 0; mi < 4; mi++)
            #pragma unroll
            for (int ni = 0; ni < 4; ni++)
                mma16816(acc[mi*4 + ni], ah[mi], bl[ni][0], bl[ni][1]);
        #pragma unroll
        for (int mi = 0; mi < 4; mi++)
            #pragma unroll
            for (int ni = 0; ni < 4; ni++)
                mma16816(acc[mi*4 + ni], al[mi], bh[ni][0], bh[ni][1]);
        if (more) {
            int nb = buf ^ 1;
            STORE_SPLIT(As[nb], lr,      a0v);
            STORE_SPLIT(As[nb], lr + 64, a1v);
            STORE_SPLIT(Bs[nb], lr,      b0v);
            STORE_SPLIT(Bs[nb], lr + 64, b1v);
            __syncthreads();
            buf = nb;
        }
    }
    #undef STORE_SPLIT
    #undef LOAD_A

    #pragma unroll
    for (int mi = 0; mi < 4; mi++) {
        int m = m0 + wm*64 + mi*16 + r0;
        #pragma unroll
        for (int ni = 0; ni < 4; ni++) {
            int n = n0 + wn*32 + ni*8 + 2*cq;
            float* d = acc[mi*4 + ni];
            float2 v0 = {d[0], d[1]};
            float2 v1 = {d[2], d[3]};
            if (epi == 1) {
                float b0v = bias[n], b1v = bias[n+1];
                v0.x = fmaxf(v0.x + b0v, 0.f); v0.y = fmaxf(v0.y + b1v, 0.f);
                v1.x = fmaxf(v1.x + b0v, 0.f); v1.y = fmaxf(v1.y + b1v, 0.f);
            } else if (epi == 2) {
                float b0v = bias[n], b1v = bias[n+1];
                v0.x += b0v; v0.y += b1v;
                v1.x += b0v; v1.y += b1v;
            }
            *(float2*)(C + (size_t)m*N + n)       = v0;
            *(float2*)(C + (size_t)(m+8)*N + n)   = v1;
        }
    }
}

__global__ __launch_bounds__(256) void gemm_bf16s(
    const float* __restrict__ A, const float* __restrict__ Bm,
    const float* __restrict__ bias, float* __restrict__ C,
    int N, int K, int epi)
{
    gemm_body<false>(A, nullptr, 0.f, Bm, bias, C, N, K, epi,
                     blockIdx.y*128, blockIdx.x*128);
}

// fused combine GEMM: C = (gate*A + (1-gate)*A2) @ B^T
__global__ __launch_bounds__(256) void gemm_wo(
    const float* __restrict__ A, const float* __restrict__ A2, float gate,
    const float* __restrict__ Bm, float* __restrict__ C, int N, int K)
{
    gemm_body<true>(A, A2, gate, Bm, nullptr, C, N, K, 0,
                    blockIdx.y*128, blockIdx.x*128);
}

// merged Q + KV projection: blocks 0..5 -> q, 6..17 -> kv
__global__ __launch_bounds__(256) void gemm_qkv(
    const float* __restrict__ A, const float* __restrict__ Wq,
    const float* __restrict__ Wkv, float* __restrict__ q,
    float* __restrict__ kv, int K)
{
    int bx = blockIdx.x, m0 = blockIdx.y*128;
    if (bx < 6)
        gemm_body<false>(A, nullptr, 0.f, Wq,  nullptr, q,  D_,   K, 0, m0, bx*128);
    else
        gemm_body<false>(A, nullptr, 0.f, Wkv, nullptr, kv, 2*D_, K, 0, m0, (bx-6)*128);
}

// ------------- tensor-core flash attention (bf16 hi/lo, fp32 acc) -------------
// grid (48, 8): bn = blockIdx.x, qt = 7 - blockIdx.y  => all heavy CTAs first
__global__ __launch_bounds__(256) void attn_mma(
    const float* __restrict__ q, const float* __restrict__ k,
    const float* __restrict__ v, float* __restrict__ o,
    int qS, int kvS, int oS)
{
    int qt = 7 - (int)blockIdx.y;          // big-work blocks launch first
    int bn = blockIdx.x;
    int b = bn / NH_, n = bn % NH_;
    int col0 = n * DH_;
    int t = threadIdx.x, lane = t & 31, warp = t >> 5;
    int r0 = lane >> 2, cq = lane & 3;

    __shared__ __align__(16) uint32_t Ks[64][68];
    __shared__ __align__(16) uint32_t Vt[64][68];

    int qrow = qt*128 + warp*16;

    uint32_t qh[4][4], ql[4][4];
    #pragma unroll
    for (int ks = 0; ks < 4; ks++) {
        int cb = ks*16 + 2*cq;
        #pragma unroll
        for (int u = 0; u < 4; u++) {
            int rr = qrow + r0 + ((u & 1) ? 8 : 0);
            int cc = cb + ((u & 2) ? 8 : 0);
            float2 qv = *(const float2*)(q + ((size_t)rr*B_ + b)*qS + col0 + cc);
            float hx = __bfloat162float(__float2bfloat16_rn(qv.x));
            float hy = __bfloat162float(__float2bfloat16_rn(qv.y));
            qh[ks][u] = pack_bf2(hx, hy);
            ql[ks][u] = pack_bf2(qv.x - hx, qv.y - hy);
        }
    }

    float Oc[8][4];
    #pragma unroll
    for (int i = 0; i < 8; i++)
        #pragma unroll
        for (int j = 0; j < 4; j++) Oc[i][j] = 0.f;
    float m0 = -3.4e38f, m8 = -3.4e38f, l0 = 0.f, l8 = 0.f;

    int nkt = 2*qt + 2;
    for (int kt = 0; kt < nkt; kt++) {
        for (int idx = t; idx < 64*16; idx += 256) {
            int key = idx >> 4, c = idx & 15;
            float4 kv4 = *(const float4*)(k + ((size_t)(kt*64+key)*B_ + b)*kvS
                                            + col0 + 4*c);
            float hx = __bfloat162float(__float2bfloat16_rn(kv4.x));
            float hy = __bfloat162float(__float2bfloat16_rn(kv4.y));
            float hz = __bfloat162float(__float2bfloat16_rn(kv4.z));
            float hw = __bfloat162float(__float2bfloat16_rn(kv4.w));
            Ks[key][2*c  ] = pack_bf2(hx, hy);
            Ks[key][2*c+1] = pack_bf2(hz, hw);
            Ks[key][32 + 2*c  ] = pack_bf2(kv4.x - hx, kv4.y - hy);
            Ks[key][32 + 2*c+1] = pack_bf2(kv4.z - hz, kv4.w - hw);
        }
        #pragma unroll
        for (int it = 0; it < 4; it++) {
            int idx = t + 256*it;
            int j = idx >> 5;
            int d = idx & 31;
            const float* vp0 = v + ((size_t)(kt*64 + 2*j)*B_ + b)*kvS + col0 + 2*d;
            float2 va = *(const float2*)vp0;
            float2 vb = *(const float2*)(vp0 + (size_t)B_*kvS);
            float hax = __bfloat162float(__float2bfloat16_rn(va.x));
            float hay = __bfloat162float(__float2bfloat16_rn(va.y));
            float hbx = __bfloat162float(__float2bfloat16_rn(vb.x));
            float hby = __bfloat162float(__float2bfloat16_rn(vb.y));
            Vt[2*d  ][j] = pack_bf2(hax, hbx);
            Vt[2*d+1][j] = pack_bf2(hay, hby);
            Vt[2*d  ][32 + j] = pack_bf2(va.x - hax, vb.x - hbx);
            Vt[2*d+1][32 + j] = pack_bf2(va.y - hay, vb.y - hby);
        }
        __syncthreads();

        float sc[8][4];
        #pragma unroll
        for (int i = 0; i < 8; i++)
            #pragma unroll
            for (int j = 0; j < 4; j++) sc[i][j] = 0.f;
        #pragma unroll
        for (int ks = 0; ks < 4; ks++)
            #pragma unroll
            for (int ni = 0; ni < 8; ni++) {
                int nr = ni*8 + r0;
                mma16816(sc[ni], qh[ks], Ks[nr][cq + 8*ks], Ks[nr][cq + 8*ks + 4]);
            }
        #pragma unroll
        for (int ks = 0; ks < 4; ks++)
            #pragma unroll
            for (int ni = 0; ni < 8; ni++) {
                int nr = ni*8 + r0;
                mma16816(sc[ni], qh[ks], Ks[nr][32 + cq + 8*ks],
                         Ks[nr][32 + cq + 8*ks + 4]);
            }
        #pragma unroll
        for (int ks = 0; ks < 4; ks++)
            #pragma unroll
            for (int ni = 0; ni < 8; ni++) {
                int nr = ni*8 + r0;
                mma16816(sc[ni], ql[ks], Ks[nr][cq + 8*ks], Ks[nr][cq + 8*ks + 4]);
            }

        const float scale = 0.125f;
        bool diag = (kt >= 2*qt);
        int rg0 = qrow + r0, rg8 = rg0 + 8;
        float tm0 = -3.4e38f, tm8 = -3.4e38f;
        #pragma unroll
        for (int ni = 0; ni < 8; ni++) {
            float s0 = sc[ni][0]*scale, s1 = sc[ni][1]*scale;
            float s2 = sc[ni][2]*scale, s3 = sc[ni][3]*scale;
            if (diag) {
                int colg = kt*64 + ni*8 + 2*cq;
                if (colg     > rg0) s0 = -3.4e38f;
                if (colg + 1 > rg0) s1 = -3.4e38f;
                if (colg     > rg8) s2 = -3.4e38f;
                if (colg + 1 > rg8) s3 = -3.4e38f;
            }
            sc[ni][0] = s0; sc[ni][1] = s1; sc[ni][2] = s2; sc[ni][3] = s3;
            tm0 = fmaxf(tm0, fmaxf(s0, s1));
            tm8 = fmaxf(tm8, fmaxf(s2, s3));
        }
        tm0 = fmaxf(tm0, __shfl_xor_sync(0xffffffff, tm0, 1));
        tm0 = fmaxf(tm0, __shfl_xor_sync(0xffffffff, tm0, 2));
        tm8 = fmaxf(tm8, __shfl_xor_sync(0xffffffff, tm8, 1));
        tm8 = fmaxf(tm8, __shfl_xor_sync(0xffffffff, tm8, 2));
        float mn0 = fmaxf(m0, tm0), mn8 = fmaxf(m8, tm8);
        float al0 = __expf(m0 - mn0), al8 = __expf(m8 - mn8);
        m0 = mn0; m8 = mn8;
        float rs0 = 0.f, rs8 = 0.f;
        #pragma unroll
        for (int ni = 0; ni < 8; ni++) {
            float p0 = __expf(sc[ni][0] - mn0);
            float p1 = __expf(sc[ni][1] - mn0);
            float p2 = __expf(sc[ni][2] - mn8);
            float p3 = __expf(sc[ni][3] - mn8);
            sc[ni][0] = p0; sc[ni][1] = p1; sc[ni][2] = p2; sc[ni][3] = p3;
            rs0 += p0 + p1; rs8 += p2 + p3;
        }
        rs0 += __shfl_xor_sync(0xffffffff, rs0, 1);
        rs0 += __shfl_xor_sync(0xffffffff, rs0, 2);
        rs8 += __shfl_xor_sync(0xffffffff, rs8, 1);
        rs8 += __shfl_xor_sync(0xffffffff, rs8, 2);
        l0 = l0*al0 + rs0;
        l8 = l8*al8 + rs8;
        #pragma unroll
        for (int ni = 0; ni < 8; ni++) {
            Oc[ni][0] *= al0; Oc[ni][1] *= al0;
            Oc[ni][2] *= al8; Oc[ni][3] *= al8;
        }

        uint32_t ph[4][4], pl[4][4];
        #pragma unroll
        for (int ks2 = 0; ks2 < 4; ks2++) {
            float x0 = sc[2*ks2][0],   x1 = sc[2*ks2][1];
            float x2 = sc[2*ks2][2],   x3 = sc[2*ks2][3];
            float y0 = sc[2*ks2+1][0], y1 = sc[2*ks2+1][1];
            float y2 = sc[2*ks2+1][2], y3 = sc[2*ks2+1][3];
            float hx0 = __bfloat162float(__float2bfloat16_rn(x0));
            float hx1 = __bfloat162float(__float2bfloat16_rn(x1));
            float hx2 = __bfloat162float(__float2bfloat16_rn(x2));
            float hx3 = __bfloat162float(__float2bfloat16_rn(x3));
            float hy0 = __bfloat162float(__float2bfloat16_rn(y0));
            float hy1 = __bfloat162float(__float2bfloat16_rn(y1));
            float hy2 = __bfloat162float(__float2bfloat16_rn(y2));
            float hy3 = __bfloat162float(__float2bfloat16_rn(y3));
            ph[ks2][0] = pack_bf2(hx0, hx1);
            ph[ks2][1] = pack_bf2(hx2, hx3);
            ph[ks2][2] = pack_bf2(hy0, hy1);
            ph[ks2][3] = pack_bf2(hy2, hy3);
            pl[ks2][0] = pack_bf2(x0 - hx0, x1 - hx1);
            pl[ks2][1] = pack_bf2(x2 - hx2, x3 - hx3);
            pl[ks2][2] = pack_bf2(y0 - hy0, y1 - hy1);
            pl[ks2][3] = pack_bf2(y2 - hy2, y3 - hy3);
        }

        #pragma unroll
        for (int ks2 = 0; ks2 < 4; ks2++)
            #pragma unroll
            for (int ni = 0; ni < 8; ni++) {
                int nr = ni*8 + r0;
                mma16816(Oc[ni], ph[ks2], Vt[nr][cq + 8*ks2], Vt[nr][cq + 8*ks2 + 4]);
            }
        #pragma unroll
        for (int ks2 = 0; ks2 < 4; ks2++)
            #pragma unroll
            for (int ni = 0; ni < 8; ni++) {
                int nr = ni*8 + r0;
                mma16816(Oc[ni], ph[ks2], Vt[nr][32 + cq + 8*ks2],
                         Vt[nr][32 + cq + 8*ks2 + 4]);
            }
        #pragma unroll
        for (int ks2 = 0; ks2 < 4; ks2++)
            #pragma unroll
            for (int ni = 0; ni < 8; ni++) {
                int nr = ni*8 + r0;
                mma16816(Oc[ni], pl[ks2], Vt[nr][cq + 8*ks2], Vt[nr][cq + 8*ks2 + 4]);
            }
        __syncthreads();
    }

    float i0 = 1.f / l0, i8 = 1.f / l8;
    #pragma unroll
    for (int ni = 0; ni < 8; ni++) {
        int cc = col0 + ni*8 + 2*cq;
        float2 w0 = {Oc[ni][0]*i0, Oc[ni][1]*i0};
        float2 w8 = {Oc[ni][2]*i8, Oc[ni][3]*i8};
        *(float2*)(o + ((size_t)(qrow + r0    )*B_ + b)*oS + cc) = w0;
        *(float2*)(o + ((size_t)(qrow + r0 + 8)*B_ + b)*oS + cc) = w8;
    }
}

// -------- memory retrieval + delta (no attn dependency) -----------------------
__global__ __launch_bounds__(256) void mem_retrieve(
    const float* __restrict__ q, const float* __restrict__ kp,
    const float* __restrict__ vp, const float* __restrict__ memory,
    const float* __restrict__ mem_norm, int l,
    float* __restrict__ content, float* __restrict__ diff, float* __restrict__ cKout,
    int qS, int kvS)
{
    int bn = blockIdx.x;
    int b = bn / NH_, n = bn % NH_;
    int chunk = blockIdx.y;
    int t = threadIdx.x;

    __shared__ float Msh[DH_][DH_+1];
    __shared__ float normsh[DH_];
    __shared__ float cqsh[4][DH_];
    __shared__ float cksh[4][DH_];

    const float* Mg = memory + ((size_t)(l*B_ + b)*NH_ + n)*DH_*DH_;
    for (int idx = t; idx < DH_*DH_; idx += 256) Msh[idx >> 6][idx & 63] = Mg[idx];
    if (t < DH_) normsh[t] = mem_norm[((size_t)(l*B_ + b)*NH_ + n)*DH_ + t];
    __syncthreads();

    int g = t >> 6, d = t & 63;
    int col = n * DH_;
    for (int it = 0; it < 32; ++it) {
        int s = chunk*128 + it*4 + g;
        size_t row = (size_t)(s*B_ + b);
        float qvl = q [row*qS  + col + d];
        float vvl = vp[row*kvS + col + d];
        float cq = qvl > 0.f ? qvl + 1.f : __expf(qvl);
        float ck = vvl > 0.f ? vvl + 1.f : __expf(vvl);
        cqsh[g][d] = cq; cksh[g][d] = ck;
        __syncthreads();
        float accA = 0.f, accB = 0.f, denQ = 0.f, denK = 0.f;
        #pragma unroll 8
        for (int kk = 0; kk < DH_; kk++) {
            float mq = Msh[kk][d];
            accA += cqsh[g][kk] * mq;
            accB += cksh[g][kk] * mq;
            denQ += cqsh[g][kk] * normsh[kk];
            denK += cksh[g][kk] * normsh[kk];
        }
        size_t oidx = row*D_ + col + d;
        content[oidx] = accA / denQ;
        diff[oidx]    = kp[row*kvS + col + d] - accB / denK;
        cKout[oidx]   = ck;
        __syncthreads();
    }
}

// -------- memory update: newM[k][v] = M[k][v] + sum_s cK[s,k]*diff[s,v] ------
__global__ __launch_bounds__(256) void mem_update(
    const float* __restrict__ cK, const float* __restrict__ diff,
    const float* __restrict__ memory, int l, float* __restrict__ outM)
{
    int bn = blockIdx.x;
    int b = bn / NH_, n = bn % NH_;
    __shared__ float aS[16][DH_];
    __shared__ float bS[16][DH_];
    int t = threadIdx.x;
    int tx = t & 15, ty = t >> 4;
    float acc[4][4] = {};
    int col = n * DH_;
    int r  = t >> 4;
    int c4 = (t & 15) * 4;
    for (int s0 = 0; s0 < S_; s0 += 16) {
        size_t row = (size_t)((s0 + r)*B_ + b);
        *(float4*)&aS[r][c4] = *(const float4*)(cK   + row*D_ + col + c4);
        *(float4*)&bS[r][c4] = *(const float4*)(diff + row*D_ + col + c4);
        __syncthreads();
        #pragma unroll
        for (int ss = 0; ss < 16; ss++) {
            float a[4], bb[4];
            #pragma unroll
            for (int u = 0; u < 4; u++) { a[u] = aS[ss][ty*4+u]; bb[u] = bS[ss][tx*4+u]; }
            #pragma unroll
            for (int i = 0; i < 4; i++)
                #pragma unroll
                for (int j = 0; j < 4; j++)
                    acc[i][j] = fmaf(a[i], bb[j], acc[i][j]);
        }
        __syncthreads();
    }
    const float* Mg = memory + ((size_t)(l*B_ + b)*NH_ + n)*DH_*DH_;
    float*       Og = outM   + ((size_t)(l*B_ + b)*NH_ + n)*DH_*DH_;
    #pragma unroll
    for (int i = 0; i < 4; i++)
        #pragma unroll
        for (int j = 0; j < 4; j++) {
            int kk = ty*4 + i, vv = tx*4 + j;
            Og[kk*DH_ + vv] = Mg[kk*DH_ + vv] + acc[i][j];
        }
}

// -------- norm update: outN = mem_norm + sum_s cK (parallel over s) ----------
__global__ __launch_bounds__(512) void norm_update(
    const float* __restrict__ cK, const float* __restrict__ mem_norm, int l,
    float* __restrict__ outN)
{
    int bn = blockIdx.x;
    int b = bn / NH_, n = bn % NH_;
    int t = threadIdx.x;
    int d = t & 63, sg = t >> 6;
    int col = n * DH_;
    float acc = 0.f;
    for (int s = sg; s < S_; s += 8)
        acc += cK[(size_t)(s*B_ + b)*D_ + col + d];
    __shared__ float red[512];
    red[t] = acc; __syncthreads();
    if (t < 256) red[t] += red[t + 256]; __syncthreads();
    if (t < 128) red[t] += red[t + 128]; __syncthreads();
    if (t < 64) {
        size_t o = ((size_t)(l*B_ + b)*NH_ + n)*DH_ + t;
        outN[o] = mem_norm[o] + red[t] + red[t + 64];
    }
}

// -------- layernorm with residual (192 threads, float4, single-pass) ----------
__global__ __launch_bounds__(192) void ln_kernel(
    const float* __restrict__ res, const float* __restrict__ y,
    const float* __restrict__ g, const float* __restrict__ bb,
    float* __restrict__ out)
{
    int row = blockIdx.x;
    int t = threadIdx.x, lane = t & 31, warp = t >> 5;   // 6 warps
    __shared__ float ws[6], wss[6];
    size_t base = (size_t)row * D_;
    float4 xr = *(const float4*)(res + base + 4*t);
    float4 yr = *(const float4*)(y   + base + 4*t);
    float4 x = {xr.x + yr.x, xr.y + yr.y, xr.z + yr.z, xr.w + yr.w};
    float s  = x.x + x.y + x.z + x.w;
    float ss = x.x*x.x + x.y*x.y + x.z*x.z + x.w*x.w;
    #pragma unroll
    for (int off = 16; off > 0; off >>= 1) {
        s  += __shfl_xor_sync(0xffffffff, s,  off);
        ss += __shfl_xor_sync(0xffffffff, ss, off);
    }
    if (lane == 0) { ws[warp] = s; wss[warp] = ss; }
    __syncthreads();
    float S = 0.f, SS = 0.f;
    #pragma unroll
    for (int w = 0; w < 6; w++) { S += ws[w]; SS += wss[w]; }
    float mu  = S * (1.f / 768.f);
    float var = SS * (1.f / 768.f) - mu*mu;
    float inv = rsqrtf(var + 1e-5f);
    float4 gv = *(const float4*)(g  + 4*t);
    float4 bv = *(const float4*)(bb + 4*t);
    float4 o4;
    o4.x = (x.x - mu) * inv * gv.x + bv.x;
    o4.y = (x.y - mu) * inv * gv.y + bv.y;
    o4.z = (x.z - mu) * inv * gv.z + bv.z;
    o4.w = (x.w - mu) * inv * gv.w + bv.w;
    *(float4*)(out + base + 4*t) = o4;
}

// ------------------------------- launcher -------------------------------------
extern "C" void kernel_launch(void* const* d_in, const int* in_sizes, int n_in,
                              void* d_out, int out_size)
{
    const int*   inp      = (const int*)  d_in[0];
    const float* word_emb = (const float*)d_in[1];
    const float* Wq       = (const float*)d_in[2];
    const float* Wkv      = (const float*)d_in[3];
    const float* Wo       = (const float*)d_in[4];
    const float* ln1g     = (const float*)d_in[5];
    const float* ln1b     = (const float*)d_in[6];
    const float* ffW1     = (const float*)d_in[7];
    const float* ffb1     = (const float*)d_in[8];
    const float* ffW2     = (const float*)d_in[9];
    const float* ffb2     = (const float*)d_in[10];
    const float* ln2g     = (const float*)d_in[11];
    const float* ln2b     = (const float*)d_in[12];
    const float* memory   = (const float*)d_in[13];
    const float* mem_norm = (const float*)d_in[14];

    float* out  = (float*)d_out;
    float* outH = out;                         // (S,B,D)
    float* outM = out + (size_t)SB_*D_;        // (L,B,NH,DH,DH)
    float* outN = outM + (size_t)L_*B_*NH_*DH_*DH_;  // (L,B,NH,DH)

    float *h, *q, *kv, *attn, *content, *cK, *diff, *ff, *out1, *wo;
    cudaGetSymbolAddress((void**)&h,       g_h);
    cudaGetSymbolAddress((void**)&q,       g_q);
    cudaGetSymbolAddress((void**)&kv,      g_kv);
    cudaGetSymbolAddress((void**)&attn,    g_attn);
    cudaGetSymbolAddress((void**)&content, g_content);
    cudaGetSymbolAddress((void**)&cK,      g_cK);
    cudaGetSymbolAddress((void**)&diff,    g_diff);
    cudaGetSymbolAddress((void**)&ff,      g_ff);
    cudaGetSymbolAddress((void**)&out1,    g_out1);
    cudaGetSymbolAddress((void**)&wo,      g_wo);

    static cudaStream_t s1 = nullptr;
    static cudaEvent_t evA = nullptr, evB = nullptr, evC = nullptr, evD = nullptr;
    if (!s1) {
        cudaStreamCreateWithFlags(&s1, cudaStreamNonBlocking);
        cudaEventCreateWithFlags(&evA, cudaEventDisableTiming);
        cudaEventCreateWithFlags(&evB, cudaEventDisableTiming);
        cudaEventCreateWithFlags(&evC, cudaEventDisableTiming);
        cudaEventCreateWithFlags(&evD, cudaEventDisableTiming);
    }

    const float gate = 1.0f / (1.0f + expf(-0.01f));

    embed_kernel<<<SB_, 256>>>(inp, word_emb, h);

    for (int l = 0; l < L_; l++) {
        // merged q|kv projection (one 576-block launch)
        gemm_qkv<<<dim3(18, SB_/128), 256>>>(h, Wq + (size_t)l*D_*D_,
                                             Wkv + (size_t)l*2*D_*D_, q, kv, D_);
        // fork side stream after qkv
        cudaEventRecord(evA, 0);
        cudaStreamWaitEvent(s1, evA, 0);
        if (l > 0) cudaStreamWaitEvent(s1, evC, 0);   // content free after Wo(l-1)

        // main stream: local causal attention (heavy CTAs first)
        attn_mma<<<dim3(B_*NH_, 8), 256>>>(q, kv /*k*/, kv + D_ /*v*/, attn,
                                           D_, 2*D_, D_);

        // side stream: memory path (content/diff/cK, M & norm updates)
        mem_retrieve<<<dim3(B_*NH_, 8), 256, 0, s1>>>(q, kv /*k*/, kv + D_ /*v*/,
                                                      memory, mem_norm, l,
                                                      content, diff, cK, D_, 2*D_);
        cudaEventRecord(evB, s1);
        mem_update<<<B_*NH_, 256, 0, s1>>>(cK, diff, memory, l, outM);
        norm_update<<<B_*NH_, 512, 0, s1>>>(cK, mem_norm, l, outN);
        cudaEventRecord(evD, s1);

        // main stream: Wo projection with fused gated combine
        cudaStreamWaitEvent(0, evB, 0);               // content ready
        gemm_wo<<<dim3(D_/128, SB_/128), 256>>>(content, attn, gate,
                                                Wo + (size_t)l*D_*D_, wo, D_, D_);
        cudaEventRecord(evC, 0);

        // ln1: out1 = LN(h + wo)
        ln_kernel<<<SB_, 192>>>(h, wo, ln1g + l*D_, ln1b + l*D_, out1);
        // ff1 = relu(out1 @ W1^T + b1)
        gemm_bf16s<<<dim3(DI_/128, SB_/128), 256>>>(out1, ffW1 + (size_t)l*DI_*D_,
                                                    ffb1 + l*DI_, ff, DI_, D_, 1);
        // ff2 = ff1 @ W2^T + b2 -> q buffer (dead until next layer's qkv)
        gemm_bf16s<<<dim3(D_/128, SB_/128), 256>>>(ff, ffW2 + (size_t)l*D_*DI_,
                                                   ffb2 + l*D_, q, D_, DI_, 2);
        // ln2: h = LN(out1 + ff2)
        ln_kernel<<<SB_, 192>>>(out1, q, ln2g + l*D_, ln2b + l*D_, h);
    }

    // join side stream before finishing
    cudaStreamWaitEvent(0, evD, 0);
    cudaMemcpyAsync(outH, h, (size_t)SB_*D_*sizeof(float),
                    cudaMemcpyDeviceToDevice);
}

// round 14
// speedup vs baseline: 2.2800x; 1.0137x over previous
#include <cuda_runtime.h>
#include <cuda_bf16.h>
#include <math.h>
#include <stdint.h>

// Problem dims
#define S_  1024
#define B_  4
#define D_  768
#define NH_ 12
#define DH_ 64
#define L_  4
#define DI_ 3072
#define SB_ (S_*B_)

// ---------------- scratch (device globals; no allocation allowed) ------------
__device__ float g_h[SB_*D_];
__device__ float g_q[SB_*D_];
__device__ float g_kv[SB_*2*D_];
__device__ float g_attn[SB_*D_];
__device__ float g_content[SB_*D_];
__device__ float g_cK[SB_*D_];
__device__ float g_diff[SB_*D_];
__device__ float g_ff[SB_*DI_];
__device__ float g_out1[SB_*D_];
__device__ float g_wo[SB_*D_];

// pack two floats into bf16x2 (lo half = first arg)
__device__ __forceinline__ uint32_t pack_bf2(float a, float b) {
    __nv_bfloat162 h = __floats2bfloat162_rn(a, b);
    return *(uint32_t*)&h;
}

__device__ __forceinline__ void mma16816(float* d, const uint32_t* a,
                                         uint32_t b0, uint32_t b1) {
    asm volatile(
        "mma.sync.aligned.m16n8k16.row.col.f32.bf16.bf16.f32 "
        "{%0,%1,%2,%3}, {%4,%5,%6,%7}, {%8,%9}, {%0,%1,%2,%3};"
        : "+f"(d[0]), "+f"(d[1]), "+f"(d[2]), "+f"(d[3])
        : "r"(a[0]), "r"(a[1]), "r"(a[2]), "r"(a[3]), "r"(b0), "r"(b1));
}

// ---------------- embedding + sinusoidal positional encoding -----------------
__global__ void embed_kernel(const int* __restrict__ inp,
                             const float* __restrict__ we,
                             float* __restrict__ h)
{
    int row = blockIdx.x;          // row = s*B + b
    int s = row / B_;
    int b = row % B_;
    int t = threadIdx.x;           // 256
    int tok = inp[s*B_ + b];
    float pos = (float)(S_ - 1 - s);
    const float lg = logf(10000.0f);
    for (int d = t; d < D_; d += 256) {
        int i = (d < 384) ? d : d - 384;
        float freq = expf(-((float)(2*i) / (float)D_) * lg);
        float ang = pos * freq;
        float pe = (d < 384) ? sinf(ang) : cosf(ang);
        h[(size_t)row*D_ + d] = we[(size_t)tok*D_ + d] * 27.712812921102035f + pe;
    }
}

// ---------------- NT GEMM body (bf16 tensor cores, hi/lo split = ~fp32) ------
#define KT 16
#define KP 20
template <bool FUSE>
__device__ __forceinline__ void gemm_body(
    const float* __restrict__ A, const float* __restrict__ A2, float gate,
    const float* __restrict__ Bm, const float* __restrict__ bias,
    float* __restrict__ C, int N, int K, int epi, int m0, int n0)
{
    __shared__ __align__(16) uint32_t As[2][128][KP];
    __shared__ __align__(16) uint32_t Bs[2][128][KP];
    int tid  = threadIdx.x;
    int warp = tid >> 5, lane = tid & 31;
    int wm = warp >> 2, wn = warp & 3;        // 2 x 4 warp grid
    int r0 = lane >> 2, cq = lane & 3;

    int lr = tid >> 2;          // 0..63
    int lc = (tid & 3) * 4;     // 0,4,8,12 (k offset in floats)
    int wc = lc >> 1;           // word col: 0,2,4,6
    const float* Ap  = A  + (size_t)(m0 + lr)*K + lc;
    const float* A2p = FUSE ? (A2 + (size_t)(m0 + lr)*K + lc) : nullptr;
    const float* Bp  = Bm + (size_t)(n0 + lr)*K + lc;

    float acc[16][4];
    #pragma unroll
    for (int i = 0; i < 16; i++)
        #pragma unroll
        for (int j = 0; j < 4; j++) acc[i][j] = 0.f;

    #define LOAD_A(off)                                                        \
        ({ float4 _a = *(const float4*)(Ap + (off));                           \
           if (FUSE) { float4 _b = *(const float4*)(A2p + (off));              \
               _a.x = gate*_a.x + (1.f-gate)*_b.x;                              \
               _a.y = gate*_a.y + (1.f-gate)*_b.y;                              \
               _a.z = gate*_a.z + (1.f-gate)*_b.z;                              \
               _a.w = gate*_a.w + (1.f-gate)*_b.w; }                            \
           _a; })

    #define STORE_SPLIT(dst, row, vec)                                          \
    {                                                                           \
        float4 _v = (vec);                                                      \
        float hx = __bfloat162float(__float2bfloat16_rn(_v.x));                 \
        float hy = __bfloat162float(__float2bfloat16_rn(_v.y));                 \
        float hz = __bfloat162float(__float2bfloat16_rn(_v.z));                 \
        float hw = __bfloat162float(__float2bfloat16_rn(_v.w));                 \
        dst[row][wc+0] = pack_bf2(hx, hy);                                      \
        dst[row][wc+1] = pack_bf2(hz, hw);                                      \
        dst[row][8+wc+0] = pack_bf2(_v.x - hx, _v.y - hy);                      \
        dst[row][8+wc+1] = pack_bf2(_v.z - hz, _v.w - hw);                      \
    }

    {
        float4 a0v = LOAD_A(0);
        float4 a1v = LOAD_A((size_t)64*K);
        float4 b0v = *(const float4*)Bp;
        float4 b1v = *(const float4*)(Bp + (size_t)64*K);
        STORE_SPLIT(As[0], lr,      a0v);
        STORE_SPLIT(As[0], lr + 64, a1v);
        STORE_SPLIT(Bs[0], lr,      b0v);
        STORE_SPLIT(Bs[0], lr + 64, b1v);
    }
    __syncthreads();

    int buf = 0;
    for (int k0 = KT; k0 < K + KT; k0 += KT) {
        bool more = (k0 < K);
        float4 a0v, a1v, b0v, b1v;
        if (more) {
            a0v = LOAD_A(k0);
            a1v = LOAD_A((size_t)64*K + k0);
            b0v = *(const float4*)(Bp + k0);
            b1v = *(const float4*)(Bp + (size_t)64*K + k0);
        }
        uint32_t ah[4][4], al[4][4], bh[4][2], bl[4][2];
        #pragma unroll
        for (int mi = 0; mi < 4; mi++) {
            int mr = wm*64 + mi*16 + r0;
            ah[mi][0] = As[buf][mr    ][cq];
            ah[mi][1] = As[buf][mr + 8][cq];
            ah[mi][2] = As[buf][mr    ][cq + 4];
            ah[mi][3] = As[buf][mr + 8][cq + 4];
            al[mi][0] = As[buf][mr    ][8 + cq];
            al[mi][1] = As[buf][mr + 8][8 + cq];
            al[mi][2] = As[buf][mr    ][8 + cq + 4];
            al[mi][3] = As[buf][mr + 8][8 + cq + 4];
        }
        #pragma unroll
        for (int ni = 0; ni < 4; ni++) {
            int nr = wn*32 + ni*8 + r0;
            bh[ni][0] = Bs[buf][nr][cq];
            bh[ni][1] = Bs[buf][nr][cq + 4];
            bl[ni][0] = Bs[buf][nr][8 + cq];
            bl[ni][1] = Bs[buf][nr][8 + cq + 4];
        }
        #pragma unroll
        for (int mi = 0; mi < 4; mi++)
            #pragma unroll
            for (int ni = 0; ni < 4; ni++)
                mma16816(acc[mi*4 + ni], ah[mi], bh[ni][0], bh[ni][1]);
        #pragma unroll
        for (int mi = 0; mi < 4; mi++)
            #pragma unroll
            for (int ni = 0; ni < 4; ni++)
                mma16816(acc[mi*4 + ni], ah[mi], bl[ni][0], bl[ni][1]);
        #pragma unroll
        for (int mi = 0; mi < 4; mi++)
            #pragma unroll
            for (int ni = 0; ni < 4; ni++)
                mma16816(acc[mi*4 + ni], al[mi], bh[ni][0], bh[ni][1]);
        if (more) {
            int nb = buf ^ 1;
            STORE_SPLIT(As[nb], lr,      a0v);
            STORE_SPLIT(As[nb], lr + 64, a1v);
            STORE_SPLIT(Bs[nb], lr,      b0v);
            STORE_SPLIT(Bs[nb], lr + 64, b1v);
            __syncthreads();
            buf = nb;
        }
    }
    #undef STORE_SPLIT
    #undef LOAD_A

    #pragma unroll
    for (int mi = 0; mi < 4; mi++) {
        int m = m0 + wm*64 + mi*16 + r0;
        #pragma unroll
        for (int ni = 0; ni < 4; ni++) {
            int n = n0 + wn*32 + ni*8 + 2*cq;
            float* d = acc[mi*4 + ni];
            float2 v0 = {d[0], d[1]};
            float2 v1 = {d[2], d[3]};
            if (epi == 1) {
                float b0v = bias[n], b1v = bias[n+1];
                v0.x = fmaxf(v0.x + b0v, 0.f); v0.y = fmaxf(v0.y + b1v, 0.f);
                v1.x = fmaxf(v1.x + b0v, 0.f); v1.y = fmaxf(v1.y + b1v, 0.f);
            } else if (epi == 2) {
                float b0v = bias[n], b1v = bias[n+1];
                v0.x += b0v; v0.y += b1v;
                v1.x += b0v; v1.y += b1v;
            }
            *(float2*)(C + (size_t)m*N + n)       = v0;
            *(float2*)(C + (size_t)(m+8)*N + n)   = v1;
        }
    }
}

__global__ __launch_bounds__(256) void gemm_bf16s(
    const float* __restrict__ A, const float* __restrict__ Bm,
    const float* __restrict__ bias, float* __restrict__ C,
    int N, int K, int epi)
{
    gemm_body<false>(A, nullptr, 0.f, Bm, bias, C, N, K, epi,
                     blockIdx.y*128, blockIdx.x*128);
}

// fused combine GEMM: C = (gate*A + (1-gate)*A2) @ B^T
__global__ __launch_bounds__(256) void gemm_wo(
    const float* __restrict__ A, const float* __restrict__ A2, float gate,
    const float* __restrict__ Bm, float* __restrict__ C, int N, int K)
{
    gemm_body<true>(A, A2, gate, Bm, nullptr, C, N, K, 0,
                    blockIdx.y*128, blockIdx.x*128);
}

// merged Q + KV projection: blocks 0..5 -> q, 6..17 -> kv
__global__ __launch_bounds__(256) void gemm_qkv(
    const float* __restrict__ A, const float* __restrict__ Wq,
    const float* __restrict__ Wkv, float* __restrict__ q,
    float* __restrict__ kv, int K)
{
    int bx = blockIdx.x, m0 = blockIdx.y*128;
    if (bx < 6)
        gemm_body<false>(A, nullptr, 0.f, Wq,  nullptr, q,  D_,   K, 0, m0, bx*128);
    else
        gemm_body<false>(A, nullptr, 0.f, Wkv, nullptr, kv, 2*D_, K, 0, m0, (bx-6)*128);
}

// ------------- tensor-core flash attention (bf16 hi/lo, fp32 acc) -------------
// 64-query tiles, 128 threads (4 warps x 16 rows). grid (48, 16),
// qt = 15 - blockIdx.y so heavy CTAs launch first. 2 CTAs/SM.
__global__ __launch_bounds__(128) void attn_mma(
    const float* __restrict__ q, const float* __restrict__ k,
    const float* __restrict__ v, float* __restrict__ o,
    int qS, int kvS, int oS)
{
    int qt = 15 - (int)blockIdx.y;         // big-work blocks launch first
    int bn = blockIdx.x;
    int b = bn / NH_, n = bn % NH_;
    int col0 = n * DH_;
    int t = threadIdx.x, lane = t & 31, warp = t >> 5;   // 4 warps
    int r0 = lane >> 2, cq = lane & 3;

    __shared__ __align__(16) uint32_t Ks[64][68];
    __shared__ __align__(16) uint32_t Vt[64][68];

    int qrow = qt*64 + warp*16;

    uint32_t qh[4][4], ql[4][4];
    #pragma unroll
    for (int ks = 0; ks < 4; ks++) {
        int cb = ks*16 + 2*cq;
        #pragma unroll
        for (int u = 0; u < 4; u++) {
            int rr = qrow + r0 + ((u & 1) ? 8 : 0);
            int cc = cb + ((u & 2) ? 8 : 0);
            float2 qv = *(const float2*)(q + ((size_t)rr*B_ + b)*qS + col0 + cc);
            float hx = __bfloat162float(__float2bfloat16_rn(qv.x));
            float hy = __bfloat162float(__float2bfloat16_rn(qv.y));
            qh[ks][u] = pack_bf2(hx, hy);
            ql[ks][u] = pack_bf2(qv.x - hx, qv.y - hy);
        }
    }

    float Oc[8][4];
    #pragma unroll
    for (int i = 0; i < 8; i++)
        #pragma unroll
        for (int j = 0; j < 4; j++) Oc[i][j] = 0.f;
    float m0 = -3.4e38f, m8 = -3.4e38f, l0 = 0.f, l8 = 0.f;

    int nkt = qt + 1;
    for (int kt = 0; kt < nkt; kt++) {
        // K tile [64 keys][64 dims] (128 threads: 8 rows per pass)
        for (int idx = t; idx < 64*16; idx += 128) {
            int key = idx >> 4, c = idx & 15;
            float4 kv4 = *(const float4*)(k + ((size_t)(kt*64+key)*B_ + b)*kvS
                                            + col0 + 4*c);
            float hx = __bfloat162float(__float2bfloat16_rn(kv4.x));
            float hy = __bfloat162float(__float2bfloat16_rn(kv4.y));
            float hz = __bfloat162float(__float2bfloat16_rn(kv4.z));
            float hw = __bfloat162float(__float2bfloat16_rn(kv4.w));
            Ks[key][2*c  ] = pack_bf2(hx, hy);
            Ks[key][2*c+1] = pack_bf2(hz, hw);
            Ks[key][32 + 2*c  ] = pack_bf2(kv4.x - hx, kv4.y - hy);
            Ks[key][32 + 2*c+1] = pack_bf2(kv4.z - hz, kv4.w - hw);
        }
        // V^T tile
        #pragma unroll
        for (int it = 0; it < 8; it++) {
            int idx = t + 128*it;           // 0..1023
            int j = idx >> 5;               // keypair 0..31
            int d = idx & 31;               // dimpair 0..31
            const float* vp0 = v + ((size_t)(kt*64 + 2*j)*B_ + b)*kvS + col0 + 2*d;
            float2 va = *(const float2*)vp0;
            float2 vb = *(const float2*)(vp0 + (size_t)B_*kvS);
            float hax = __bfloat162float(__float2bfloat16_rn(va.x));
            float hay = __bfloat162float(__float2bfloat16_rn(va.y));
            float hbx = __bfloat162float(__float2bfloat16_rn(vb.x));
            float hby = __bfloat162float(__float2bfloat16_rn(vb.y));
            Vt[2*d  ][j] = pack_bf2(hax, hbx);
            Vt[2*d+1][j] = pack_bf2(hay, hby);
            Vt[2*d  ][32 + j] = pack_bf2(va.x - hax, vb.x - hbx);
            Vt[2*d+1][32 + j] = pack_bf2(va.y - hay, vb.y - hby);
        }
        __syncthreads();

        float sc[8][4];
        #pragma unroll
        for (int i = 0; i < 8; i++)
            #pragma unroll
            for (int j = 0; j < 4; j++) sc[i][j] = 0.f;
        #pragma unroll
        for (int ks = 0; ks < 4; ks++)
            #pragma unroll
            for (int ni = 0; ni < 8; ni++) {
                int nr = ni*8 + r0;
                mma16816(sc[ni], qh[ks], Ks[nr][cq + 8*ks], Ks[nr][cq + 8*ks + 4]);
            }
        #pragma unroll
        for (int ks = 0; ks < 4; ks++)
            #pragma unroll
            for (int ni = 0; ni < 8; ni++) {
                int nr = ni*8 + r0;
                mma16816(sc[ni], qh[ks], Ks[nr][32 + cq + 8*ks],
                         Ks[nr][32 + cq + 8*ks + 4]);
            }
        #pragma unroll
        for (int ks = 0; ks < 4; ks++)
            #pragma unroll
            for (int ni = 0; ni < 8; ni++) {
                int nr = ni*8 + r0;
                mma16816(sc[ni], ql[ks], Ks[nr][cq + 8*ks], Ks[nr][cq + 8*ks + 4]);
            }

        const float scale = 0.125f;
        bool diag = (kt == qt);
        int rg0 = qrow + r0, rg8 = rg0 + 8;
        float tm0 = -3.4e38f, tm8 = -3.4e38f;
        #pragma unroll
        for (int ni = 0; ni < 8; ni++) {
            float s0 = sc[ni][0]*scale, s1 = sc[ni][1]*scale;
            float s2 = sc[ni][2]*scale, s3 = sc[ni][3]*scale;
            if (diag) {
                int colg = kt*64 + ni*8 + 2*cq;
                if (colg     > rg0) s0 = -3.4e38f;
                if (colg + 1 > rg0) s1 = -3.4e38f;
                if (colg     > rg8) s2 = -3.4e38f;
                if (colg + 1 > rg8) s3 = -3.4e38f;
            }
            sc[ni][0] = s0; sc[ni][1] = s1; sc[ni][2] = s2; sc[ni][3] = s3;
            tm0 = fmaxf(tm0, fmaxf(s0, s1));
            tm8 = fmaxf(tm8, fmaxf(s2, s3));
        }
        tm0 = fmaxf(tm0, __shfl_xor_sync(0xffffffff, tm0, 1));
        tm0 = fmaxf(tm0, __shfl_xor_sync(0xffffffff, tm0, 2));
        tm8 = fmaxf(tm8, __shfl_xor_sync(0xffffffff, tm8, 1));
        tm8 = fmaxf(tm8, __shfl_xor_sync(0xffffffff, tm8, 2));
        float mn0 = fmaxf(m0, tm0), mn8 = fmaxf(m8, tm8);
        float al0 = __expf(m0 - mn0), al8 = __expf(m8 - mn8);
        m0 = mn0; m8 = mn8;
        float rs0 = 0.f, rs8 = 0.f;
        #pragma unroll
        for (int ni = 0; ni < 8; ni++) {
            float p0 = __expf(sc[ni][0] - mn0);
            float p1 = __expf(sc[ni][1] - mn0);
            float p2 = __expf(sc[ni][2] - mn8);
            float p3 = __expf(sc[ni][3] - mn8);
            sc[ni][0] = p0; sc[ni][1] = p1; sc[ni][2] = p2; sc[ni][3] = p3;
            rs0 += p0 + p1; rs8 += p2 + p3;
        }
        rs0 += __shfl_xor_sync(0xffffffff, rs0, 1);
        rs0 += __shfl_xor_sync(0xffffffff, rs0, 2);
        rs8 += __shfl_xor_sync(0xffffffff, rs8, 1);
        rs8 += __shfl_xor_sync(0xffffffff, rs8, 2);
        l0 = l0*al0 + rs0;
        l8 = l8*al8 + rs8;
        #pragma unroll
        for (int ni = 0; ni < 8; ni++) {
            Oc[ni][0] *= al0; Oc[ni][1] *= al0;
            Oc[ni][2] *= al8; Oc[ni][3] *= al8;
        }

        uint32_t ph[4][4], pl[4][4];
        #pragma unroll
        for (int ks2 = 0; ks2 < 4; ks2++) {
            float x0 = sc[2*ks2][0],   x1 = sc[2*ks2][1];
            float x2 = sc[2*ks2][2],   x3 = sc[2*ks2][3];
            float y0 = sc[2*ks2+1][0], y1 = sc[2*ks2+1][1];
            float y2 = sc[2*ks2+1][2], y3 = sc[2*ks2+1][3];
            float hx0 = __bfloat162float(__float2bfloat16_rn(x0));
            float hx1 = __bfloat162float(__float2bfloat16_rn(x1));
            float hx2 = __bfloat162float(__float2bfloat16_rn(x2));
            float hx3 = __bfloat162float(__float2bfloat16_rn(x3));
            float hy0 = __bfloat162float(__float2bfloat16_rn(y0));
            float hy1 = __bfloat162float(__float2bfloat16_rn(y1));
            float hy2 = __bfloat162float(__float2bfloat16_rn(y2));
            float hy3 = __bfloat162float(__float2bfloat16_rn(y3));
            ph[ks2][0] = pack_bf2(hx0, hx1);
            ph[ks2][1] = pack_bf2(hx2, hx3);
            ph[ks2][2] = pack_bf2(hy0, hy1);
            ph[ks2][3] = pack_bf2(hy2, hy3);
            pl[ks2][0] = pack_bf2(x0 - hx0, x1 - hx1);
            pl[ks2][1] = pack_bf2(x2 - hx2, x3 - hx3);
            pl[ks2][2] = pack_bf2(y0 - hy0, y1 - hy1);
            pl[ks2][3] = pack_bf2(y2 - hy2, y3 - hy3);
        }

        #pragma unroll
        for (int ks2 = 0; ks2 < 4; ks2++)
            #pragma unroll
            for (int ni = 0; ni < 8; ni++) {
                int nr = ni*8 + r0;
                mma16816(Oc[ni], ph[ks2], Vt[nr][cq + 8*ks2], Vt[nr][cq + 8*ks2 + 4]);
            }
        #pragma unroll
        for (int ks2 = 0; ks2 < 4; ks2++)
            #pragma unroll
            for (int ni = 0; ni < 8; ni++) {
                int nr = ni*8 + r0;
                mma16816(Oc[ni], ph[ks2], Vt[nr][32 + cq + 8*ks2],
                         Vt[nr][32 + cq + 8*ks2 + 4]);
            }
        #pragma unroll
        for (int ks2 = 0; ks2 < 4; ks2++)
            #pragma unroll
            for (int ni = 0; ni < 8; ni++) {
                int nr = ni*8 + r0;
                mma16816(Oc[ni], pl[ks2], Vt[nr][cq + 8*ks2], Vt[nr][cq + 8*ks2 + 4]);
            }
        __syncthreads();
    }

    float i0 = 1.f / l0, i8 = 1.f / l8;
    #pragma unroll
    for (int ni = 0; ni < 8; ni++) {
        int cc = col0 + ni*8 + 2*cq;
        float2 w0 = {Oc[ni][0]*i0, Oc[ni][1]*i0};
        float2 w8 = {Oc[ni][2]*i8, Oc[ni][3]*i8};
        *(float2*)(o + ((size_t)(qrow + r0    )*B_ + b)*oS + cc) = w0;
        *(float2*)(o + ((size_t)(qrow + r0 + 8)*B_ + b)*oS + cc) = w8;
    }
}

// -------- memory retrieval + delta (no attn dependency) -----------------------
__global__ __launch_bounds__(256) void mem_retrieve(
    const float* __restrict__ q, const float* __restrict__ kp,
    const float* __restrict__ vp, const float* __restrict__ memory,
    const float* __restrict__ mem_norm, int l,
    float* __restrict__ content, float* __restrict__ diff, float* __restrict__ cKout,
    int qS, int kvS)
{
    int bn = blockIdx.x;
    int b = bn / NH_, n = bn % NH_;
    int chunk = blockIdx.y;
    int t = threadIdx.x;

    __shared__ float Msh[DH_][DH_+1];
    __shared__ float normsh[DH_];
    __shared__ float cqsh[4][DH_];
    __shared__ float cksh[4][DH_];

    const float* Mg = memory + ((size_t)(l*B_ + b)*NH_ + n)*DH_*DH_;
    for (int idx = t; idx < DH_*DH_; idx += 256) Msh[idx >> 6][idx & 63] = Mg[idx];
    if (t < DH_) normsh[t] = mem_norm[((size_t)(l*B_ + b)*NH_ + n)*DH_ + t];
    __syncthreads();

    int g = t >> 6, d = t & 63;
    int col = n * DH_;
    for (int it = 0; it < 32; ++it) {
        int s = chunk*128 + it*4 + g;
        size_t row = (size_t)(s*B_ + b);
        float qvl = q [row*qS  + col + d];
        float vvl = vp[row*kvS + col + d];
        float cq = qvl > 0.f ? qvl + 1.f : __expf(qvl);
        float ck = vvl > 0.f ? vvl + 1.f : __expf(vvl);
        cqsh[g][d] = cq; cksh[g][d] = ck;
        __syncthreads();
        float accA = 0.f, accB = 0.f, denQ = 0.f, denK = 0.f;
        #pragma unroll 8
        for (int kk = 0; kk < DH_; kk++) {
            float mq = Msh[kk][d];
            accA += cqsh[g][kk] * mq;
            accB += cksh[g][kk] * mq;
            denQ += cqsh[g][kk] * normsh[kk];
            denK += cksh[g][kk] * normsh[kk];
        }
        size_t oidx = row*D_ + col + d;
        content[oidx] = accA / denQ;
        diff[oidx]    = kp[row*kvS + col + d] - accB / denK;
        cKout[oidx]   = ck;
        __syncthreads();
    }
}

// -------- memory update: newM[k][v] = M[k][v] + sum_s cK[s,k]*diff[s,v] ------
__global__ __launch_bounds__(256) void mem_update(
    const float* __restrict__ cK, const float* __restrict__ diff,
    const float* __restrict__ memory, int l, float* __restrict__ outM)
{
    int bn = blockIdx.x;
    int b = bn / NH_, n = bn % NH_;
    __shared__ float aS[16][DH_];
    __shared__ float bS[16][DH_];
    int t = threadIdx.x;
    int tx = t & 15, ty = t >> 4;
    float acc[4][4] = {};
    int col = n * DH_;
    int r  = t >> 4;
    int c4 = (t & 15) * 4;
    for (int s0 = 0; s0 < S_; s0 += 16) {
        size_t row = (size_t)((s0 + r)*B_ + b);
        *(float4*)&aS[r][c4] = *(const float4*)(cK   + row*D_ + col + c4);
        *(float4*)&bS[r][c4] = *(const float4*)(diff + row*D_ + col + c4);
        __syncthreads();
        #pragma unroll
        for (int ss = 0; ss < 16; ss++) {
            float a[4], bb[4];
            #pragma unroll
            for (int u = 0; u < 4; u++) { a[u] = aS[ss][ty*4+u]; bb[u] = bS[ss][tx*4+u]; }
            #pragma unroll
            for (int i = 0; i < 4; i++)
                #pragma unroll
                for (int j = 0; j < 4; j++)
                    acc[i][j] = fmaf(a[i], bb[j], acc[i][j]);
        }
        __syncthreads();
    }
    const float* Mg = memory + ((size_t)(l*B_ + b)*NH_ + n)*DH_*DH_;
    float*       Og = outM   + ((size_t)(l*B_ + b)*NH_ + n)*DH_*DH_;
    #pragma unroll
    for (int i = 0; i < 4; i++)
        #pragma unroll
        for (int j = 0; j < 4; j++) {
            int kk = ty*4 + i, vv = tx*4 + j;
            Og[kk*DH_ + vv] = Mg[kk*DH_ + vv] + acc[i][j];
        }
}

// -------- norm update: outN = mem_norm + sum_s cK (parallel over s) ----------
__global__ __launch_bounds__(512) void norm_update(
    const float* __restrict__ cK, const float* __restrict__ mem_norm, int l,
    float* __restrict__ outN)
{
    int bn = blockIdx.x;
    int b = bn / NH_, n = bn % NH_;
    int t = threadIdx.x;
    int d = t & 63, sg = t >> 6;
    int col = n * DH_;
    float acc = 0.f;
    for (int s = sg; s < S_; s += 8)
        acc += cK[(size_t)(s*B_ + b)*D_ + col + d];
    __shared__ float red[512];
    red[t] = acc; __syncthreads();
    if (t < 256) red[t] += red[t + 256]; __syncthreads();
    if (t < 128) red[t] += red[t + 128]; __syncthreads();
    if (t < 64) {
        size_t o = ((size_t)(l*B_ + b)*NH_ + n)*DH_ + t;
        outN[o] = mem_norm[o] + red[t] + red[t + 64];
    }
}

// -------- layernorm with residual (192 threads, float4, single-pass) ----------
__global__ __launch_bounds__(192) void ln_kernel(
    const float* __restrict__ res, const float* __restrict__ y,
    const float* __restrict__ g, const float* __restrict__ bb,
    float* __restrict__ out)
{
    int row = blockIdx.x;
    int t = threadIdx.x, lane = t & 31, warp = t >> 5;   // 6 warps
    __shared__ float ws[6], wss[6];
    size_t base = (size_t)row * D_;
    float4 xr = *(const float4*)(res + base + 4*t);
    float4 yr = *(const float4*)(y   + base + 4*t);
    float4 x = {xr.x + yr.x, xr.y + yr.y, xr.z + yr.z, xr.w + yr.w};
    float s  = x.x + x.y + x.z + x.w;
    float ss = x.x*x.x + x.y*x.y + x.z*x.z + x.w*x.w;
    #pragma unroll
    for (int off = 16; off > 0; off >>= 1) {
        s  += __shfl_xor_sync(0xffffffff, s,  off);
        ss += __shfl_xor_sync(0xffffffff, ss, off);
    }
    if (lane == 0) { ws[warp] = s; wss[warp] = ss; }
    __syncthreads();
    float S = 0.f, SS = 0.f;
    #pragma unroll
    for (int w = 0; w < 6; w++) { S += ws[w]; SS += wss[w]; }
    float mu  = S * (1.f / 768.f);
    float var = SS * (1.f / 768.f) - mu*mu;
    float inv = rsqrtf(var + 1e-5f);
    float4 gv = *(const float4*)(g  + 4*t);
    float4 bv = *(const float4*)(bb + 4*t);
    float4 o4;
    o4.x = (x.x - mu) * inv * gv.x + bv.x;
    o4.y = (x.y - mu) * inv * gv.y + bv.y;
    o4.z = (x.z - mu) * inv * gv.z + bv.z;
    o4.w = (x.w - mu) * inv * gv.w + bv.w;
    *(float4*)(out + base + 4*t) = o4;
}

// ------------------------------- launcher -------------------------------------
extern "C" void kernel_launch(void* const* d_in, const int* in_sizes, int n_in,
                              void* d_out, int out_size)
{
    const int*   inp      = (const int*)  d_in[0];
    const float* word_emb = (const float*)d_in[1];
    const float* Wq       = (const float*)d_in[2];
    const float* Wkv      = (const float*)d_in[3];
    const float* Wo       = (const float*)d_in[4];
    const float* ln1g     = (const float*)d_in[5];
    const float* ln1b     = (const float*)d_in[6];
    const float* ffW1     = (const float*)d_in[7];
    const float* ffb1     = (const float*)d_in[8];
    const float* ffW2     = (const float*)d_in[9];
    const float* ffb2     = (const float*)d_in[10];
    const float* ln2g     = (const float*)d_in[11];
    const float* ln2b     = (const float*)d_in[12];
    const float* memory   = (const float*)d_in[13];
    const float* mem_norm = (const float*)d_in[14];

    float* out  = (float*)d_out;
    float* outH = out;                         // (S,B,D)
    float* outM = out + (size_t)SB_*D_;        // (L,B,NH,DH,DH)
    float* outN = outM + (size_t)L_*B_*NH_*DH_*DH_;  // (L,B,NH,DH)

    float *h, *q, *kv, *attn, *content, *cK, *diff, *ff, *out1, *wo;
    cudaGetSymbolAddress((void**)&h,       g_h);
    cudaGetSymbolAddress((void**)&q,       g_q);
    cudaGetSymbolAddress((void**)&kv,      g_kv);
    cudaGetSymbolAddress((void**)&attn,    g_attn);
    cudaGetSymbolAddress((void**)&content, g_content);
    cudaGetSymbolAddress((void**)&cK,      g_cK);
    cudaGetSymbolAddress((void**)&diff,    g_diff);
    cudaGetSymbolAddress((void**)&ff,      g_ff);
    cudaGetSymbolAddress((void**)&out1,    g_out1);
    cudaGetSymbolAddress((void**)&wo,      g_wo);

    static cudaStream_t s1 = nullptr;
    static cudaEvent_t evA = nullptr, evB = nullptr, evC = nullptr, evD = nullptr;
    if (!s1) {
        cudaStreamCreateWithFlags(&s1, cudaStreamNonBlocking);
        cudaEventCreateWithFlags(&evA, cudaEventDisableTiming);
        cudaEventCreateWithFlags(&evB, cudaEventDisableTiming);
        cudaEventCreateWithFlags(&evC, cudaEventDisableTiming);
        cudaEventCreateWithFlags(&evD, cudaEventDisableTiming);
    }

    const float gate = 1.0f / (1.0f + expf(-0.01f));

    embed_kernel<<<SB_, 256>>>(inp, word_emb, h);

    for (int l = 0; l < L_; l++) {
        // merged q|kv projection (one 576-block launch)
        gemm_qkv<<<dim3(18, SB_/128), 256>>>(h, Wq + (size_t)l*D_*D_,
                                             Wkv + (size_t)l*2*D_*D_, q, kv, D_);
        // fork side stream after qkv
        cudaEventRecord(evA, 0);
        cudaStreamWaitEvent(s1, evA, 0);
        if (l > 0) cudaStreamWaitEvent(s1, evC, 0);   // content free after Wo(l-1)

        // main stream: local causal attention (64-query tiles, heavy first)
        attn_mma<<<dim3(B_*NH_, 16), 128>>>(q, kv /*k*/, kv + D_ /*v*/, attn,
                                            D_, 2*D_, D_);

        // side stream: memory path (content/diff/cK, M & norm updates)
        mem_retrieve<<<dim3(B_*NH_, 8), 256, 0, s1>>>(q, kv /*k*/, kv + D_ /*v*/,
                                                      memory, mem_norm, l,
                                                      content, diff, cK, D_, 2*D_);
        cudaEventRecord(evB, s1);
        mem_update<<<B_*NH_, 256, 0, s1>>>(cK, diff, memory, l, outM);
        norm_update<<<B_*NH_, 512, 0, s1>>>(cK, mem_norm, l, outN);
        cudaEventRecord(evD, s1);

        // main stream: Wo projection with fused gated combine
        cudaStreamWaitEvent(0, evB, 0);               // content ready
        gemm_wo<<<dim3(D_/128, SB_/128), 256>>>(content, attn, gate,
                                                Wo + (size_t)l*D_*D_, wo, D_, D_);
        cudaEventRecord(evC, 0);

        // ln1: out1 = LN(h + wo)
        ln_kernel<<<SB_, 192>>>(h, wo, ln1g + l*D_, ln1b + l*D_, out1);
        // ff1 = relu(out1 @ W1^T + b1)
        gemm_bf16s<<<dim3(DI_/128, SB_/128), 256>>>(out1, ffW1 + (size_t)l*DI_*D_,
                                                    ffb1 + l*DI_, ff, DI_, D_, 1);
        // ff2 = ff1 @ W2^T + b2 -> q buffer (dead until next layer's qkv)
        gemm_bf16s<<<dim3(D_/128, SB_/128), 256>>>(ff, ffW2 + (size_t)l*D_*DI_,
                                                   ffb2 + l*D_, q, D_, DI_, 2);
        // ln2: h = LN(out1 + ff2)
        ln_kernel<<<SB_, 192>>>(out1, q, ln2g + l*D_, ln2b + l*D_, h);
    }

    // join side stream before finishing
    cudaStreamWaitEvent(0, evD, 0);
    cudaMemcpyAsync(outH, h, (size_t)SB_*D_*sizeof(float),
                    cudaMemcpyDeviceToDevice);
}

// round 15
// speedup vs baseline: 2.6393x; 1.1576x over previous
#include <cuda_runtime.h>
#include <cuda_bf16.h>
#include <cuda_fp16.h>
#include <math.h>
#include <stdint.h>

// Problem dims
#define S_  1024
#define B_  4
#define D_  768
#define NH_ 12
#define DH_ 64
#define L_  4
#define DI_ 3072
#define SB_ (S_*B_)

// ---------------- scratch (device globals; no allocation allowed) ------------
__device__ float g_h[SB_*D_];
__device__ float g_q[SB_*D_];
__device__ float g_kv[SB_*2*D_];
__device__ float g_attn[SB_*D_];
__device__ float g_content[SB_*D_];
__device__ float g_cK[SB_*D_];
__device__ float g_diff[SB_*D_];
__device__ float g_ff[SB_*DI_];
__device__ float g_out1[SB_*D_];
__device__ float g_wo[SB_*D_];

// pack two floats into bf16x2 (lo half = first arg)
__device__ __forceinline__ uint32_t pack_bf2(float a, float b) {
    __nv_bfloat162 h = __floats2bfloat162_rn(a, b);
    return *(uint32_t*)&h;
}
// pack two floats into fp16x2
__device__ __forceinline__ uint32_t pack_hf2(float a, float b) {
    __half2 h = __floats2half2_rn(a, b);
    return *(uint32_t*)&h;
}

// bf16 mma (attention path)
__device__ __forceinline__ void mma16816(float* d, const uint32_t* a,
                                         uint32_t b0, uint32_t b1) {
    asm volatile(
        "mma.sync.aligned.m16n8k16.row.col.f32.bf16.bf16.f32 "
        "{%0,%1,%2,%3}, {%4,%5,%6,%7}, {%8,%9}, {%0,%1,%2,%3};"
        : "+f"(d[0]), "+f"(d[1]), "+f"(d[2]), "+f"(d[3])
        : "r"(a[0]), "r"(a[1]), "r"(a[2]), "r"(a[3]), "r"(b0), "r"(b1));
}
// fp16 mma (GEMM path)
__device__ __forceinline__ void mma16816h(float* d, const uint32_t* a,
                                          uint32_t b0, uint32_t b1) {
    asm volatile(
        "mma.sync.aligned.m16n8k16.row.col.f32.f16.f16.f32 "
        "{%0,%1,%2,%3}, {%4,%5,%6,%7}, {%8,%9}, {%0,%1,%2,%3};"
        : "+f"(d[0]), "+f"(d[1]), "+f"(d[2]), "+f"(d[3])
        : "r"(a[0]), "r"(a[1]), "r"(a[2]), "r"(a[3]), "r"(b0), "r"(b1));
}

// ---------------- embedding + sinusoidal positional encoding -----------------
__global__ void embed_kernel(const int* __restrict__ inp,
                             const float* __restrict__ we,
                             float* __restrict__ h)
{
    int row = blockIdx.x;          // row = s*B + b
    int s = row / B_;
    int b = row % B_;
    int t = threadIdx.x;           // 256
    int tok = inp[s*B_ + b];
    float pos = (float)(S_ - 1 - s);
    const float lg = logf(10000.0f);
    for (int d = t; d < D_; d += 256) {
        int i = (d < 384) ? d : d - 384;
        float freq = expf(-((float)(2*i) / (float)D_) * lg);
        float ang = pos * freq;
        float pe = (d < 384) ? sinf(ang) : cosf(ang);
        h[(size_t)row*D_ + d] = we[(size_t)tok*D_ + d] * 27.712812921102035f + pe;
    }
}

// ---------------- NT GEMM body (fp16 tensor cores, 2-term: ahbh + ahbl) ------
// C[M,N] = A[M,K] @ B[N,K]^T. 128x128 tile, KT=16, 8 warps.
// A quantized to fp16 hi only (error 2^-11 rel); B split hi+lo (full precision).
// FUSE: A := gate*A + (1-gate)*A2 elementwise at load.
// epi: 0 = none, 1 = bias+relu, 2 = bias
#define KT 16
#define KP 20
template <bool FUSE>
__device__ __forceinline__ void gemm_body(
    const float* __restrict__ A, const float* __restrict__ A2, float gate,
    const float* __restrict__ Bm, const float* __restrict__ bias,
    float* __restrict__ C, int N, int K, int epi, int m0, int n0)
{
    __shared__ __align__(16) uint32_t As[2][128][KP];
    __shared__ __align__(16) uint32_t Bs[2][128][KP];
    int tid  = threadIdx.x;
    int warp = tid >> 5, lane = tid & 31;
    int wm = warp >> 2, wn = warp & 3;        // 2 x 4 warp grid
    int r0 = lane >> 2, cq = lane & 3;

    int lr = tid >> 2;          // 0..63
    int lc = (tid & 3) * 4;     // 0,4,8,12 (k offset in floats)
    int wc = lc >> 1;           // word col: 0,2,4,6
    const float* Ap  = A  + (size_t)(m0 + lr)*K + lc;
    const float* A2p = FUSE ? (A2 + (size_t)(m0 + lr)*K + lc) : nullptr;
    const float* Bp  = Bm + (size_t)(n0 + lr)*K + lc;

    float acc[16][4];
    #pragma unroll
    for (int i = 0; i < 16; i++)
        #pragma unroll
        for (int j = 0; j < 4; j++) acc[i][j] = 0.f;

    #define LOAD_A(off)                                                        \
        ({ float4 _a = *(const float4*)(Ap + (off));                           \
           if (FUSE) { float4 _b = *(const float4*)(A2p + (off));              \
               _a.x = gate*_a.x + (1.f-gate)*_b.x;                              \
               _a.y = gate*_a.y + (1.f-gate)*_b.y;                              \
               _a.z = gate*_a.z + (1.f-gate)*_b.z;                              \
               _a.w = gate*_a.w + (1.f-gate)*_b.w; }                            \
           _a; })

    // A: hi plane only (fp16)
    #define STORE_A(dst, row, vec)                                              \
    {                                                                           \
        float4 _v = (vec);                                                      \
        dst[row][wc+0] = pack_hf2(_v.x, _v.y);                                  \
        dst[row][wc+1] = pack_hf2(_v.z, _v.w);                                  \
    }
    // B: hi + lo planes (fp16 split, ~22-bit reconstruction)
    #define STORE_B(dst, row, vec)                                              \
    {                                                                           \
        float4 _v = (vec);                                                      \
        float hx = __half2float(__float2half_rn(_v.x));                         \
        float hy = __half2float(__float2half_rn(_v.y));                         \
        float hz = __half2float(__float2half_rn(_v.z));                         \
        float hw = __half2float(__float2half_rn(_v.w));                         \
        dst[row][wc+0] = pack_hf2(hx, hy);                                      \
        dst[row][wc+1] = pack_hf2(hz, hw);                                      \
        dst[row][8+wc+0] = pack_hf2(_v.x - hx, _v.y - hy);                      \
        dst[row][8+wc+1] = pack_hf2(_v.z - hz, _v.w - hw);                      \
    }

    {
        float4 a0v = LOAD_A(0);
        float4 a1v = LOAD_A((size_t)64*K);
        float4 b0v = *(const float4*)Bp;
        float4 b1v = *(const float4*)(Bp + (size_t)64*K);
        STORE_A(As[0], lr,      a0v);
        STORE_A(As[0], lr + 64, a1v);
        STORE_B(Bs[0], lr,      b0v);
        STORE_B(Bs[0], lr + 64, b1v);
    }
    __syncthreads();

    int buf = 0;
    for (int k0 = KT; k0 < K + KT; k0 += KT) {
        bool more = (k0 < K);
        float4 a0v, a1v, b0v, b1v;
        if (more) {
            a0v = LOAD_A(k0);
            a1v = LOAD_A((size_t)64*K + k0);
            b0v = *(const float4*)(Bp + k0);
            b1v = *(const float4*)(Bp + (size_t)64*K + k0);
        }
        uint32_t ah[4][4], bh[4][2], bl[4][2];
        #pragma unroll
        for (int mi = 0; mi < 4; mi++) {
            int mr = wm*64 + mi*16 + r0;
            ah[mi][0] = As[buf][mr    ][cq];
            ah[mi][1] = As[buf][mr + 8][cq];
            ah[mi][2] = As[buf][mr    ][cq + 4];
            ah[mi][3] = As[buf][mr + 8][cq + 4];
        }
        #pragma unroll
        for (int ni = 0; ni < 4; ni++) {
            int nr = wn*32 + ni*8 + r0;
            bh[ni][0] = Bs[buf][nr][cq];
            bh[ni][1] = Bs[buf][nr][cq + 4];
            bl[ni][0] = Bs[buf][nr][8 + cq];
            bl[ni][1] = Bs[buf][nr][8 + cq + 4];
        }
        // term 1: ah * bh
        #pragma unroll
        for (int mi = 0; mi < 4; mi++)
            #pragma unroll
            for (int ni = 0; ni < 4; ni++)
                mma16816h(acc[mi*4 + ni], ah[mi], bh[ni][0], bh[ni][1]);
        // term 2: ah * bl
        #pragma unroll
        for (int mi = 0; mi < 4; mi++)
            #pragma unroll
            for (int ni = 0; ni < 4; ni++)
                mma16816h(acc[mi*4 + ni], ah[mi], bl[ni][0], bl[ni][1]);
        if (more) {
            int nb = buf ^ 1;
            STORE_A(As[nb], lr,      a0v);
            STORE_A(As[nb], lr + 64, a1v);
            STORE_B(Bs[nb], lr,      b0v);
            STORE_B(Bs[nb], lr + 64, b1v);
            __syncthreads();
            buf = nb;
        }
    }
    #undef STORE_A
    #undef STORE_B
    #undef LOAD_A

    #pragma unroll
    for (int mi = 0; mi < 4; mi++) {
        int m = m0 + wm*64 + mi*16 + r0;
        #pragma unroll
        for (int ni = 0; ni < 4; ni++) {
            int n = n0 + wn*32 + ni*8 + 2*cq;
            float* d = acc[mi*4 + ni];
            float2 v0 = {d[0], d[1]};
            float2 v1 = {d[2], d[3]};
            if (epi == 1) {
                float b0v = bias[n], b1v = bias[n+1];
                v0.x = fmaxf(v0.x + b0v, 0.f); v0.y = fmaxf(v0.y + b1v, 0.f);
                v1.x = fmaxf(v1.x + b0v, 0.f); v1.y = fmaxf(v1.y + b1v, 0.f);
            } else if (epi == 2) {
                float b0v = bias[n], b1v = bias[n+1];
                v0.x += b0v; v0.y += b1v;
                v1.x += b0v; v1.y += b1v;
            }
            *(float2*)(C + (size_t)m*N + n)       = v0;
            *(float2*)(C + (size_t)(m+8)*N + n)   = v1;
        }
    }
}

__global__ __launch_bounds__(256) void gemm_bf16s(
    const float* __restrict__ A, const float* __restrict__ Bm,
    const float* __restrict__ bias, float* __restrict__ C,
    int N, int K, int epi)
{
    gemm_body<false>(A, nullptr, 0.f, Bm, bias, C, N, K, epi,
                     blockIdx.y*128, blockIdx.x*128);
}

// fused combine GEMM: C = (gate*A + (1-gate)*A2) @ B^T
__global__ __launch_bounds__(256) void gemm_wo(
    const float* __restrict__ A, const float* __restrict__ A2, float gate,
    const float* __restrict__ Bm, float* __restrict__ C, int N, int K)
{
    gemm_body<true>(A, A2, gate, Bm, nullptr, C, N, K, 0,
                    blockIdx.y*128, blockIdx.x*128);
}

// merged Q + KV projection: blocks 0..5 -> q, 6..17 -> kv
__global__ __launch_bounds__(256) void gemm_qkv(
    const float* __restrict__ A, const float* __restrict__ Wq,
    const float* __restrict__ Wkv, float* __restrict__ q,
    float* __restrict__ kv, int K)
{
    int bx = blockIdx.x, m0 = blockIdx.y*128;
    if (bx < 6)
        gemm_body<false>(A, nullptr, 0.f, Wq,  nullptr, q,  D_,   K, 0, m0, bx*128);
    else
        gemm_body<false>(A, nullptr, 0.f, Wkv, nullptr, kv, 2*D_, K, 0, m0, (bx-6)*128);
}

// ------------- tensor-core flash attention (bf16 hi/lo, fp32 acc) -------------
// 64-query tiles, 128 threads (4 warps x 16 rows). grid (48, 16),
// qt = 15 - blockIdx.y so heavy CTAs launch first. 2 CTAs/SM.
__global__ __launch_bounds__(128) void attn_mma(
    const float* __restrict__ q, const float* __restrict__ k,
    const float* __restrict__ v, float* __restrict__ o,
    int qS, int kvS, int oS)
{
    int qt = 15 - (int)blockIdx.y;         // big-work blocks launch first
    int bn = blockIdx.x;
    int b = bn / NH_, n = bn % NH_;
    int col0 = n * DH_;
    int t = threadIdx.x, lane = t & 31, warp = t >> 5;   // 4 warps
    int r0 = lane >> 2, cq = lane & 3;

    __shared__ __align__(16) uint32_t Ks[64][68];
    __shared__ __align__(16) uint32_t Vt[64][68];

    int qrow = qt*64 + warp*16;

    uint32_t qh[4][4], ql[4][4];
    #pragma unroll
    for (int ks = 0; ks < 4; ks++) {
        int cb = ks*16 + 2*cq;
        #pragma unroll
        for (int u = 0; u < 4; u++) {
            int rr = qrow + r0 + ((u & 1) ? 8 : 0);
            int cc = cb + ((u & 2) ? 8 : 0);
            float2 qv = *(const float2*)(q + ((size_t)rr*B_ + b)*qS + col0 + cc);
            float hx = __bfloat162float(__float2bfloat16_rn(qv.x));
            float hy = __bfloat162float(__float2bfloat16_rn(qv.y));
            qh[ks][u] = pack_bf2(hx, hy);
            ql[ks][u] = pack_bf2(qv.x - hx, qv.y - hy);
        }
    }

    float Oc[8][4];
    #pragma unroll
    for (int i = 0; i < 8; i++)
        #pragma unroll
        for (int j = 0; j < 4; j++) Oc[i][j] = 0.f;
    float m0 = -3.4e38f, m8 = -3.4e38f, l0 = 0.f, l8 = 0.f;

    int nkt = qt + 1;
    for (int kt = 0; kt < nkt; kt++) {
        // K tile [64 keys][64 dims] (128 threads: 8 rows per pass)
        for (int idx = t; idx < 64*16; idx += 128) {
            int key = idx >> 4, c = idx & 15;
            float4 kv4 = *(const float4*)(k + ((size_t)(kt*64+key)*B_ + b)*kvS
                                            + col0 + 4*c);
            float hx = __bfloat162float(__float2bfloat16_rn(kv4.x));
            float hy = __bfloat162float(__float2bfloat16_rn(kv4.y));
            float hz = __bfloat162float(__float2bfloat16_rn(kv4.z));
            float hw = __bfloat162float(__float2bfloat16_rn(kv4.w));
            Ks[key][2*c  ] = pack_bf2(hx, hy);
            Ks[key][2*c+1] = pack_bf2(hz, hw);
            Ks[key][32 + 2*c  ] = pack_bf2(kv4.x - hx, kv4.y - hy);
            Ks[key][32 + 2*c+1] = pack_bf2(kv4.z - hz, kv4.w - hw);
        }
        // V^T tile
        #pragma unroll
        for (int it = 0; it < 8; it++) {
            int idx = t + 128*it;           // 0..1023
            int j = idx >> 5;               // keypair 0..31
            int d = idx & 31;               // dimpair 0..31
            const float* vp0 = v + ((size_t)(kt*64 + 2*j)*B_ + b)*kvS + col0 + 2*d;
            float2 va = *(const float2*)vp0;
            float2 vb = *(const float2*)(vp0 + (size_t)B_*kvS);
            float hax = __bfloat162float(__float2bfloat16_rn(va.x));
            float hay = __bfloat162float(__float2bfloat16_rn(va.y));
            float hbx = __bfloat162float(__float2bfloat16_rn(vb.x));
            float hby = __bfloat162float(__float2bfloat16_rn(vb.y));
            Vt[2*d  ][j] = pack_bf2(hax, hbx);
            Vt[2*d+1][j] = pack_bf2(hay, hby);
            Vt[2*d  ][32 + j] = pack_bf2(va.x - hax, vb.x - hbx);
            Vt[2*d+1][32 + j] = pack_bf2(va.y - hay, vb.y - hby);
        }
        __syncthreads();

        float sc[8][4];
        #pragma unroll
        for (int i = 0; i < 8; i++)
            #pragma unroll
            for (int j = 0; j < 4; j++) sc[i][j] = 0.f;
        #pragma unroll
        for (int ks = 0; ks < 4; ks++)
            #pragma unroll
            for (int ni = 0; ni < 8; ni++) {
                int nr = ni*8 + r0;
                mma16816(sc[ni], qh[ks], Ks[nr][cq + 8*ks], Ks[nr][cq + 8*ks + 4]);
            }
        #pragma unroll
        for (int ks = 0; ks < 4; ks++)
            #pragma unroll
            for (int ni = 0; ni < 8; ni++) {
                int nr = ni*8 + r0;
                mma16816(sc[ni], qh[ks], Ks[nr][32 + cq + 8*ks],
                         Ks[nr][32 + cq + 8*ks + 4]);
            }
        #pragma unroll
        for (int ks = 0; ks < 4; ks++)
            #pragma unroll
            for (int ni = 0; ni < 8; ni++) {
                int nr = ni*8 + r0;
                mma16816(sc[ni], ql[ks], Ks[nr][cq + 8*ks], Ks[nr][cq + 8*ks + 4]);
            }

        const float scale = 0.125f;
        bool diag = (kt == qt);
        int rg0 = qrow + r0, rg8 = rg0 + 8;
        float tm0 = -3.4e38f, tm8 = -3.4e38f;
        #pragma unroll
        for (int ni = 0; ni < 8; ni++) {
            float s0 = sc[ni][0]*scale, s1 = sc[ni][1]*scale;
            float s2 = sc[ni][2]*scale, s3 = sc[ni][3]*scale;
            if (diag) {
                int colg = kt*64 + ni*8 + 2*cq;
                if (colg     > rg0) s0 = -3.4e38f;
                if (colg + 1 > rg0) s1 = -3.4e38f;
                if (colg     > rg8) s2 = -3.4e38f;
                if (colg + 1 > rg8) s3 = -3.4e38f;
            }
            sc[ni][0] = s0; sc[ni][1] = s1; sc[ni][2] = s2; sc[ni][3] = s3;
            tm0 = fmaxf(tm0, fmaxf(s0, s1));
            tm8 = fmaxf(tm8, fmaxf(s2, s3));
        }
        tm0 = fmaxf(tm0, __shfl_xor_sync(0xffffffff, tm0, 1));
        tm0 = fmaxf(tm0, __shfl_xor_sync(0xffffffff, tm0, 2));
        tm8 = fmaxf(tm8, __shfl_xor_sync(0xffffffff, tm8, 1));
        tm8 = fmaxf(tm8, __shfl_xor_sync(0xffffffff, tm8, 2));
        float mn0 = fmaxf(m0, tm0), mn8 = fmaxf(m8, tm8);
        float al0 = __expf(m0 - mn0), al8 = __expf(m8 - mn8);
        m0 = mn0; m8 = mn8;
        float rs0 = 0.f, rs8 = 0.f;
        #pragma unroll
        for (int ni = 0; ni < 8; ni++) {
            float p0 = __expf(sc[ni][0] - mn0);
            float p1 = __expf(sc[ni][1] - mn0);
            float p2 = __expf(sc[ni][2] - mn8);
            float p3 = __expf(sc[ni][3] - mn8);
            sc[ni][0] = p0; sc[ni][1] = p1; sc[ni][2] = p2; sc[ni][3] = p3;
            rs0 += p0 + p1; rs8 += p2 + p3;
        }
        rs0 += __shfl_xor_sync(0xffffffff, rs0, 1);
        rs0 += __shfl_xor_sync(0xffffffff, rs0, 2);
        rs8 += __shfl_xor_sync(0xffffffff, rs8, 1);
        rs8 += __shfl_xor_sync(0xffffffff, rs8, 2);
        l0 = l0*al0 + rs0;
        l8 = l8*al8 + rs8;
        #pragma unroll
        for (int ni = 0; ni < 8; ni++) {
            Oc[ni][0] *= al0; Oc[ni][1] *= al0;
            Oc[ni][2] *= al8; Oc[ni][3] *= al8;
        }

        uint32_t ph[4][4], pl[4][4];
        #pragma unroll
        for (int ks2 = 0; ks2 < 4; ks2++) {
            float x0 = sc[2*ks2][0],   x1 = sc[2*ks2][1];
            float x2 = sc[2*ks2][2],   x3 = sc[2*ks2][3];
            float y0 = sc[2*ks2+1][0], y1 = sc[2*ks2+1][1];
            float y2 = sc[2*ks2+1][2], y3 = sc[2*ks2+1][3];
            float hx0 = __bfloat162float(__float2bfloat16_rn(x0));
            float hx1 = __bfloat162float(__float2bfloat16_rn(x1));
            float hx2 = __bfloat162float(__float2bfloat16_rn(x2));
            float hx3 = __bfloat162float(__float2bfloat16_rn(x3));
            float hy0 = __bfloat162float(__float2bfloat16_rn(y0));
            float hy1 = __bfloat162float(__float2bfloat16_rn(y1));
            float hy2 = __bfloat162float(__float2bfloat16_rn(y2));
            float hy3 = __bfloat162float(__float2bfloat16_rn(y3));
            ph[ks2][0] = pack_bf2(hx0, hx1);
            ph[ks2][1] = pack_bf2(hx2, hx3);
            ph[ks2][2] = pack_bf2(hy0, hy1);
            ph[ks2][3] = pack_bf2(hy2, hy3);
            pl[ks2][0] = pack_bf2(x0 - hx0, x1 - hx1);
            pl[ks2][1] = pack_bf2(x2 - hx2, x3 - hx3);
            pl[ks2][2] = pack_bf2(y0 - hy0, y1 - hy1);
            pl[ks2][3] = pack_bf2(y2 - hy2, y3 - hy3);
        }

        #pragma unroll
        for (int ks2 = 0; ks2 < 4; ks2++)
            #pragma unroll
            for (int ni = 0; ni < 8; ni++) {
                int nr = ni*8 + r0;
                mma16816(Oc[ni], ph[ks2], Vt[nr][cq + 8*ks2], Vt[nr][cq + 8*ks2 + 4]);
            }
        #pragma unroll
        for (int ks2 = 0; ks2 < 4; ks2++)
            #pragma unroll
            for (int ni = 0; ni < 8; ni++) {
                int nr = ni*8 + r0;
                mma16816(Oc[ni], ph[ks2], Vt[nr][32 + cq + 8*ks2],
                         Vt[nr][32 + cq + 8*ks2 + 4]);
            }
        #pragma unroll
        for (int ks2 = 0; ks2 < 4; ks2++)
            #pragma unroll
            for (int ni = 0; ni < 8; ni++) {
                int nr = ni*8 + r0;
                mma16816(Oc[ni], pl[ks2], Vt[nr][cq + 8*ks2], Vt[nr][cq + 8*ks2 + 4]);
            }
        __syncthreads();
    }

    float i0 = 1.f / l0, i8 = 1.f / l8;
    #pragma unroll
    for (int ni = 0; ni < 8; ni++) {
        int cc = col0 + ni*8 + 2*cq;
        float2 w0 = {Oc[ni][0]*i0, Oc[ni][1]*i0};
        float2 w8 = {Oc[ni][2]*i8, Oc[ni][3]*i8};
        *(float2*)(o + ((size_t)(qrow + r0    )*B_ + b)*oS + cc) = w0;
        *(float2*)(o + ((size_t)(qrow + r0 + 8)*B_ + b)*oS + cc) = w8;
    }
}

// -------- memory retrieval + delta (no attn dependency) -----------------------
__global__ __launch_bounds__(256) void mem_retrieve(
    const float* __restrict__ q, const float* __restrict__ kp,
    const float* __restrict__ vp, const float* __restrict__ memory,
    const float* __restrict__ mem_norm, int l,
    float* __restrict__ content, float* __restrict__ diff, float* __restrict__ cKout,
    int qS, int kvS)
{
    int bn = blockIdx.x;
    int b = bn / NH_, n = bn % NH_;
    int chunk = blockIdx.y;
    int t = threadIdx.x;

    __shared__ float Msh[DH_][DH_+1];
    __shared__ float normsh[DH_];
    __shared__ float cqsh[4][DH_];
    __shared__ float cksh[4][DH_];

    const float* Mg = memory + ((size_t)(l*B_ + b)*NH_ + n)*DH_*DH_;
    for (int idx = t; idx < DH_*DH_; idx += 256) Msh[idx >> 6][idx & 63] = Mg[idx];
    if (t < DH_) normsh[t] = mem_norm[((size_t)(l*B_ + b)*NH_ + n)*DH_ + t];
    __syncthreads();

    int g = t >> 6, d = t & 63;
    int col = n * DH_;
    for (int it = 0; it < 32; ++it) {
        int s = chunk*128 + it*4 + g;
        size_t row = (size_t)(s*B_ + b);
        float qvl = q [row*qS  + col + d];
        float vvl = vp[row*kvS + col + d];
        float cq = qvl > 0.f ? qvl + 1.f : __expf(qvl);
        float ck = vvl > 0.f ? vvl + 1.f : __expf(vvl);
        cqsh[g][d] = cq; cksh[g][d] = ck;
        __syncthreads();
        float accA = 0.f, accB = 0.f, denQ = 0.f, denK = 0.f;
        #pragma unroll 8
        for (int kk = 0; kk < DH_; kk++) {
            float mq = Msh[kk][d];
            accA += cqsh[g][kk] * mq;
            accB += cksh[g][kk] * mq;
            denQ += cqsh[g][kk] * normsh[kk];
            denK += cksh[g][kk] * normsh[kk];
        }
        size_t oidx = row*D_ + col + d;
        content[oidx] = accA / denQ;
        diff[oidx]    = kp[row*kvS + col + d] - accB / denK;
        cKout[oidx]   = ck;
        __syncthreads();
    }
}

// -------- memory update: newM[k][v] = M[k][v] + sum_s cK[s,k]*diff[s,v] ------
__global__ __launch_bounds__(256) void mem_update(
    const float* __restrict__ cK, const float* __restrict__ diff,
    const float* __restrict__ memory, int l, float* __restrict__ outM)
{
    int bn = blockIdx.x;
    int b = bn / NH_, n = bn % NH_;
    __shared__ float aS[16][DH_];
    __shared__ float bS[16][DH_];
    int t = threadIdx.x;
    int tx = t & 15, ty = t >> 4;
    float acc[4][4] = {};
    int col = n * DH_;
    int r  = t >> 4;
    int c4 = (t & 15) * 4;
    for (int s0 = 0; s0 < S_; s0 += 16) {
        size_t row = (size_t)((s0 + r)*B_ + b);
        *(float4*)&aS[r][c4] = *(const float4*)(cK   + row*D_ + col + c4);
        *(float4*)&bS[r][c4] = *(const float4*)(diff + row*D_ + col + c4);
        __syncthreads();
        #pragma unroll
        for (int ss = 0; ss < 16; ss++) {
            float a[4], bb[4];
            #pragma unroll
            for (int u = 0; u < 4; u++) { a[u] = aS[ss][ty*4+u]; bb[u] = bS[ss][tx*4+u]; }
            #pragma unroll
            for (int i = 0; i < 4; i++)
                #pragma unroll
                for (int j = 0; j < 4; j++)
                    acc[i][j] = fmaf(a[i], bb[j], acc[i][j]);
        }
        __syncthreads();
    }
    const float* Mg = memory + ((size_t)(l*B_ + b)*NH_ + n)*DH_*DH_;
    float*       Og = outM   + ((size_t)(l*B_ + b)*NH_ + n)*DH_*DH_;
    #pragma unroll
    for (int i = 0; i < 4; i++)
        #pragma unroll
        for (int j = 0; j < 4; j++) {
            int kk = ty*4 + i, vv = tx*4 + j;
            Og[kk*DH_ + vv] = Mg[kk*DH_ + vv] + acc[i][j];
        }
}

// -------- norm update: outN = mem_norm + sum_s cK (parallel over s) ----------
__global__ __launch_bounds__(512) void norm_update(
    const float* __restrict__ cK, const float* __restrict__ mem_norm, int l,
    float* __restrict__ outN)
{
    int bn = blockIdx.x;
    int b = bn / NH_, n = bn % NH_;
    int t = threadIdx.x;
    int d = t & 63, sg = t >> 6;
    int col = n * DH_;
    float acc = 0.f;
    for (int s = sg; s < S_; s += 8)
        acc += cK[(size_t)(s*B_ + b)*D_ + col + d];
    __shared__ float red[512];
    red[t] = acc; __syncthreads();
    if (t < 256) red[t] += red[t + 256]; __syncthreads();
    if (t < 128) red[t] += red[t + 128]; __syncthreads();
    if (t < 64) {
        size_t o = ((size_t)(l*B_ + b)*NH_ + n)*DH_ + t;
        outN[o] = mem_norm[o] + red[t] + red[t + 64];
    }
}

// -------- layernorm with residual (192 threads, float4, single-pass) ----------
__global__ __launch_bounds__(192) void ln_kernel(
    const float* __restrict__ res, const float* __restrict__ y,
    const float* __restrict__ g, const float* __restrict__ bb,
    float* __restrict__ out)
{
    int row = blockIdx.x;
    int t = threadIdx.x, lane = t & 31, warp = t >> 5;   // 6 warps
    __shared__ float ws[6], wss[6];
    size_t base = (size_t)row * D_;
    float4 xr = *(const float4*)(res + base + 4*t);
    float4 yr = *(const float4*)(y   + base + 4*t);
    float4 x = {xr.x + yr.x, xr.y + yr.y, xr.z + yr.z, xr.w + yr.w};
    float s  = x.x + x.y + x.z + x.w;
    float ss = x.x*x.x + x.y*x.y + x.z*x.z + x.w*x.w;
    #pragma unroll
    for (int off = 16; off > 0; off >>= 1) {
        s  += __shfl_xor_sync(0xffffffff, s,  off);
        ss += __shfl_xor_sync(0xffffffff, ss, off);
    }
    if (lane == 0) { ws[warp] = s; wss[warp] = ss; }
    __syncthreads();
    float S = 0.f, SS = 0.f;
    #pragma unroll
    for (int w = 0; w < 6; w++) { S += ws[w]; SS += wss[w]; }
    float mu  = S * (1.f / 768.f);
    float var = SS * (1.f / 768.f) - mu*mu;
    float inv = rsqrtf(var + 1e-5f);
    float4 gv = *(const float4*)(g  + 4*t);
    float4 bv = *(const float4*)(bb + 4*t);
    float4 o4;
    o4.x = (x.x - mu) * inv * gv.x + bv.x;
    o4.y = (x.y - mu) * inv * gv.y + bv.y;
    o4.z = (x.z - mu) * inv * gv.z + bv.z;
    o4.w = (x.w - mu) * inv * gv.w + bv.w;
    *(float4*)(out + base + 4*t) = o4;
}

// ------------------------------- launcher -------------------------------------
extern "C" void kernel_launch(void* const* d_in, const int* in_sizes, int n_in,
                              void* d_out, int out_size)
{
    const int*   inp      = (const int*)  d_in[0];
    const float* word_emb = (const float*)d_in[1];
    const float* Wq       = (const float*)d_in[2];
    const float* Wkv      = (const float*)d_in[3];
    const float* Wo       = (const float*)d_in[4];
    const float* ln1g     = (const float*)d_in[5];
    const float* ln1b     = (const float*)d_in[6];
    const float* ffW1     = (const float*)d_in[7];
    const float* ffb1     = (const float*)d_in[8];
    const float* ffW2     = (const float*)d_in[9];
    const float* ffb2     = (const float*)d_in[10];
    const float* ln2g     = (const float*)d_in[11];
    const float* ln2b     = (const float*)d_in[12];
    const float* memory   = (const float*)d_in[13];
    const float* mem_norm = (const float*)d_in[14];

    float* out  = (float*)d_out;
    float* outH = out;                         // (S,B,D)
    float* outM = out + (size_t)SB_*D_;        // (L,B,NH,DH,DH)
    float* outN = outM + (size_t)L_*B_*NH_*DH_*DH_;  // (L,B,NH,DH)

    float *h, *q, *kv, *attn, *content, *cK, *diff, *ff, *out1, *wo;
    cudaGetSymbolAddress((void**)&h,       g_h);
    cudaGetSymbolAddress((void**)&q,       g_q);
    cudaGetSymbolAddress((void**)&kv,      g_kv);
    cudaGetSymbolAddress((void**)&attn,    g_attn);
    cudaGetSymbolAddress((void**)&content, g_content);
    cudaGetSymbolAddress((void**)&cK,      g_cK);
    cudaGetSymbolAddress((void**)&diff,    g_diff);
    cudaGetSymbolAddress((void**)&ff,      g_ff);
    cudaGetSymbolAddress((void**)&out1,    g_out1);
    cudaGetSymbolAddress((void**)&wo,      g_wo);

    static cudaStream_t s1 = nullptr;
    static cudaEvent_t evA = nullptr, evB = nullptr, evC = nullptr, evD = nullptr;
    if (!s1) {
        cudaStreamCreateWithFlags(&s1, cudaStreamNonBlocking);
        cudaEventCreateWithFlags(&evA, cudaEventDisableTiming);
        cudaEventCreateWithFlags(&evB, cudaEventDisableTiming);
        cudaEventCreateWithFlags(&evC, cudaEventDisableTiming);
        cudaEventCreateWithFlags(&evD, cudaEventDisableTiming);
    }

    const float gate = 1.0f / (1.0f + expf(-0.01f));

    embed_kernel<<<SB_, 256>>>(inp, word_emb, h);

    for (int l = 0; l < L_; l++) {
        // merged q|kv projection (one 576-block launch)
        gemm_qkv<<<dim3(18, SB_/128), 256>>>(h, Wq + (size_t)l*D_*D_,
                                             Wkv + (size_t)l*2*D_*D_, q, kv, D_);
        // fork side stream after qkv
        cudaEventRecord(evA, 0);
        cudaStreamWaitEvent(s1, evA, 0);
        if (l > 0) cudaStreamWaitEvent(s1, evC, 0);   // content free after Wo(l-1)

        // main stream: local causal attention (64-query tiles, heavy first)
        attn_mma<<<dim3(B_*NH_, 16), 128>>>(q, kv /*k*/, kv + D_ /*v*/, attn,
                                            D_, 2*D_, D_);

        // side stream: memory path (content/diff/cK, M & norm updates)
        mem_retrieve<<<dim3(B_*NH_, 8), 256, 0, s1>>>(q, kv /*k*/, kv + D_ /*v*/,
                                                      memory, mem_norm, l,
                                                      content, diff, cK, D_, 2*D_);
        cudaEventRecord(evB, s1);
        mem_update<<<B_*NH_, 256, 0, s1>>>(cK, diff, memory, l, outM);
        norm_update<<<B_*NH_, 512, 0, s1>>>(cK, mem_norm, l, outN);
        cudaEventRecord(evD, s1);

        // main stream: Wo projection with fused gated combine
        cudaStreamWaitEvent(0, evB, 0);               // content ready
        gemm_wo<<<dim3(D_/128, SB_/128), 256>>>(content, attn, gate,
                                                Wo + (size_t)l*D_*D_, wo, D_, D_);
        cudaEventRecord(evC, 0);

        // ln1: out1 = LN(h + wo)
        ln_kernel<<<SB_, 192>>>(h, wo, ln1g + l*D_, ln1b + l*D_, out1);
        // ff1 = relu(out1 @ W1^T + b1)
        gemm_bf16s<<<dim3(DI_/128, SB_/128), 256>>>(out1, ffW1 + (size_t)l*DI_*D_,
                                                    ffb1 + l*DI_, ff, DI_, D_, 1);
        // ff2 = ff1 @ W2^T + b2 -> q buffer (dead until next layer's qkv)
        gemm_bf16s<<<dim3(D_/128, SB_/128), 256>>>(ff, ffW2 + (size_t)l*D_*DI_,
                                                   ffb2 + l*D_, q, D_, DI_, 2);
        // ln2: h = LN(out1 + ff2)
        ln_kernel<<<SB_, 192>>>(out1, q, ln2g + l*D_, ln2b + l*D_, h);
    }

    // join side stream before finishing
    cudaStreamWaitEvent(0, evD, 0);
    cudaMemcpyAsync(outH, h, (size_t)SB_*D_*sizeof(float),
                    cudaMemcpyDeviceToDevice);
}

// round 16
// speedup vs baseline: 3.5308x; 1.3378x over previous
#include <cuda_runtime.h>
#include <cuda_bf16.h>
#include <cuda_fp16.h>
#include <math.h>
#include <stdint.h>

// Problem dims
#define S_  1024
#define B_  4
#define D_  768
#define NH_ 12
#define DH_ 64
#define L_  4
#define DI_ 3072
#define SB_ (S_*B_)

// ---------------- scratch (device globals; no allocation allowed) ------------
__device__ float g_h[SB_*D_];
__device__ float g_q[SB_*D_];
__device__ float g_kv[SB_*2*D_];
__device__ float g_attn[SB_*D_];
__device__ float g_content[SB_*D_];
__device__ float g_cK[SB_*D_];
__device__ float g_diff[SB_*D_];
__device__ float g_ff[SB_*DI_];
__device__ float g_out1[SB_*D_];
__device__ float g_wo[SB_*D_];

// pack two floats into fp16x2
__device__ __forceinline__ uint32_t pack_hf2(float a, float b) {
    __half2 h = __floats2half2_rn(a, b);
    return *(uint32_t*)&h;
}

// fp16 mma
__device__ __forceinline__ void mma16816h(float* d, const uint32_t* a,
                                          uint32_t b0, uint32_t b1) {
    asm volatile(
        "mma.sync.aligned.m16n8k16.row.col.f32.f16.f16.f32 "
        "{%0,%1,%2,%3}, {%4,%5,%6,%7}, {%8,%9}, {%0,%1,%2,%3};"
        : "+f"(d[0]), "+f"(d[1]), "+f"(d[2]), "+f"(d[3])
        : "r"(a[0]), "r"(a[1]), "r"(a[2]), "r"(a[3]), "r"(b0), "r"(b1));
}

// ---------------- embedding + sinusoidal positional encoding -----------------
__global__ void embed_kernel(const int* __restrict__ inp,
                             const float* __restrict__ we,
                             float* __restrict__ h)
{
    int row = blockIdx.x;          // row = s*B + b
    int s = row / B_;
    int b = row % B_;
    int t = threadIdx.x;           // 256
    int tok = inp[s*B_ + b];
    float pos = (float)(S_ - 1 - s);
    const float lg = logf(10000.0f);
    for (int d = t; d < D_; d += 256) {
        int i = (d < 384) ? d : d - 384;
        float freq = expf(-((float)(2*i) / (float)D_) * lg);
        float ang = pos * freq;
        float pe = (d < 384) ? sinf(ang) : cosf(ang);
        h[(size_t)row*D_ + d] = we[(size_t)tok*D_ + d] * 27.712812921102035f + pe;
    }
}

// ---------------- NT GEMM body (pure fp16, 1 term) ---------------------------
// C[M,N] = A[M,K] @ B[N,K]^T. 128x128 tile, KT=16, 8 warps, 16 mmas/ktile.
// FUSE: A := gate*A + (1-gate)*A2 elementwise at load.
// epi: 0 = none, 1 = bias+relu, 2 = bias
#define KT 16
#define KP 20
template <bool FUSE>
__device__ __forceinline__ void gemm_body(
    const float* __restrict__ A, const float* __restrict__ A2, float gate,
    const float* __restrict__ Bm, const float* __restrict__ bias,
    float* __restrict__ C, int N, int K, int epi, int m0, int n0)
{
    __shared__ __align__(16) uint32_t As[2][128][KP];
    __shared__ __align__(16) uint32_t Bs[2][128][KP];
    int tid  = threadIdx.x;
    int warp = tid >> 5, lane = tid & 31;
    int wm = warp >> 2, wn = warp & 3;        // 2 x 4 warp grid
    int r0 = lane >> 2, cq = lane & 3;

    int lr = tid >> 2;          // 0..63
    int lc = (tid & 3) * 4;     // 0,4,8,12 (k offset in floats)
    int wc = lc >> 1;           // word col: 0,2,4,6
    const float* Ap  = A  + (size_t)(m0 + lr)*K + lc;
    const float* A2p = FUSE ? (A2 + (size_t)(m0 + lr)*K + lc) : nullptr;
    const float* Bp  = Bm + (size_t)(n0 + lr)*K + lc;

    float acc[16][4];
    #pragma unroll
    for (int i = 0; i < 16; i++)
        #pragma unroll
        for (int j = 0; j < 4; j++) acc[i][j] = 0.f;

    #define LOAD_A(off)                                                        \
        ({ float4 _a = *(const float4*)(Ap + (off));                           \
           if (FUSE) { float4 _b = *(const float4*)(A2p + (off));              \
               _a.x = gate*_a.x + (1.f-gate)*_b.x;                              \
               _a.y = gate*_a.y + (1.f-gate)*_b.y;                              \
               _a.z = gate*_a.z + (1.f-gate)*_b.z;                              \
               _a.w = gate*_a.w + (1.f-gate)*_b.w; }                            \
           _a; })

    // fp16 hi plane only (both operands)
    #define STORE_H(dst, row, vec)                                              \
    {                                                                           \
        float4 _v = (vec);                                                      \
        dst[row][wc+0] = pack_hf2(_v.x, _v.y);                                  \
        dst[row][wc+1] = pack_hf2(_v.z, _v.w);                                  \
    }

    {
        float4 a0v = LOAD_A(0);
        float4 a1v = LOAD_A((size_t)64*K);
        float4 b0v = *(const float4*)Bp;
        float4 b1v = *(const float4*)(Bp + (size_t)64*K);
        STORE_H(As[0], lr,      a0v);
        STORE_H(As[0], lr + 64, a1v);
        STORE_H(Bs[0], lr,      b0v);
        STORE_H(Bs[0], lr + 64, b1v);
    }
    __syncthreads();

    int buf = 0;
    for (int k0 = KT; k0 < K + KT; k0 += KT) {
        bool more = (k0 < K);
        float4 a0v, a1v, b0v, b1v;
        if (more) {
            a0v = LOAD_A(k0);
            a1v = LOAD_A((size_t)64*K + k0);
            b0v = *(const float4*)(Bp + k0);
            b1v = *(const float4*)(Bp + (size_t)64*K + k0);
        }
        uint32_t ah[4][4], bh[4][2];
        #pragma unroll
        for (int mi = 0; mi < 4; mi++) {
            int mr = wm*64 + mi*16 + r0;
            ah[mi][0] = As[buf][mr    ][cq];
            ah[mi][1] = As[buf][mr + 8][cq];
            ah[mi][2] = As[buf][mr    ][cq + 4];
            ah[mi][3] = As[buf][mr + 8][cq + 4];
        }
        #pragma unroll
        for (int ni = 0; ni < 4; ni++) {
            int nr = wn*32 + ni*8 + r0;
            bh[ni][0] = Bs[buf][nr][cq];
            bh[ni][1] = Bs[buf][nr][cq + 4];
        }
        #pragma unroll
        for (int mi = 0; mi < 4; mi++)
            #pragma unroll
            for (int ni = 0; ni < 4; ni++)
                mma16816h(acc[mi*4 + ni], ah[mi], bh[ni][0], bh[ni][1]);
        if (more) {
            int nb = buf ^ 1;
            STORE_H(As[nb], lr,      a0v);
            STORE_H(As[nb], lr + 64, a1v);
            STORE_H(Bs[nb], lr,      b0v);
            STORE_H(Bs[nb], lr + 64, b1v);
            __syncthreads();
            buf = nb;
        }
    }
    #undef STORE_H
    #undef LOAD_A

    #pragma unroll
    for (int mi = 0; mi < 4; mi++) {
        int m = m0 + wm*64 + mi*16 + r0;
        #pragma unroll
        for (int ni = 0; ni < 4; ni++) {
            int n = n0 + wn*32 + ni*8 + 2*cq;
            float* d = acc[mi*4 + ni];
            float2 v0 = {d[0], d[1]};
            float2 v1 = {d[2], d[3]};
            if (epi == 1) {
                float b0v = bias[n], b1v = bias[n+1];
                v0.x = fmaxf(v0.x + b0v, 0.f); v0.y = fmaxf(v0.y + b1v, 0.f);
                v1.x = fmaxf(v1.x + b0v, 0.f); v1.y = fmaxf(v1.y + b1v, 0.f);
            } else if (epi == 2) {
                float b0v = bias[n], b1v = bias[n+1];
                v0.x += b0v; v0.y += b1v;
                v1.x += b0v; v1.y += b1v;
            }
            *(float2*)(C + (size_t)m*N + n)       = v0;
            *(float2*)(C + (size_t)(m+8)*N + n)   = v1;
        }
    }
}

__global__ __launch_bounds__(256) void gemm_bf16s(
    const float* __restrict__ A, const float* __restrict__ Bm,
    const float* __restrict__ bias, float* __restrict__ C,
    int N, int K, int epi)
{
    gemm_body<false>(A, nullptr, 0.f, Bm, bias, C, N, K, epi,
                     blockIdx.y*128, blockIdx.x*128);
}

// fused combine GEMM: C = (gate*A + (1-gate)*A2) @ B^T
__global__ __launch_bounds__(256) void gemm_wo(
    const float* __restrict__ A, const float* __restrict__ A2, float gate,
    const float* __restrict__ Bm, float* __restrict__ C, int N, int K)
{
    gemm_body<true>(A, A2, gate, Bm, nullptr, C, N, K, 0,
                    blockIdx.y*128, blockIdx.x*128);
}

// merged Q + KV projection: blocks 0..5 -> q, 6..17 -> kv
__global__ __launch_bounds__(256) void gemm_qkv(
    const float* __restrict__ A, const float* __restrict__ Wq,
    const float* __restrict__ Wkv, float* __restrict__ q,
    float* __restrict__ kv, int K)
{
    int bx = blockIdx.x, m0 = blockIdx.y*128;
    if (bx < 6)
        gemm_body<false>(A, nullptr, 0.f, Wq,  nullptr, q,  D_,   K, 0, m0, bx*128);
    else
        gemm_body<false>(A, nullptr, 0.f, Wkv, nullptr, kv, 2*D_, K, 0, m0, (bx-6)*128);
}

// ------------- tensor-core flash attention (fp16 2-term, fp32 acc) ------------
// 64-query tiles, 128 threads (4 warps x 16 rows). grid (48, 16),
// qt = 15 - blockIdx.y so heavy CTAs launch first.
// QK: qh(fp16) x (Kh + Kl).  PV: ph(fp16) x (Vh + Vl).
__global__ __launch_bounds__(128) void attn_mma(
    const float* __restrict__ q, const float* __restrict__ k,
    const float* __restrict__ v, float* __restrict__ o,
    int qS, int kvS, int oS)
{
    int qt = 15 - (int)blockIdx.y;         // big-work blocks launch first
    int bn = blockIdx.x;
    int b = bn / NH_, n = bn % NH_;
    int col0 = n * DH_;
    int t = threadIdx.x, lane = t & 31, warp = t >> 5;   // 4 warps
    int r0 = lane >> 2, cq = lane & 3;

    __shared__ __align__(16) uint32_t Ks[64][68];
    __shared__ __align__(16) uint32_t Vt[64][68];

    int qrow = qt*64 + warp*16;

    uint32_t qh[4][4];
    #pragma unroll
    for (int ks = 0; ks < 4; ks++) {
        int cb = ks*16 + 2*cq;
        #pragma unroll
        for (int u = 0; u < 4; u++) {
            int rr = qrow + r0 + ((u & 1) ? 8 : 0);
            int cc = cb + ((u & 2) ? 8 : 0);
            float2 qv = *(const float2*)(q + ((size_t)rr*B_ + b)*qS + col0 + cc);
            qh[ks][u] = pack_hf2(qv.x, qv.y);
        }
    }

    float Oc[8][4];
    #pragma unroll
    for (int i = 0; i < 8; i++)
        #pragma unroll
        for (int j = 0; j < 4; j++) Oc[i][j] = 0.f;
    float m0 = -3.4e38f, m8 = -3.4e38f, l0 = 0.f, l8 = 0.f;

    int nkt = qt + 1;
    for (int kt = 0; kt < nkt; kt++) {
        // K tile [64 keys][64 dims], fp16 hi + lo
        for (int idx = t; idx < 64*16; idx += 128) {
            int key = idx >> 4, c = idx & 15;
            float4 kv4 = *(const float4*)(k + ((size_t)(kt*64+key)*B_ + b)*kvS
                                            + col0 + 4*c);
            float hx = __half2float(__float2half_rn(kv4.x));
            float hy = __half2float(__float2half_rn(kv4.y));
            float hz = __half2float(__float2half_rn(kv4.z));
            float hw = __half2float(__float2half_rn(kv4.w));
            Ks[key][2*c  ] = pack_hf2(hx, hy);
            Ks[key][2*c+1] = pack_hf2(hz, hw);
            Ks[key][32 + 2*c  ] = pack_hf2(kv4.x - hx, kv4.y - hy);
            Ks[key][32 + 2*c+1] = pack_hf2(kv4.z - hz, kv4.w - hw);
        }
        // V^T tile, fp16 hi + lo
        #pragma unroll
        for (int it = 0; it < 8; it++) {
            int idx = t + 128*it;           // 0..1023
            int j = idx >> 5;               // keypair 0..31
            int d = idx & 31;               // dimpair 0..31
            const float* vp0 = v + ((size_t)(kt*64 + 2*j)*B_ + b)*kvS + col0 + 2*d;
            float2 va = *(const float2*)vp0;
            float2 vb = *(const float2*)(vp0 + (size_t)B_*kvS);
            float hax = __half2float(__float2half_rn(va.x));
            float hay = __half2float(__float2half_rn(va.y));
            float hbx = __half2float(__float2half_rn(vb.x));
            float hby = __half2float(__float2half_rn(vb.y));
            Vt[2*d  ][j] = pack_hf2(hax, hbx);
            Vt[2*d+1][j] = pack_hf2(hay, hby);
            Vt[2*d  ][32 + j] = pack_hf2(va.x - hax, vb.x - hbx);
            Vt[2*d+1][32 + j] = pack_hf2(va.y - hay, vb.y - hby);
        }
        __syncthreads();

        float sc[8][4];
        #pragma unroll
        for (int i = 0; i < 8; i++)
            #pragma unroll
            for (int j = 0; j < 4; j++) sc[i][j] = 0.f;
        // QK: qh*Kh then qh*Kl
        #pragma unroll
        for (int ks = 0; ks < 4; ks++)
            #pragma unroll
            for (int ni = 0; ni < 8; ni++) {
                int nr = ni*8 + r0;
                mma16816h(sc[ni], qh[ks], Ks[nr][cq + 8*ks], Ks[nr][cq + 8*ks + 4]);
            }
        #pragma unroll
        for (int ks = 0; ks < 4; ks++)
            #pragma unroll
            for (int ni = 0; ni < 8; ni++) {
                int nr = ni*8 + r0;
                mma16816h(sc[ni], qh[ks], Ks[nr][32 + cq + 8*ks],
                          Ks[nr][32 + cq + 8*ks + 4]);
            }

        const float scale = 0.125f;
        bool diag = (kt == qt);
        int rg0 = qrow + r0, rg8 = rg0 + 8;
        float tm0 = -3.4e38f, tm8 = -3.4e38f;
        #pragma unroll
        for (int ni = 0; ni < 8; ni++) {
            float s0 = sc[ni][0]*scale, s1 = sc[ni][1]*scale;
            float s2 = sc[ni][2]*scale, s3 = sc[ni][3]*scale;
            if (diag) {
                int colg = kt*64 + ni*8 + 2*cq;
                if (colg     > rg0) s0 = -3.4e38f;
                if (colg + 1 > rg0) s1 = -3.4e38f;
                if (colg     > rg8) s2 = -3.4e38f;
                if (colg + 1 > rg8) s3 = -3.4e38f;
            }
            sc[ni][0] = s0; sc[ni][1] = s1; sc[ni][2] = s2; sc[ni][3] = s3;
            tm0 = fmaxf(tm0, fmaxf(s0, s1));
            tm8 = fmaxf(tm8, fmaxf(s2, s3));
        }
        tm0 = fmaxf(tm0, __shfl_xor_sync(0xffffffff, tm0, 1));
        tm0 = fmaxf(tm0, __shfl_xor_sync(0xffffffff, tm0, 2));
        tm8 = fmaxf(tm8, __shfl_xor_sync(0xffffffff, tm8, 1));
        tm8 = fmaxf(tm8, __shfl_xor_sync(0xffffffff, tm8, 2));
        float mn0 = fmaxf(m0, tm0), mn8 = fmaxf(m8, tm8);
        float al0 = __expf(m0 - mn0), al8 = __expf(m8 - mn8);
        m0 = mn0; m8 = mn8;
        float rs0 = 0.f, rs8 = 0.f;
        #pragma unroll
        for (int ni = 0; ni < 8; ni++) {
            float p0 = __expf(sc[ni][0] - mn0);
            float p1 = __expf(sc[ni][1] - mn0);
            float p2 = __expf(sc[ni][2] - mn8);
            float p3 = __expf(sc[ni][3] - mn8);
            sc[ni][0] = p0; sc[ni][1] = p1; sc[ni][2] = p2; sc[ni][3] = p3;
            rs0 += p0 + p1; rs8 += p2 + p3;
        }
        rs0 += __shfl_xor_sync(0xffffffff, rs0, 1);
        rs0 += __shfl_xor_sync(0xffffffff, rs0, 2);
        rs8 += __shfl_xor_sync(0xffffffff, rs8, 1);
        rs8 += __shfl_xor_sync(0xffffffff, rs8, 2);
        l0 = l0*al0 + rs0;
        l8 = l8*al8 + rs8;
        #pragma unroll
        for (int ni = 0; ni < 8; ni++) {
            Oc[ni][0] *= al0; Oc[ni][1] *= al0;
            Oc[ni][2] *= al8; Oc[ni][3] *= al8;
        }

        // repack P (fp16 hi only)
        uint32_t ph[4][4];
        #pragma unroll
        for (int ks2 = 0; ks2 < 4; ks2++) {
            ph[ks2][0] = pack_hf2(sc[2*ks2][0],   sc[2*ks2][1]);
            ph[ks2][1] = pack_hf2(sc[2*ks2][2],   sc[2*ks2][3]);
            ph[ks2][2] = pack_hf2(sc[2*ks2+1][0], sc[2*ks2+1][1]);
            ph[ks2][3] = pack_hf2(sc[2*ks2+1][2], sc[2*ks2+1][3]);
        }

        // PV: ph*Vh then ph*Vl
        #pragma unroll
        for (int ks2 = 0; ks2 < 4; ks2++)
            #pragma unroll
            for (int ni = 0; ni < 8; ni++) {
                int nr = ni*8 + r0;
                mma16816h(Oc[ni], ph[ks2], Vt[nr][cq + 8*ks2], Vt[nr][cq + 8*ks2 + 4]);
            }
        #pragma unroll
        for (int ks2 = 0; ks2 < 4; ks2++)
            #pragma unroll
            for (int ni = 0; ni < 8; ni++) {
                int nr = ni*8 + r0;
                mma16816h(Oc[ni], ph[ks2], Vt[nr][32 + cq + 8*ks2],
                          Vt[nr][32 + cq + 8*ks2 + 4]);
            }
        __syncthreads();
    }

    float i0 = 1.f / l0, i8 = 1.f / l8;
    #pragma unroll
    for (int ni = 0; ni < 8; ni++) {
        int cc = col0 + ni*8 + 2*cq;
        float2 w0 = {Oc[ni][0]*i0, Oc[ni][1]*i0};
        float2 w8 = {Oc[ni][2]*i8, Oc[ni][3]*i8};
        *(float2*)(o + ((size_t)(qrow + r0    )*B_ + b)*oS + cc) = w0;
        *(float2*)(o + ((size_t)(qrow + r0 + 8)*B_ + b)*oS + cc) = w8;
    }
}

// -------- memory retrieval + delta (no attn dependency) -----------------------
__global__ __launch_bounds__(256) void mem_retrieve(
    const float* __restrict__ q, const float* __restrict__ kp,
    const float* __restrict__ vp, const float* __restrict__ memory,
    const float* __restrict__ mem_norm, int l,
    float* __restrict__ content, float* __restrict__ diff, float* __restrict__ cKout,
    int qS, int kvS)
{
    int bn = blockIdx.x;
    int b = bn / NH_, n = bn % NH_;
    int chunk = blockIdx.y;
    int t = threadIdx.x;

    __shared__ float Msh[DH_][DH_+1];
    __shared__ float normsh[DH_];
    __shared__ float cqsh[4][DH_];
    __shared__ float cksh[4][DH_];

    const float* Mg = memory + ((size_t)(l*B_ + b)*NH_ + n)*DH_*DH_;
    for (int idx = t; idx < DH_*DH_; idx += 256) Msh[idx >> 6][idx & 63] = Mg[idx];
    if (t < DH_) normsh[t] = mem_norm[((size_t)(l*B_ + b)*NH_ + n)*DH_ + t];
    __syncthreads();

    int g = t >> 6, d = t & 63;
    int col = n * DH_;
    for (int it = 0; it < 32; ++it) {
        int s = chunk*128 + it*4 + g;
        size_t row = (size_t)(s*B_ + b);
        float qvl = q [row*qS  + col + d];
        float vvl = vp[row*kvS + col + d];
        float cq = qvl > 0.f ? qvl + 1.f : __expf(qvl);
        float ck = vvl > 0.f ? vvl + 1.f : __expf(vvl);
        cqsh[g][d] = cq; cksh[g][d] = ck;
        __syncthreads();
        float accA = 0.f, accB = 0.f, denQ = 0.f, denK = 0.f;
        #pragma unroll 8
        for (int kk = 0; kk < DH_; kk++) {
            float mq = Msh[kk][d];
            accA += cqsh[g][kk] * mq;
            accB += cksh[g][kk] * mq;
            denQ += cqsh[g][kk] * normsh[kk];
            denK += cksh[g][kk] * normsh[kk];
        }
        size_t oidx = row*D_ + col + d;
        content[oidx] = accA / denQ;
        diff[oidx]    = kp[row*kvS + col + d] - accB / denK;
        cKout[oidx]   = ck;
        __syncthreads();
    }
}

// -------- memory update: newM[k][v] = M[k][v] + sum_s cK[s,k]*diff[s,v] ------
__global__ __launch_bounds__(256) void mem_update(
    const float* __restrict__ cK, const float* __restrict__ diff,
    const float* __restrict__ memory, int l, float* __restrict__ outM)
{
    int bn = blockIdx.x;
    int b = bn / NH_, n = bn % NH_;
    __shared__ float aS[16][DH_];
    __shared__ float bS[16][DH_];
    int t = threadIdx.x;
    int tx = t & 15, ty = t >> 4;
    float acc[4][4] = {};
    int col = n * DH_;
    int r  = t >> 4;
    int c4 = (t & 15) * 4;
    for (int s0 = 0; s0 < S_; s0 += 16) {
        size_t row = (size_t)((s0 + r)*B_ + b);
        *(float4*)&aS[r][c4] = *(const float4*)(cK   + row*D_ + col + c4);
        *(float4*)&bS[r][c4] = *(const float4*)(diff + row*D_ + col + c4);
        __syncthreads();
        #pragma unroll
        for (int ss = 0; ss < 16; ss++) {
            float a[4], bb[4];
            #pragma unroll
            for (int u = 0; u < 4; u++) { a[u] = aS[ss][ty*4+u]; bb[u] = bS[ss][tx*4+u]; }
            #pragma unroll
            for (int i = 0; i < 4; i++)
                #pragma unroll
                for (int j = 0; j < 4; j++)
                    acc[i][j] = fmaf(a[i], bb[j], acc[i][j]);
        }
        __syncthreads();
    }
    const float* Mg = memory + ((size_t)(l*B_ + b)*NH_ + n)*DH_*DH_;
    float*       Og = outM   + ((size_t)(l*B_ + b)*NH_ + n)*DH_*DH_;
    #pragma unroll
    for (int i = 0; i < 4; i++)
        #pragma unroll
        for (int j = 0; j < 4; j++) {
            int kk = ty*4 + i, vv = tx*4 + j;
            Og[kk*DH_ + vv] = Mg[kk*DH_ + vv] + acc[i][j];
        }
}

// -------- norm update: outN = mem_norm + sum_s cK (parallel over s) ----------
__global__ __launch_bounds__(512) void norm_update(
    const float* __restrict__ cK, const float* __restrict__ mem_norm, int l,
    float* __restrict__ outN)
{
    int bn = blockIdx.x;
    int b = bn / NH_, n = bn % NH_;
    int t = threadIdx.x;
    int d = t & 63, sg = t >> 6;
    int col = n * DH_;
    float acc = 0.f;
    for (int s = sg; s < S_; s += 8)
        acc += cK[(size_t)(s*B_ + b)*D_ + col + d];
    __shared__ float red[512];
    red[t] = acc; __syncthreads();
    if (t < 256) red[t] += red[t + 256]; __syncthreads();
    if (t < 128) red[t] += red[t + 128]; __syncthreads();
    if (t < 64) {
        size_t o = ((size_t)(l*B_ + b)*NH_ + n)*DH_ + t;
        outN[o] = mem_norm[o] + red[t] + red[t + 64];
    }
}

// -------- layernorm with residual (192 threads, float4, single-pass) ----------
__global__ __launch_bounds__(192) void ln_kernel(
    const float* __restrict__ res, const float* __restrict__ y,
    const float* __restrict__ g, const float* __restrict__ bb,
    float* __restrict__ out)
{
    int row = blockIdx.x;
    int t = threadIdx.x, lane = t & 31, warp = t >> 5;   // 6 warps
    __shared__ float ws[6], wss[6];
    size_t base = (size_t)row * D_;
    float4 xr = *(const float4*)(res + base + 4*t);
    float4 yr = *(const float4*)(y   + base + 4*t);
    float4 x = {xr.x + yr.x, xr.y + yr.y, xr.z + yr.z, xr.w + yr.w};
    float s  = x.x + x.y + x.z + x.w;
    float ss = x.x*x.x + x.y*x.y + x.z*x.z + x.w*x.w;
    #pragma unroll
    for (int off = 16; off > 0; off >>= 1) {
        s  += __shfl_xor_sync(0xffffffff, s,  off);
        ss += __shfl_xor_sync(0xffffffff, ss, off);
    }
    if (lane == 0) { ws[warp] = s; wss[warp] = ss; }
    __syncthreads();
    float S = 0.f, SS = 0.f;
    #pragma unroll
    for (int w = 0; w < 6; w++) { S += ws[w]; SS += wss[w]; }
    float mu  = S * (1.f / 768.f);
    float var = SS * (1.f / 768.f) - mu*mu;
    float inv = rsqrtf(var + 1e-5f);
    float4 gv = *(const float4*)(g  + 4*t);
    float4 bv = *(const float4*)(bb + 4*t);
    float4 o4;
    o4.x = (x.x - mu) * inv * gv.x + bv.x;
    o4.y = (x.y - mu) * inv * gv.y + bv.y;
    o4.z = (x.z - mu) * inv * gv.z + bv.z;
    o4.w = (x.w - mu) * inv * gv.w + bv.w;
    *(float4*)(out + base + 4*t) = o4;
}

// ------------------------------- launcher -------------------------------------
extern "C" void kernel_launch(void* const* d_in, const int* in_sizes, int n_in,
                              void* d_out, int out_size)
{
    const int*   inp      = (const int*)  d_in[0];
    const float* word_emb = (const float*)d_in[1];
    const float* Wq       = (const float*)d_in[2];
    const float* Wkv      = (const float*)d_in[3];
    const float* Wo       = (const float*)d_in[4];
    const float* ln1g     = (const float*)d_in[5];
    const float* ln1b     = (const float*)d_in[6];
    const float* ffW1     = (const float*)d_in[7];
    const float* ffb1     = (const float*)d_in[8];
    const float* ffW2     = (const float*)d_in[9];
    const float* ffb2     = (const float*)d_in[10];
    const float* ln2g     = (const float*)d_in[11];
    const float* ln2b     = (const float*)d_in[12];
    const float* memory   = (const float*)d_in[13];
    const float* mem_norm = (const float*)d_in[14];

    float* out  = (float*)d_out;
    float* outH = out;                         // (S,B,D)
    float* outM = out + (size_t)SB_*D_;        // (L,B,NH,DH,DH)
    float* outN = outM + (size_t)L_*B_*NH_*DH_*DH_;  // (L,B,NH,DH)

    float *h, *q, *kv, *attn, *content, *cK, *diff, *ff, *out1, *wo;
    cudaGetSymbolAddress((void**)&h,       g_h);
    cudaGetSymbolAddress((void**)&q,       g_q);
    cudaGetSymbolAddress((void**)&kv,      g_kv);
    cudaGetSymbolAddress((void**)&attn,    g_attn);
    cudaGetSymbolAddress((void**)&content, g_content);
    cudaGetSymbolAddress((void**)&cK,      g_cK);
    cudaGetSymbolAddress((void**)&diff,    g_diff);
    cudaGetSymbolAddress((void**)&ff,      g_ff);
    cudaGetSymbolAddress((void**)&out1,    g_out1);
    cudaGetSymbolAddress((void**)&wo,      g_wo);

    static cudaStream_t s1 = nullptr;
    static cudaEvent_t evA = nullptr, evB = nullptr, evC = nullptr, evD = nullptr;
    if (!s1) {
        cudaStreamCreateWithFlags(&s1, cudaStreamNonBlocking);
        cudaEventCreateWithFlags(&evA, cudaEventDisableTiming);
        cudaEventCreateWithFlags(&evB, cudaEventDisableTiming);
        cudaEventCreateWithFlags(&evC, cudaEventDisableTiming);
        cudaEventCreateWithFlags(&evD, cudaEventDisableTiming);
    }

    const float gate = 1.0f / (1.0f + expf(-0.01f));

    embed_kernel<<<SB_, 256>>>(inp, word_emb, h);

    for (int l = 0; l < L_; l++) {
        // merged q|kv projection (one 576-block launch)
        gemm_qkv<<<dim3(18, SB_/128), 256>>>(h, Wq + (size_t)l*D_*D_,
                                             Wkv + (size_t)l*2*D_*D_, q, kv, D_);
        // fork side stream after qkv
        cudaEventRecord(evA, 0);
        cudaStreamWaitEvent(s1, evA, 0);
        if (l > 0) cudaStreamWaitEvent(s1, evC, 0);   // content free after Wo(l-1)

        // main stream: local causal attention (64-query tiles, heavy first)
        attn_mma<<<dim3(B_*NH_, 16), 128>>>(q, kv /*k*/, kv + D_ /*v*/, attn,
                                            D_, 2*D_, D_);

        // side stream: memory path (content/diff/cK, M & norm updates)
        mem_retrieve<<<dim3(B_*NH_, 8), 256, 0, s1>>>(q, kv /*k*/, kv + D_ /*v*/,
                                                      memory, mem_norm, l,
                                                      content, diff, cK, D_, 2*D_);
        cudaEventRecord(evB, s1);
        mem_update<<<B_*NH_, 256, 0, s1>>>(cK, diff, memory, l, outM);
        norm_update<<<B_*NH_, 512, 0, s1>>>(cK, mem_norm, l, outN);
        cudaEventRecord(evD, s1);

        // main stream: Wo projection with fused gated combine
        cudaStreamWaitEvent(0, evB, 0);               // content ready
        gemm_wo<<<dim3(D_/128, SB_/128), 256>>>(content, attn, gate,
                                                Wo + (size_t)l*D_*D_, wo, D_, D_);
        cudaEventRecord(evC, 0);

        // ln1: out1 = LN(h + wo)
        ln_kernel<<<SB_, 192>>>(h, wo, ln1g + l*D_, ln1b + l*D_, out1);
        // ff1 = relu(out1 @ W1^T + b1)
        gemm_bf16s<<<dim3(DI_/128, SB_/128), 256>>>(out1, ffW1 + (size_t)l*DI_*D_,
                                                    ffb1 + l*DI_, ff, DI_, D_, 1);
        // ff2 = ff1 @ W2^T + b2 -> q buffer (dead until next layer's qkv)
        gemm_bf16s<<<dim3(D_/128, SB_/128), 256>>>(ff, ffW2 + (size_t)l*D_*DI_,
                                                   ffb2 + l*D_, q, D_, DI_, 2);
        // ln2: h = LN(out1 + ff2)
        ln_kernel<<<SB_, 192>>>(out1, q, ln2g + l*D_, ln2b + l*D_, h);
    }

    // join side stream before finishing
    cudaStreamWaitEvent(0, evD, 0);
    cudaMemcpyAsync(outH, h, (size_t)SB_*D_*sizeof(float),
                    cudaMemcpyDeviceToDevice);
}

// round 17
// speedup vs baseline: 3.8075x; 1.0784x over previous
#include <cuda_runtime.h>
#include <cuda_bf16.h>
#include <cuda_fp16.h>
#include <math.h>
#include <stdint.h>

// Problem dims
#define S_  1024
#define B_  4
#define D_  768
#define NH_ 12
#define DH_ 64
#define L_  4
#define DI_ 3072
#define SB_ (S_*B_)

// ---------------- scratch (device globals; no allocation allowed) ------------
__device__ float g_h[SB_*D_];
__device__ float g_q[SB_*D_];
__device__ float g_kv[SB_*2*D_];
__device__ float g_attn[SB_*D_];
__device__ float g_content[SB_*D_];
__device__ float g_cK[SB_*D_];
__device__ float g_diff[SB_*D_];
__device__ float g_ff[SB_*DI_];
__device__ float g_out1[SB_*D_];
__device__ float g_wo[SB_*D_];

// pack two floats into fp16x2
__device__ __forceinline__ uint32_t pack_hf2(float a, float b) {
    __half2 h = __floats2half2_rn(a, b);
    return *(uint32_t*)&h;
}

// fp16 mma
__device__ __forceinline__ void mma16816h(float* d, const uint32_t* a,
                                          uint32_t b0, uint32_t b1) {
    asm volatile(
        "mma.sync.aligned.m16n8k16.row.col.f32.f16.f16.f32 "
        "{%0,%1,%2,%3}, {%4,%5,%6,%7}, {%8,%9}, {%0,%1,%2,%3};"
        : "+f"(d[0]), "+f"(d[1]), "+f"(d[2]), "+f"(d[3])
        : "r"(a[0]), "r"(a[1]), "r"(a[2]), "r"(a[3]), "r"(b0), "r"(b1));
}

// ---------------- embedding + sinusoidal positional encoding -----------------
__global__ void embed_kernel(const int* __restrict__ inp,
                             const float* __restrict__ we,
                             float* __restrict__ h)
{
    int row = blockIdx.x;          // row = s*B + b
    int s = row / B_;
    int b = row % B_;
    int t = threadIdx.x;           // 256
    int tok = inp[s*B_ + b];
    float pos = (float)(S_ - 1 - s);
    const float lg = logf(10000.0f);
    for (int d = t; d < D_; d += 256) {
        int i = (d < 384) ? d : d - 384;
        float freq = expf(-((float)(2*i) / (float)D_) * lg);
        float ang = pos * freq;
        float pe = (d < 384) ? sinf(ang) : cosf(ang);
        h[(size_t)row*D_ + d] = we[(size_t)tok*D_ + d] * 27.712812921102035f + pe;
    }
}

// ---------------- NT GEMM body (pure fp16, 1 term) ---------------------------
// C[M,N] = A[M,K] @ B[N,K]^T. 128x128 tile, KT=16, 8 warps, 16 mmas/ktile.
// FUSE: A := gate*A + (1-gate)*A2 elementwise at load.
// epi: 0 = none, 1 = bias+relu, 2 = bias
#define KT 16
#define KP 20
template <bool FUSE>
__device__ __forceinline__ void gemm_body(
    const float* __restrict__ A, const float* __restrict__ A2, float gate,
    const float* __restrict__ Bm, const float* __restrict__ bias,
    float* __restrict__ C, int N, int K, int epi, int m0, int n0)
{
    __shared__ __align__(16) uint32_t As[2][128][KP];
    __shared__ __align__(16) uint32_t Bs[2][128][KP];
    int tid  = threadIdx.x;
    int warp = tid >> 5, lane = tid & 31;
    int wm = warp >> 2, wn = warp & 3;        // 2 x 4 warp grid
    int r0 = lane >> 2, cq = lane & 3;

    int lr = tid >> 2;          // 0..63
    int lc = (tid & 3) * 4;     // 0,4,8,12 (k offset in floats)
    int wc = lc >> 1;           // word col: 0,2,4,6
    const float* Ap  = A  + (size_t)(m0 + lr)*K + lc;
    const float* A2p = FUSE ? (A2 + (size_t)(m0 + lr)*K + lc) : nullptr;
    const float* Bp  = Bm + (size_t)(n0 + lr)*K + lc;

    float acc[16][4];
    #pragma unroll
    for (int i = 0; i < 16; i++)
        #pragma unroll
        for (int j = 0; j < 4; j++) acc[i][j] = 0.f;

    #define LOAD_A(off)                                                        \
        ({ float4 _a = *(const float4*)(Ap + (off));                           \
           if (FUSE) { float4 _b = *(const float4*)(A2p + (off));              \
               _a.x = gate*_a.x + (1.f-gate)*_b.x;                              \
               _a.y = gate*_a.y + (1.f-gate)*_b.y;                              \
               _a.z = gate*_a.z + (1.f-gate)*_b.z;                              \
               _a.w = gate*_a.w + (1.f-gate)*_b.w; }                            \
           _a; })

    #define STORE_H(dst, row, vec)                                              \
    {                                                                           \
        float4 _v = (vec);                                                      \
        dst[row][wc+0] = pack_hf2(_v.x, _v.y);                                  \
        dst[row][wc+1] = pack_hf2(_v.z, _v.w);                                  \
    }

    {
        float4 a0v = LOAD_A(0);
        float4 a1v = LOAD_A((size_t)64*K);
        float4 b0v = *(const float4*)Bp;
        float4 b1v = *(const float4*)(Bp + (size_t)64*K);
        STORE_H(As[0], lr,      a0v);
        STORE_H(As[0], lr + 64, a1v);
        STORE_H(Bs[0], lr,      b0v);
        STORE_H(Bs[0], lr + 64, b1v);
    }
    __syncthreads();

    int buf = 0;
    for (int k0 = KT; k0 < K + KT; k0 += KT) {
        bool more = (k0 < K);
        float4 a0v, a1v, b0v, b1v;
        if (more) {
            a0v = LOAD_A(k0);
            a1v = LOAD_A((size_t)64*K + k0);
            b0v = *(const float4*)(Bp + k0);
            b1v = *(const float4*)(Bp + (size_t)64*K + k0);
        }
        uint32_t ah[4][4], bh[4][2];
        #pragma unroll
        for (int mi = 0; mi < 4; mi++) {
            int mr = wm*64 + mi*16 + r0;
            ah[mi][0] = As[buf][mr    ][cq];
            ah[mi][1] = As[buf][mr + 8][cq];
            ah[mi][2] = As[buf][mr    ][cq + 4];
            ah[mi][3] = As[buf][mr + 8][cq + 4];
        }
        #pragma unroll
        for (int ni = 0; ni < 4; ni++) {
            int nr = wn*32 + ni*8 + r0;
            bh[ni][0] = Bs[buf][nr][cq];
            bh[ni][1] = Bs[buf][nr][cq + 4];
        }
        #pragma unroll
        for (int mi = 0; mi < 4; mi++)
            #pragma unroll
            for (int ni = 0; ni < 4; ni++)
                mma16816h(acc[mi*4 + ni], ah[mi], bh[ni][0], bh[ni][1]);
        if (more) {
            int nb = buf ^ 1;
            STORE_H(As[nb], lr,      a0v);
            STORE_H(As[nb], lr + 64, a1v);
            STORE_H(Bs[nb], lr,      b0v);
            STORE_H(Bs[nb], lr + 64, b1v);
            __syncthreads();
            buf = nb;
        }
    }
    #undef STORE_H
    #undef LOAD_A

    #pragma unroll
    for (int mi = 0; mi < 4; mi++) {
        int m = m0 + wm*64 + mi*16 + r0;
        #pragma unroll
        for (int ni = 0; ni < 4; ni++) {
            int n = n0 + wn*32 + ni*8 + 2*cq;
            float* d = acc[mi*4 + ni];
            float2 v0 = {d[0], d[1]};
            float2 v1 = {d[2], d[3]};
            if (epi == 1) {
                float b0v = bias[n], b1v = bias[n+1];
                v0.x = fmaxf(v0.x + b0v, 0.f); v0.y = fmaxf(v0.y + b1v, 0.f);
                v1.x = fmaxf(v1.x + b0v, 0.f); v1.y = fmaxf(v1.y + b1v, 0.f);
            } else if (epi == 2) {
                float b0v = bias[n], b1v = bias[n+1];
                v0.x += b0v; v0.y += b1v;
                v1.x += b0v; v1.y += b1v;
            }
            *(float2*)(C + (size_t)m*N + n)       = v0;
            *(float2*)(C + (size_t)(m+8)*N + n)   = v1;
        }
    }
}

__global__ __launch_bounds__(256) void gemm_bf16s(
    const float* __restrict__ A, const float* __restrict__ Bm,
    const float* __restrict__ bias, float* __restrict__ C,
    int N, int K, int epi)
{
    gemm_body<false>(A, nullptr, 0.f, Bm, bias, C, N, K, epi,
                     blockIdx.y*128, blockIdx.x*128);
}

// fused combine GEMM: C = (gate*A + (1-gate)*A2) @ B^T
__global__ __launch_bounds__(256) void gemm_wo(
    const float* __restrict__ A, const float* __restrict__ A2, float gate,
    const float* __restrict__ Bm, float* __restrict__ C, int N, int K)
{
    gemm_body<true>(A, A2, gate, Bm, nullptr, C, N, K, 0,
                    blockIdx.y*128, blockIdx.x*128);
}

// merged Q + KV projection: blocks 0..5 -> q, 6..17 -> kv
__global__ __launch_bounds__(256) void gemm_qkv(
    const float* __restrict__ A, const float* __restrict__ Wq,
    const float* __restrict__ Wkv, float* __restrict__ q,
    float* __restrict__ kv, int K)
{
    int bx = blockIdx.x, m0 = blockIdx.y*128;
    if (bx < 6)
        gemm_body<false>(A, nullptr, 0.f, Wq,  nullptr, q,  D_,   K, 0, m0, bx*128);
    else
        gemm_body<false>(A, nullptr, 0.f, Wkv, nullptr, kv, 2*D_, K, 0, m0, (bx-6)*128);
}

// ------------- tensor-core flash attention (pure fp16, fp32 acc) --------------
// 64-query tiles, 128 threads (4 warps x 16 rows). grid (48, 16),
// qt = 15 - blockIdx.y so heavy CTAs launch first. 1-term fp16 QK and PV.
#define AP 36   // smem pitch (32 data words + 4 pad; 4*r0+cq conflict-free)
__global__ __launch_bounds__(128) void attn_mma(
    const float* __restrict__ q, const float* __restrict__ k,
    const float* __restrict__ v, float* __restrict__ o,
    int qS, int kvS, int oS)
{
    int qt = 15 - (int)blockIdx.y;         // big-work blocks launch first
    int bn = blockIdx.x;
    int b = bn / NH_, n = bn % NH_;
    int col0 = n * DH_;
    int t = threadIdx.x, lane = t & 31, warp = t >> 5;   // 4 warps
    int r0 = lane >> 2, cq = lane & 3;

    __shared__ __align__(16) uint32_t Ks[64][AP];
    __shared__ __align__(16) uint32_t Vt[64][AP];

    int qrow = qt*64 + warp*16;

    uint32_t qh[4][4];
    #pragma unroll
    for (int ks = 0; ks < 4; ks++) {
        int cb = ks*16 + 2*cq;
        #pragma unroll
        for (int u = 0; u < 4; u++) {
            int rr = qrow + r0 + ((u & 1) ? 8 : 0);
            int cc = cb + ((u & 2) ? 8 : 0);
            float2 qv = *(const float2*)(q + ((size_t)rr*B_ + b)*qS + col0 + cc);
            qh[ks][u] = pack_hf2(qv.x, qv.y);
        }
    }

    float Oc[8][4];
    #pragma unroll
    for (int i = 0; i < 8; i++)
        #pragma unroll
        for (int j = 0; j < 4; j++) Oc[i][j] = 0.f;
    float m0 = -3.4e38f, m8 = -3.4e38f, l0 = 0.f, l8 = 0.f;

    int nkt = qt + 1;
    for (int kt = 0; kt < nkt; kt++) {
        // K tile [64 keys][64 dims], fp16
        for (int idx = t; idx < 64*16; idx += 128) {
            int key = idx >> 4, c = idx & 15;
            float4 kv4 = *(const float4*)(k + ((size_t)(kt*64+key)*B_ + b)*kvS
                                            + col0 + 4*c);
            Ks[key][2*c  ] = pack_hf2(kv4.x, kv4.y);
            Ks[key][2*c+1] = pack_hf2(kv4.z, kv4.w);
        }
        // V^T tile, fp16
        #pragma unroll
        for (int it = 0; it < 8; it++) {
            int idx = t + 128*it;           // 0..1023
            int j = idx >> 5;               // keypair 0..31
            int d = idx & 31;               // dimpair 0..31
            const float* vp0 = v + ((size_t)(kt*64 + 2*j)*B_ + b)*kvS + col0 + 2*d;
            float2 va = *(const float2*)vp0;
            float2 vb = *(const float2*)(vp0 + (size_t)B_*kvS);
            Vt[2*d  ][j] = pack_hf2(va.x, vb.x);
            Vt[2*d+1][j] = pack_hf2(va.y, vb.y);
        }
        __syncthreads();

        float sc[8][4];
        #pragma unroll
        for (int i = 0; i < 8; i++)
            #pragma unroll
            for (int j = 0; j < 4; j++) sc[i][j] = 0.f;
        #pragma unroll
        for (int ks = 0; ks < 4; ks++)
            #pragma unroll
            for (int ni = 0; ni < 8; ni++) {
                int nr = ni*8 + r0;
                mma16816h(sc[ni], qh[ks], Ks[nr][cq + 8*ks], Ks[nr][cq + 8*ks + 4]);
            }

        const float scale = 0.125f;
        bool diag = (kt == qt);
        int rg0 = qrow + r0, rg8 = rg0 + 8;
        float tm0 = -3.4e38f, tm8 = -3.4e38f;
        #pragma unroll
        for (int ni = 0; ni < 8; ni++) {
            float s0 = sc[ni][0]*scale, s1 = sc[ni][1]*scale;
            float s2 = sc[ni][2]*scale, s3 = sc[ni][3]*scale;
            if (diag) {
                int colg = kt*64 + ni*8 + 2*cq;
                if (colg     > rg0) s0 = -3.4e38f;
                if (colg + 1 > rg0) s1 = -3.4e38f;
                if (colg     > rg8) s2 = -3.4e38f;
                if (colg + 1 > rg8) s3 = -3.4e38f;
            }
            sc[ni][0] = s0; sc[ni][1] = s1; sc[ni][2] = s2; sc[ni][3] = s3;
            tm0 = fmaxf(tm0, fmaxf(s0, s1));
            tm8 = fmaxf(tm8, fmaxf(s2, s3));
        }
        tm0 = fmaxf(tm0, __shfl_xor_sync(0xffffffff, tm0, 1));
        tm0 = fmaxf(tm0, __shfl_xor_sync(0xffffffff, tm0, 2));
        tm8 = fmaxf(tm8, __shfl_xor_sync(0xffffffff, tm8, 1));
        tm8 = fmaxf(tm8, __shfl_xor_sync(0xffffffff, tm8, 2));
        float mn0 = fmaxf(m0, tm0), mn8 = fmaxf(m8, tm8);
        float al0 = __expf(m0 - mn0), al8 = __expf(m8 - mn8);
        m0 = mn0; m8 = mn8;
        float rs0 = 0.f, rs8 = 0.f;
        #pragma unroll
        for (int ni = 0; ni < 8; ni++) {
            float p0 = __expf(sc[ni][0] - mn0);
            float p1 = __expf(sc[ni][1] - mn0);
            float p2 = __expf(sc[ni][2] - mn8);
            float p3 = __expf(sc[ni][3] - mn8);
            sc[ni][0] = p0; sc[ni][1] = p1; sc[ni][2] = p2; sc[ni][3] = p3;
            rs0 += p0 + p1; rs8 += p2 + p3;
        }
        rs0 += __shfl_xor_sync(0xffffffff, rs0, 1);
        rs0 += __shfl_xor_sync(0xffffffff, rs0, 2);
        rs8 += __shfl_xor_sync(0xffffffff, rs8, 1);
        rs8 += __shfl_xor_sync(0xffffffff, rs8, 2);
        l0 = l0*al0 + rs0;
        l8 = l8*al8 + rs8;
        #pragma unroll
        for (int ni = 0; ni < 8; ni++) {
            Oc[ni][0] *= al0; Oc[ni][1] *= al0;
            Oc[ni][2] *= al8; Oc[ni][3] *= al8;
        }

        // repack P (fp16)
        uint32_t ph[4][4];
        #pragma unroll
        for (int ks2 = 0; ks2 < 4; ks2++) {
            ph[ks2][0] = pack_hf2(sc[2*ks2][0],   sc[2*ks2][1]);
            ph[ks2][1] = pack_hf2(sc[2*ks2][2],   sc[2*ks2][3]);
            ph[ks2][2] = pack_hf2(sc[2*ks2+1][0], sc[2*ks2+1][1]);
            ph[ks2][3] = pack_hf2(sc[2*ks2+1][2], sc[2*ks2+1][3]);
        }

        #pragma unroll
        for (int ks2 = 0; ks2 < 4; ks2++)
            #pragma unroll
            for (int ni = 0; ni < 8; ni++) {
                int nr = ni*8 + r0;
                mma16816h(Oc[ni], ph[ks2], Vt[nr][cq + 8*ks2], Vt[nr][cq + 8*ks2 + 4]);
            }
        __syncthreads();
    }

    float i0 = 1.f / l0, i8 = 1.f / l8;
    #pragma unroll
    for (int ni = 0; ni < 8; ni++) {
        int cc = col0 + ni*8 + 2*cq;
        float2 w0 = {Oc[ni][0]*i0, Oc[ni][1]*i0};
        float2 w8 = {Oc[ni][2]*i8, Oc[ni][3]*i8};
        *(float2*)(o + ((size_t)(qrow + r0    )*B_ + b)*oS + cc) = w0;
        *(float2*)(o + ((size_t)(qrow + r0 + 8)*B_ + b)*oS + cc) = w8;
    }
}

// -------- memory retrieval + delta (register-cached M, shuffle denominators) --
__global__ __launch_bounds__(256) void mem_retrieve(
    const float* __restrict__ q, const float* __restrict__ kp,
    const float* __restrict__ vp, const float* __restrict__ memory,
    const float* __restrict__ mem_norm, int l,
    float* __restrict__ content, float* __restrict__ diff, float* __restrict__ cKout,
    int qS, int kvS)
{
    int bn = blockIdx.x;
    int b = bn / NH_, n = bn % NH_;
    int chunk = blockIdx.y;
    int t = threadIdx.x, lane = t & 31, warp = t >> 5;
    int g = t >> 6, d = t & 63;

    __shared__ float2 cqk[4][DH_];
    __shared__ float2 wden[8];

    // register-cache M column d (invariant over s)
    const float* Mg = memory + ((size_t)(l*B_ + b)*NH_ + n)*DH_*DH_;
    float Mreg[DH_];
    #pragma unroll
    for (int kk = 0; kk < DH_; kk++) Mreg[kk] = Mg[kk*DH_ + d];
    float nrm = mem_norm[((size_t)(l*B_ + b)*NH_ + n)*DH_ + d];

    int col = n * DH_;
    for (int it = 0; it < 32; ++it) {
        int s = chunk*128 + it*4 + g;
        size_t row = (size_t)(s*B_ + b);
        float qvl = q [row*qS  + col + d];
        float vvl = vp[row*kvS + col + d];
        float cq = qvl > 0.f ? qvl + 1.f : __expf(qvl);
        float ck = vvl > 0.f ? vvl + 1.f : __expf(vvl);
        // denominators: den = sum_d c*nrm, via warp shuffles (+ cross-warp smem)
        float dq = cq * nrm, dk = ck * nrm;
        #pragma unroll
        for (int off = 16; off > 0; off >>= 1) {
            dq += __shfl_xor_sync(0xffffffff, dq, off);
            dk += __shfl_xor_sync(0xffffffff, dk, off);
        }
        if (lane == 0) wden[warp] = make_float2(dq, dk);
        cqk[g][d] = make_float2(cq, ck);
        __syncthreads();
        float2 w0 = wden[2*g], w1 = wden[2*g + 1];
        float denQ = w0.x + w1.x, denK = w0.y + w1.y;
        float accA = 0.f, accB = 0.f;
        #pragma unroll
        for (int kk = 0; kk < DH_; kk++) {
            float2 c = cqk[g][kk];
            accA += c.x * Mreg[kk];
            accB += c.y * Mreg[kk];
        }
        size_t oidx = row*D_ + col + d;
        content[oidx] = accA / denQ;
        diff[oidx]    = kp[row*kvS + col + d] - accB / denK;
        cKout[oidx]   = ck;
        __syncthreads();
    }
}

// -------- memory update: newM[k][v] = M[k][v] + sum_s cK[s,k]*diff[s,v] ------
__global__ __launch_bounds__(256) void mem_update(
    const float* __restrict__ cK, const float* __restrict__ diff,
    const float* __restrict__ memory, int l, float* __restrict__ outM)
{
    int bn = blockIdx.x;
    int b = bn / NH_, n = bn % NH_;
    __shared__ float aS[16][DH_];
    __shared__ float bS[16][DH_];
    int t = threadIdx.x;
    int tx = t & 15, ty = t >> 4;
    float acc[4][4] = {};
    int col = n * DH_;
    int r  = t >> 4;
    int c4 = (t & 15) * 4;
    for (int s0 = 0; s0 < S_; s0 += 16) {
        size_t row = (size_t)((s0 + r)*B_ + b);
        *(float4*)&aS[r][c4] = *(const float4*)(cK   + row*D_ + col + c4);
        *(float4*)&bS[r][c4] = *(const float4*)(diff + row*D_ + col + c4);
        __syncthreads();
        #pragma unroll
        for (int ss = 0; ss < 16; ss++) {
            float a[4], bb[4];
            #pragma unroll
            for (int u = 0; u < 4; u++) { a[u] = aS[ss][ty*4+u]; bb[u] = bS[ss][tx*4+u]; }
            #pragma unroll
            for (int i = 0; i < 4; i++)
                #pragma unroll
                for (int j = 0; j < 4; j++)
                    acc[i][j] = fmaf(a[i], bb[j], acc[i][j]);
        }
        __syncthreads();
    }
    const float* Mg = memory + ((size_t)(l*B_ + b)*NH_ + n)*DH_*DH_;
    float*       Og = outM   + ((size_t)(l*B_ + b)*NH_ + n)*DH_*DH_;
    #pragma unroll
    for (int i = 0; i < 4; i++)
        #pragma unroll
        for (int j = 0; j < 4; j++) {
            int kk = ty*4 + i, vv = tx*4 + j;
            Og[kk*DH_ + vv] = Mg[kk*DH_ + vv] + acc[i][j];
        }
}

// -------- norm update: outN = mem_norm + sum_s cK (parallel over s) ----------
__global__ __launch_bounds__(512) void norm_update(
    const float* __restrict__ cK, const float* __restrict__ mem_norm, int l,
    float* __restrict__ outN)
{
    int bn = blockIdx.x;
    int b = bn / NH_, n = bn % NH_;
    int t = threadIdx.x;
    int d = t & 63, sg = t >> 6;
    int col = n * DH_;
    float acc = 0.f;
    for (int s = sg; s < S_; s += 8)
        acc += cK[(size_t)(s*B_ + b)*D_ + col + d];
    __shared__ float red[512];
    red[t] = acc; __syncthreads();
    if (t < 256) red[t] += red[t + 256]; __syncthreads();
    if (t < 128) red[t] += red[t + 128]; __syncthreads();
    if (t < 64) {
        size_t o = ((size_t)(l*B_ + b)*NH_ + n)*DH_ + t;
        outN[o] = mem_norm[o] + red[t] + red[t + 64];
    }
}

// -------- layernorm with residual (192 threads, float4, single-pass) ----------
__global__ __launch_bounds__(192) void ln_kernel(
    const float* __restrict__ res, const float* __restrict__ y,
    const float* __restrict__ g, const float* __restrict__ bb,
    float* __restrict__ out)
{
    int row = blockIdx.x;
    int t = threadIdx.x, lane = t & 31, warp = t >> 5;   // 6 warps
    __shared__ float ws[6], wss[6];
    size_t base = (size_t)row * D_;
    float4 xr = *(const float4*)(res + base + 4*t);
    float4 yr = *(const float4*)(y   + base + 4*t);
    float4 x = {xr.x + yr.x, xr.y + yr.y, xr.z + yr.z, xr.w + yr.w};
    float s  = x.x + x.y + x.z + x.w;
    float ss = x.x*x.x + x.y*x.y + x.z*x.z + x.w*x.w;
    #pragma unroll
    for (int off = 16; off > 0; off >>= 1) {
        s  += __shfl_xor_sync(0xffffffff, s,  off);
        ss += __shfl_xor_sync(0xffffffff, ss, off);
    }
    if (lane == 0) { ws[warp] = s; wss[warp] = ss; }
    __syncthreads();
    float S = 0.f, SS = 0.f;
    #pragma unroll
    for (int w = 0; w < 6; w++) { S += ws[w]; SS += wss[w]; }
    float mu  = S * (1.f / 768.f);
    float var = SS * (1.f / 768.f) - mu*mu;
    float inv = rsqrtf(var + 1e-5f);
    float4 gv = *(const float4*)(g  + 4*t);
    float4 bv = *(const float4*)(bb + 4*t);
    float4 o4;
    o4.x = (x.x - mu) * inv * gv.x + bv.x;
    o4.y = (x.y - mu) * inv * gv.y + bv.y;
    o4.z = (x.z - mu) * inv * gv.z + bv.z;
    o4.w = (x.w - mu) * inv * gv.w + bv.w;
    *(float4*)(out + base + 4*t) = o4;
}

// ------------------------------- launcher -------------------------------------
extern "C" void kernel_launch(void* const* d_in, const int* in_sizes, int n_in,
                              void* d_out, int out_size)
{
    const int*   inp      = (const int*)  d_in[0];
    const float* word_emb = (const float*)d_in[1];
    const float* Wq       = (const float*)d_in[2];
    const float* Wkv      = (const float*)d_in[3];
    const float* Wo       = (const float*)d_in[4];
    const float* ln1g     = (const float*)d_in[5];
    const float* ln1b     = (const float*)d_in[6];
    const float* ffW1     = (const float*)d_in[7];
    const float* ffb1     = (const float*)d_in[8];
    const float* ffW2     = (const float*)d_in[9];
    const float* ffb2     = (const float*)d_in[10];
    const float* ln2g     = (const float*)d_in[11];
    const float* ln2b     = (const float*)d_in[12];
    const float* memory   = (const float*)d_in[13];
    const float* mem_norm = (const float*)d_in[14];

    float* out  = (float*)d_out;
    float* outH = out;                         // (S,B,D)
    float* outM = out + (size_t)SB_*D_;        // (L,B,NH,DH,DH)
    float* outN = outM + (size_t)L_*B_*NH_*DH_*DH_;  // (L,B,NH,DH)

    float *h, *q, *kv, *attn, *content, *cK, *diff, *ff, *out1, *wo;
    cudaGetSymbolAddress((void**)&h,       g_h);
    cudaGetSymbolAddress((void**)&q,       g_q);
    cudaGetSymbolAddress((void**)&kv,      g_kv);
    cudaGetSymbolAddress((void**)&attn,    g_attn);
    cudaGetSymbolAddress((void**)&content, g_content);
    cudaGetSymbolAddress((void**)&cK,      g_cK);
    cudaGetSymbolAddress((void**)&diff,    g_diff);
    cudaGetSymbolAddress((void**)&ff,      g_ff);
    cudaGetSymbolAddress((void**)&out1,    g_out1);
    cudaGetSymbolAddress((void**)&wo,      g_wo);

    static cudaStream_t s1 = nullptr;
    static cudaEvent_t evA = nullptr, evB = nullptr, evC = nullptr, evD = nullptr;
    if (!s1) {
        cudaStreamCreateWithFlags(&s1, cudaStreamNonBlocking);
        cudaEventCreateWithFlags(&evA, cudaEventDisableTiming);
        cudaEventCreateWithFlags(&evB, cudaEventDisableTiming);
        cudaEventCreateWithFlags(&evC, cudaEventDisableTiming);
        cudaEventCreateWithFlags(&evD, cudaEventDisableTiming);
    }

    const float gate = 1.0f / (1.0f + expf(-0.01f));

    embed_kernel<<<SB_, 256>>>(inp, word_emb, h);

    for (int l = 0; l < L_; l++) {
        // merged q|kv projection (one 576-block launch)
        gemm_qkv<<<dim3(18, SB_/128), 256>>>(h, Wq + (size_t)l*D_*D_,
                                             Wkv + (size_t)l*2*D_*D_, q, kv, D_);
        // fork side stream after qkv
        cudaEventRecord(evA, 0);
        cudaStreamWaitEvent(s1, evA, 0);
        if (l > 0) cudaStreamWaitEvent(s1, evC, 0);   // content free after Wo(l-1)

        // main stream: local causal attention (64-query tiles, heavy first)
        attn_mma<<<dim3(B_*NH_, 16), 128>>>(q, kv /*k*/, kv + D_ /*v*/, attn,
                                            D_, 2*D_, D_);

        // side stream: memory path (content/diff/cK, M & norm updates)
        mem_retrieve<<<dim3(B_*NH_, 8), 256, 0, s1>>>(q, kv /*k*/, kv + D_ /*v*/,
                                                      memory, mem_norm, l,
                                                      content, diff, cK, D_, 2*D_);
        cudaEventRecord(evB, s1);
        mem_update<<<B_*NH_, 256, 0, s1>>>(cK, diff, memory, l, outM);
        norm_update<<<B_*NH_, 512, 0, s1>>>(cK, mem_norm, l, outN);
        cudaEventRecord(evD, s1);

        // main stream: Wo projection with fused gated combine
        cudaStreamWaitEvent(0, evB, 0);               // content ready
        gemm_wo<<<dim3(D_/128, SB_/128), 256>>>(content, attn, gate,
                                                Wo + (size_t)l*D_*D_, wo, D_, D_);
        cudaEventRecord(evC, 0);

        // ln1: out1 = LN(h + wo)
        ln_kernel<<<SB_, 192>>>(h, wo, ln1g + l*D_, ln1b + l*D_, out1);
        // ff1 = relu(out1 @ W1^T + b1)
        gemm_bf16s<<<dim3(DI_/128, SB_/128), 256>>>(out1, ffW1 + (size_t)l*DI_*D_,
                                                    ffb1 + l*DI_, ff, DI_, D_, 1);
        // ff2 = ff1 @ W2^T + b2 -> q buffer (dead until next layer's qkv)
        gemm_bf16s<<<dim3(D_/128, SB_/128), 256>>>(ff, ffW2 + (size_t)l*D_*DI_,
                                                   ffb2 + l*D_, q, D_, DI_, 2);
        // ln2: h = LN(out1 + ff2)
        ln_kernel<<<SB_, 192>>>(out1, q, ln2g + l*D_, ln2b + l*D_, h);
    }

    // join side stream before finishing
    cudaStreamWaitEvent(0, evD, 0);
    cudaMemcpyAsync(outH, h, (size_t)SB_*D_*sizeof(float),
                    cudaMemcpyDeviceToDevice);
}